// round 1
// baseline (speedup 1.0000x reference)
#include <cuda_runtime.h>
#include <math.h>
#include <stdint.h>

// Problem dims
#define BB  512
#define XDIM 32768
#define PDIM 512
#define DDIM 64
#define HDIM 128
#define G1D 1024

// Scratch (device globals; no allocation)
__device__ float g_h1[BB * G1D];            // 2 MB
__device__ float g_h[BB * PDIM];            // 1 MB
__device__ float g_hWh[DDIM * BB * HDIM];   // 16.8 MB, layout [d][b][h]
__device__ float g_js[DDIM];
__device__ float g_es[DDIM];

__device__ __forceinline__ float eluf(float x) {
    return x > 0.f ? x : expm1f(x);
}

// ---------------------------------------------------------------------------
// Tiled SGEMM: C[M,N] = (epi? elu(A@B + bias) : A@B)
// A row-major [M,K], B row-major [K,N]. BM=BN=64, BK=16, 256 threads, 4x4 tile.
// Batched over blockIdx.z with strides sB, sC (A shared when sA==0).
// ---------------------------------------------------------------------------
template <int EPI>
__global__ void sgemm64(const float* __restrict__ A, const float* __restrict__ Bm,
                        const float* __restrict__ bias, float* __restrict__ C,
                        int M, int N, int K, long sB, long sC)
{
    __shared__ __align__(16) float As[16][68];   // [k][m], padded
    __shared__ __align__(16) float Bs[16][64];   // [k][n]

    const float* Bz = Bm + (long)blockIdx.z * sB;
    float* Cz = C + (long)blockIdx.z * sC;

    const int tid = threadIdx.x;
    const int tx = tid & 15, ty = tid >> 4;
    const int rowBase = blockIdx.y * 64;
    const int colBase = blockIdx.x * 64;

    const int aRow = tid >> 2;            // 0..63
    const int aCol = (tid & 3) << 2;      // 0,4,8,12
    const int bRow = tid >> 4;            // 0..15
    const int bCol = (tid & 15) << 2;     // 0..60

    float acc[4][4];
#pragma unroll
    for (int i = 0; i < 4; i++)
#pragma unroll
        for (int j = 0; j < 4; j++) acc[i][j] = 0.f;

    for (int k0 = 0; k0 < K; k0 += 16) {
        float4 av = *(const float4*)(A + (long)(rowBase + aRow) * K + k0 + aCol);
        As[aCol + 0][aRow] = av.x;
        As[aCol + 1][aRow] = av.y;
        As[aCol + 2][aRow] = av.z;
        As[aCol + 3][aRow] = av.w;
        float4 bv = *(const float4*)(Bz + (long)(k0 + bRow) * N + colBase + bCol);
        *(float4*)&Bs[bRow][bCol] = bv;
        __syncthreads();

#pragma unroll
        for (int kk = 0; kk < 16; kk++) {
            float4 a = *(const float4*)&As[kk][ty << 2];
            float4 b = *(const float4*)&Bs[kk][tx << 2];
            acc[0][0] = fmaf(a.x, b.x, acc[0][0]);
            acc[0][1] = fmaf(a.x, b.y, acc[0][1]);
            acc[0][2] = fmaf(a.x, b.z, acc[0][2]);
            acc[0][3] = fmaf(a.x, b.w, acc[0][3]);
            acc[1][0] = fmaf(a.y, b.x, acc[1][0]);
            acc[1][1] = fmaf(a.y, b.y, acc[1][1]);
            acc[1][2] = fmaf(a.y, b.z, acc[1][2]);
            acc[1][3] = fmaf(a.y, b.w, acc[1][3]);
            acc[2][0] = fmaf(a.z, b.x, acc[2][0]);
            acc[2][1] = fmaf(a.z, b.y, acc[2][1]);
            acc[2][2] = fmaf(a.z, b.z, acc[2][2]);
            acc[2][3] = fmaf(a.z, b.w, acc[2][3]);
            acc[3][0] = fmaf(a.w, b.x, acc[3][0]);
            acc[3][1] = fmaf(a.w, b.y, acc[3][1]);
            acc[3][2] = fmaf(a.w, b.z, acc[3][2]);
            acc[3][3] = fmaf(a.w, b.w, acc[3][3]);
        }
        __syncthreads();
    }

#pragma unroll
    for (int i = 0; i < 4; i++) {
        int r = rowBase + (ty << 2) + i;
#pragma unroll
        for (int j = 0; j < 4; j++) {
            int c = colBase + (tx << 2) + j;
            float v = acc[i][j];
            if (EPI) v = eluf(v + bias[c]);
            Cz[(long)r * N + c] = v;
        }
    }
}

// ---------------------------------------------------------------------------
// Per-dim head: one block per d (256 threads = 8 warps). Each warp processes
// one batch row at a time, computing joint and marginal scores together
// (sharing the W2 smem reads). Deterministic block reduction, no atomics.
// smem: W2[d] (64KB) + Wz/b1/b2/W3 (2KB) + per-warp a1 staging (8KB) + red.
// ---------------------------------------------------------------------------
#define HEAD_SMEM_FLOATS (16384 + 4 * 128 + 8 * 256 + 16)
#define HEAD_SMEM_BYTES  (HEAD_SMEM_FLOATS * 4)

__global__ void head_kernel(const float* __restrict__ z, const int* __restrict__ perm,
                            const float* __restrict__ Wz, const float* __restrict__ b1,
                            const float* __restrict__ W2, const float* __restrict__ b2,
                            const float* __restrict__ W3, const float* __restrict__ b3)
{
    extern __shared__ __align__(16) float sm[];
    float* W2s = sm;                   // 16384
    float* Wzs = sm + 16384;           // 128
    float* b1s = Wzs + 128;
    float* b2s = b1s + 128;
    float* W3s = b2s + 128;
    float* a1b = W3s + 128;            // 8*256
    float* red = a1b + 8 * 256;        // 16

    const int d = blockIdx.x;
    const int tid = threadIdx.x;
    const int lane = tid & 31;
    const int warp = tid >> 5;

    const float* W2d = W2 + (long)d * HDIM * HDIM;
    for (int i = tid; i < (HDIM * HDIM) / 4; i += 256)
        ((float4*)W2s)[i] = ((const float4*)W2d)[i];
    if (tid < HDIM) {
        Wzs[tid] = Wz[d * HDIM + tid];
        b1s[tid] = b1[d * HDIM + tid];
        b2s[tid] = b2[d * HDIM + tid];
        W3s[tid] = W3[d * HDIM + tid];
    }
    __syncthreads();

    const float b3d = b3[d];
    float* a1j = a1b + warp * 256;
    float* a1m = a1j + 128;
    const float* hb = g_hWh + (long)d * BB * HDIM;

    float sumj = 0.f, sume = 0.f;

    for (int it = 0; it < BB / 8; it++) {
        const int b = it * 8 + warp;
        const int pb = perm[b];
        const float zb = z[b * DDIM + d];
        const float* hj = hb + (long)b * HDIM;
        const float* hm = hb + (long)pb * HDIM;

#pragma unroll
        for (int i = 0; i < 4; i++) {
            int h = lane + 32 * i;
            float w = fmaf(zb, Wzs[h], b1s[h]);
            a1j[h] = eluf(hj[h] + w);
            a1m[h] = eluf(hm[h] + w);
        }
        __syncwarp();

        float aj0 = 0.f, aj1 = 0.f, aj2 = 0.f, aj3 = 0.f;
        float am0 = 0.f, am1 = 0.f, am2 = 0.f, am3 = 0.f;
#pragma unroll 8
        for (int h2 = 0; h2 < HDIM; h2++) {
            float xj = a1j[h2];
            float xm = a1m[h2];
            float4 w = ((const float4*)(W2s + h2 * HDIM))[lane];
            aj0 = fmaf(xj, w.x, aj0); am0 = fmaf(xm, w.x, am0);
            aj1 = fmaf(xj, w.y, aj1); am1 = fmaf(xm, w.y, am1);
            aj2 = fmaf(xj, w.z, aj2); am2 = fmaf(xm, w.z, am2);
            aj3 = fmaf(xj, w.w, aj3); am3 = fmaf(xm, w.w, am3);
        }

        const int k0 = lane * 4;
        float pj = 0.f, pm = 0.f;
        aj0 = eluf(aj0 + b2s[k0 + 0]); pj = fmaf(aj0, W3s[k0 + 0], pj);
        aj1 = eluf(aj1 + b2s[k0 + 1]); pj = fmaf(aj1, W3s[k0 + 1], pj);
        aj2 = eluf(aj2 + b2s[k0 + 2]); pj = fmaf(aj2, W3s[k0 + 2], pj);
        aj3 = eluf(aj3 + b2s[k0 + 3]); pj = fmaf(aj3, W3s[k0 + 3], pj);
        am0 = eluf(am0 + b2s[k0 + 0]); pm = fmaf(am0, W3s[k0 + 0], pm);
        am1 = eluf(am1 + b2s[k0 + 1]); pm = fmaf(am1, W3s[k0 + 1], pm);
        am2 = eluf(am2 + b2s[k0 + 2]); pm = fmaf(am2, W3s[k0 + 2], pm);
        am3 = eluf(am3 + b2s[k0 + 3]); pm = fmaf(am3, W3s[k0 + 3], pm);

#pragma unroll
        for (int off = 16; off; off >>= 1) {
            pj += __shfl_xor_sync(0xffffffffu, pj, off);
            pm += __shfl_xor_sync(0xffffffffu, pm, off);
        }
        sumj += pj + b3d;
        sume += expf(pm + b3d);
        __syncwarp();
    }

    if (lane == 0) { red[warp] = sumj; red[8 + warp] = sume; }
    __syncthreads();
    if (tid == 0) {
        float sj = 0.f, se = 0.f;
#pragma unroll
        for (int w = 0; w < 8; w++) { sj += red[w]; se += red[8 + w]; }
        g_js[d] = sj;
        g_es[d] = se;
    }
}

// ---------------------------------------------------------------------------
// Finalize: out = -mean_d( mean_b(joint) - log(mean_b(exp(marg))) )
// ---------------------------------------------------------------------------
__global__ void finalize_kernel(float* __restrict__ out)
{
    int t = threadIdx.x;  // 32 threads
    float acc = 0.f;
    for (int d = t; d < DDIM; d += 32) {
        float mi = g_js[d] * (1.f / BB) - logf(g_es[d] * (1.f / BB));
        acc += mi;
    }
#pragma unroll
    for (int off = 16; off; off >>= 1)
        acc += __shfl_xor_sync(0xffffffffu, acc, off);
    if (t == 0) out[0] = -acc * (1.f / DDIM);
}

// ---------------------------------------------------------------------------
extern "C" void kernel_launch(void* const* d_in, const int* in_sizes, int n_in,
                              void* d_out, int out_size)
{
    const float* x   = (const float*)d_in[0];
    const float* z   = (const float*)d_in[1];
    const int*   perm= (const int*)  d_in[2];
    const float* Wg1 = (const float*)d_in[3];
    const float* bg1 = (const float*)d_in[4];
    const float* Wg2 = (const float*)d_in[5];
    const float* bg2 = (const float*)d_in[6];
    const float* Wh  = (const float*)d_in[7];
    const float* Wz  = (const float*)d_in[8];
    const float* b1  = (const float*)d_in[9];
    const float* W2  = (const float*)d_in[10];
    const float* b2  = (const float*)d_in[11];
    const float* W3  = (const float*)d_in[12];
    const float* b3  = (const float*)d_in[13];

    float* h1;  cudaGetSymbolAddress((void**)&h1,  g_h1);
    float* h;   cudaGetSymbolAddress((void**)&h,   g_h);
    float* hwh; cudaGetSymbolAddress((void**)&hwh, g_hWh);

    // K1: h1 = elu(x @ Wg1 + bg1)   [512,1024], K=32768
    sgemm64<1><<<dim3(G1D / 64, BB / 64, 1), 256>>>(
        x, Wg1, bg1, h1, BB, G1D, XDIM, 0, 0);

    // K2: h = elu(h1 @ Wg2 + bg2)   [512,512], K=1024
    sgemm64<1><<<dim3(PDIM / 64, BB / 64, 1), 256>>>(
        h1, Wg2, bg2, h, BB, PDIM, G1D, 0, 0);

    // K3: hWh[d] = h @ Wh[d]        [512,128] x 64, K=512
    sgemm64<0><<<dim3(HDIM / 64, BB / 64, DDIM), 256>>>(
        h, Wh, nullptr, hwh, BB, HDIM, PDIM,
        (long)PDIM * HDIM, (long)BB * HDIM);

    // K4: per-dim 3-layer heads (joint + marginal) + per-d reductions
    cudaFuncSetAttribute(head_kernel,
                         cudaFuncAttributeMaxDynamicSharedMemorySize,
                         HEAD_SMEM_BYTES);
    head_kernel<<<DDIM, 256, HEAD_SMEM_BYTES>>>(z, perm, Wz, b1, W2, b2, W3, b3);

    // K5: scalar
    finalize_kernel<<<1, 32>>>((float*)d_out);
}

// round 3
// speedup vs baseline: 3.1637x; 3.1637x over previous
#include <cuda_runtime.h>
#include <cuda_bf16.h>
#include <math.h>
#include <stdint.h>

// Problem dims
#define BB   512
#define XDIM 32768
#define PDIM 512
#define DDIM 64
#define HDIM 128
#define G1D  1024

// K1 HMMA GEMM config
#define KS     4
#define KCHUNK (XDIM / KS)      // 8192
#define BM 128
#define BN 128
#define BK 32                   // bf16 elems per stage
#define NIT (KCHUNK / BK)       // 256
#define PITCH 40                // smem row pitch in bf16 (80 bytes)
#define MAT_BYTES (128 * PITCH * 2)   // 10240
#define STG_BYTES (4 * MAT_BYTES)     // 40960
#define GEMM_SMEM (2 * STG_BYTES)     // 81920

// ---------------- device scratch (no allocations allowed) ----------------
__device__ __nv_bfloat16 g_xhi[BB * XDIM];     // 32 MB
__device__ __nv_bfloat16 g_xlo[BB * XDIM];     // 32 MB
__device__ __nv_bfloat16 g_wthi[G1D * XDIM];   // 64 MB  (Wg1^T [N][K])
__device__ __nv_bfloat16 g_wtlo[G1D * XDIM];   // 64 MB
__device__ float g_part[KS * BB * G1D];        // 8 MB   (K-split partials)
__device__ float g_h1[BB * G1D];               // 2 MB
__device__ float g_h[BB * PDIM];               // 1 MB
__device__ float g_hWh[DDIM * BB * HDIM];      // 16.8 MB  [d][b][h]
__device__ float g_js[2 * DDIM];
__device__ float g_es[2 * DDIM];

__device__ __forceinline__ float eluf(float x) {
    return x > 0.f ? x : expm1f(x);
}

__device__ __forceinline__ uint32_t smem_u32(const void* p) {
    uint32_t a;
    asm("{ .reg .u64 t; cvta.to.shared.u64 t, %1; cvt.u32.u64 %0, t; }"
        : "=r"(a) : "l"(p));
    return a;
}

#define CP16(dst, src) \
    asm volatile("cp.async.cg.shared.global [%0], [%1], 16;" \
                 :: "r"(dst), "l"(src) : "memory")
#define CP_COMMIT() asm volatile("cp.async.commit_group;" ::: "memory")
#define CP_WAIT1()  asm volatile("cp.async.wait_group 1;" ::: "memory")
#define CP_WAIT0()  asm volatile("cp.async.wait_group 0;" ::: "memory")

__device__ __forceinline__ void ldmx4(uint32_t* r, uint32_t addr) {
    asm volatile("ldmatrix.sync.aligned.m8n8.x4.shared.b16 {%0,%1,%2,%3}, [%4];"
                 : "=r"(r[0]), "=r"(r[1]), "=r"(r[2]), "=r"(r[3]) : "r"(addr));
}
__device__ __forceinline__ void mma16816(float* c, const uint32_t* a,
                                         uint32_t b0, uint32_t b1) {
    asm volatile(
        "mma.sync.aligned.m16n8k16.row.col.f32.bf16.bf16.f32 "
        "{%0,%1,%2,%3}, {%4,%5,%6,%7}, {%8,%9}, {%0,%1,%2,%3};"
        : "+f"(c[0]), "+f"(c[1]), "+f"(c[2]), "+f"(c[3])
        : "r"(a[0]), "r"(a[1]), "r"(a[2]), "r"(a[3]), "r"(b0), "r"(b1));
}

// ---------------- conversion kernels ----------------
__global__ void conv_x_kernel(const float4* __restrict__ x) {
    int i = blockIdx.x * 256 + threadIdx.x;   // float4 index over BB*XDIM/4
    float4 v = x[i];
    __nv_bfloat16 h0 = __float2bfloat16(v.x), h1 = __float2bfloat16(v.y);
    __nv_bfloat16 h2 = __float2bfloat16(v.z), h3 = __float2bfloat16(v.w);
    __nv_bfloat16 l0 = __float2bfloat16(v.x - __bfloat162float(h0));
    __nv_bfloat16 l1 = __float2bfloat16(v.y - __bfloat162float(h1));
    __nv_bfloat16 l2 = __float2bfloat16(v.z - __bfloat162float(h2));
    __nv_bfloat16 l3 = __float2bfloat16(v.w - __bfloat162float(h3));
    __nv_bfloat162* ph = (__nv_bfloat162*)g_xhi;
    __nv_bfloat162* pl = (__nv_bfloat162*)g_xlo;
    __nv_bfloat162 a; a.x = h0; a.y = h1;
    __nv_bfloat162 b; b.x = h2; b.y = h3;
    ph[2 * i] = a; ph[2 * i + 1] = b;
    a.x = l0; a.y = l1; b.x = l2; b.y = l3;
    pl[2 * i] = a; pl[2 * i + 1] = b;
}

// Transpose-convert Wg1 [K][N] fp32 -> wthi/wtlo [N][K] bf16
__global__ void conv_wt_kernel(const float* __restrict__ W) {
    __shared__ float s[64][33];
    const int kt = blockIdx.x * 64;
    const int nt = blockIdx.y * 32;
    const int tx = threadIdx.x & 31, ty = threadIdx.x >> 5;  // 32 x 8
    for (int r = ty; r < 64; r += 8)
        s[r][tx] = W[(size_t)(kt + r) * G1D + nt + tx];
    __syncthreads();
    for (int n = ty; n < 32; n += 8) {
        float a = s[tx * 2][n], b = s[tx * 2 + 1][n];
        __nv_bfloat16 ah = __float2bfloat16(a);
        __nv_bfloat16 bh = __float2bfloat16(b);
        __nv_bfloat16 al = __float2bfloat16(a - __bfloat162float(ah));
        __nv_bfloat16 bl = __float2bfloat16(b - __bfloat162float(bh));
        __nv_bfloat162 vh; vh.x = ah; vh.y = bh;
        __nv_bfloat162 vl; vl.x = al; vl.y = bl;
        ((__nv_bfloat162*)(g_wthi + (size_t)(nt + n) * XDIM + kt))[tx] = vh;
        ((__nv_bfloat162*)(g_wtlo + (size_t)(nt + n) * XDIM + kt))[tx] = vl;
    }
}

// ---------------- K1: bf16-split HMMA GEMM ----------------
// smem per stage: Ah | Al | Bh | Bl, each 128 rows x PITCH bf16.
__device__ __forceinline__ void k1_load_stage(uint32_t sb, int stage,
                                              int mBase, int nBase, int k0,
                                              int tid) {
    uint32_t st = sb + stage * STG_BYTES;
#pragma unroll
    for (int t = 0; t < 2; t++) {
        int ci = tid + t * 256;        // 0..511
        int r = ci >> 2, ch = ci & 3;  // row, 16B chunk
        uint32_t so = (uint32_t)(r * (PITCH * 2) + ch * 16);
        size_t goA = (size_t)(mBase + r) * XDIM + k0 + ch * 8;
        size_t goB = (size_t)(nBase + r) * XDIM + k0 + ch * 8;
        CP16(st + 0 * MAT_BYTES + so, g_xhi + goA);
        CP16(st + 1 * MAT_BYTES + so, g_xlo + goA);
        CP16(st + 2 * MAT_BYTES + so, g_wthi + goB);
        CP16(st + 3 * MAT_BYTES + so, g_wtlo + goB);
    }
}

__global__ void __launch_bounds__(256, 1) gemm_k1_kernel() {
    extern __shared__ char sm[];
    const uint32_t sb = smem_u32(sm);
    const int tid = threadIdx.x;
    const int lane = tid & 31;
    const int wid = tid >> 5;
    const int warpM = wid >> 2;   // 0..1 -> 64 rows
    const int warpN = wid & 3;    // 0..3 -> 32 cols

    const int nBase = blockIdx.x * BN;
    const int mBase = blockIdx.y * BM;
    const int kBase = blockIdx.z * KCHUNK;

    // ldmatrix per-lane address offset (bytes), shared by A and B patterns:
    // row = tile0 + (lane&7) + ((lane>>3)&1)*8 ; col16 = (lane>>4)
    const uint32_t laneOff =
        (uint32_t)(((lane & 7) + ((lane >> 3) & 1) * 8) * (PITCH * 2) +
                   (lane >> 4) * 16);

    float acc[4][4][4];
#pragma unroll
    for (int i = 0; i < 4; i++)
#pragma unroll
        for (int j = 0; j < 4; j++)
#pragma unroll
            for (int k = 0; k < 4; k++) acc[i][j][k] = 0.f;

    k1_load_stage(sb, 0, mBase, nBase, kBase, tid);
    CP_COMMIT();

#pragma unroll 1
    for (int it = 0; it < NIT; it++) {
        if (it + 1 < NIT) {
            k1_load_stage(sb, (it + 1) & 1, mBase, nBase,
                          kBase + (it + 1) * BK, tid);
            CP_COMMIT();
            CP_WAIT1();
        } else {
            CP_WAIT0();
        }
        __syncthreads();

        uint32_t st = sb + (it & 1) * STG_BYTES;
        uint32_t aBaseH = st + 0 * MAT_BYTES + (uint32_t)(warpM * 64) * (PITCH * 2) + laneOff;
        uint32_t aBaseL = st + 1 * MAT_BYTES + (uint32_t)(warpM * 64) * (PITCH * 2) + laneOff;
        uint32_t bBaseH = st + 2 * MAT_BYTES + (uint32_t)(warpN * 32) * (PITCH * 2) + laneOff;
        uint32_t bBaseL = st + 3 * MAT_BYTES + (uint32_t)(warpN * 32) * (PITCH * 2) + laneOff;

#pragma unroll
        for (int ks = 0; ks < 2; ks++) {
            const uint32_t kb = ks * 32;   // 16 bf16 = 32 bytes
            uint32_t ah[4][4], al[4][4], bh[2][4], bl[2][4];
#pragma unroll
            for (int mt = 0; mt < 4; mt++) {
                ldmx4(ah[mt], aBaseH + (uint32_t)(mt * 16) * (PITCH * 2) + kb);
                ldmx4(al[mt], aBaseL + (uint32_t)(mt * 16) * (PITCH * 2) + kb);
            }
#pragma unroll
            for (int p = 0; p < 2; p++) {
                ldmx4(bh[p], bBaseH + (uint32_t)(p * 16) * (PITCH * 2) + kb);
                ldmx4(bl[p], bBaseL + (uint32_t)(p * 16) * (PITCH * 2) + kb);
            }
            // B tile nt regs: {b[nt>>1][nt&1], b[nt>>1][(nt&1)+2]}
#pragma unroll
            for (int mt = 0; mt < 4; mt++) {
#pragma unroll
                for (int nt = 0; nt < 4; nt++) {
                    const int p = nt >> 1, q = nt & 1;
                    mma16816(acc[mt][nt], ah[mt], bh[p][q], bh[p][q + 2]);
                    mma16816(acc[mt][nt], ah[mt], bl[p][q], bl[p][q + 2]);
                    mma16816(acc[mt][nt], al[mt], bh[p][q], bh[p][q + 2]);
                }
            }
        }
        __syncthreads();
    }

    // epilogue: write fp32 partials [kspl][m][n]
    float* base = g_part + (size_t)blockIdx.z * (BB * G1D);
#pragma unroll
    for (int mt = 0; mt < 4; mt++) {
        int m0 = mBase + warpM * 64 + mt * 16 + (lane >> 2);
#pragma unroll
        for (int nt = 0; nt < 4; nt++) {
            int n0 = nBase + warpN * 32 + nt * 8 + (lane & 3) * 2;
            float2 v0 = make_float2(acc[mt][nt][0], acc[mt][nt][1]);
            float2 v1 = make_float2(acc[mt][nt][2], acc[mt][nt][3]);
            *(float2*)(base + (size_t)m0 * G1D + n0) = v0;
            *(float2*)(base + (size_t)(m0 + 8) * G1D + n0) = v1;
        }
    }
}

// partials -> h1 = elu(sum + bias)
__global__ void reduce_h1_kernel(const float* __restrict__ bg1) {
    const int i = blockIdx.x * 256 + threadIdx.x;  // over BB*G1D
    float s = 0.f;
#pragma unroll
    for (int k = 0; k < KS; k++) s += g_part[k * (BB * G1D) + i];
    g_h1[i] = eluf(s + bg1[i & (G1D - 1)]);
}

// ---------------- fp32 tiled SGEMM (K2, K3) ----------------
template <int EPI>
__global__ void sgemm64(const float* __restrict__ A, const float* __restrict__ Bm,
                        const float* __restrict__ bias, float* __restrict__ C,
                        int M, int N, int K, long sB, long sC)
{
    __shared__ __align__(16) float As[16][68];
    __shared__ __align__(16) float Bs[16][64];

    const float* Bz = Bm + (long)blockIdx.z * sB;
    float* Cz = C + (long)blockIdx.z * sC;

    const int tid = threadIdx.x;
    const int tx = tid & 15, ty = tid >> 4;
    const int rowBase = blockIdx.y * 64;
    const int colBase = blockIdx.x * 64;

    const int aRow = tid >> 2;
    const int aCol = (tid & 3) << 2;
    const int bRow = tid >> 4;
    const int bCol = (tid & 15) << 2;

    float acc[4][4];
#pragma unroll
    for (int i = 0; i < 4; i++)
#pragma unroll
        for (int j = 0; j < 4; j++) acc[i][j] = 0.f;

    for (int k0 = 0; k0 < K; k0 += 16) {
        float4 av = *(const float4*)(A + (long)(rowBase + aRow) * K + k0 + aCol);
        As[aCol + 0][aRow] = av.x;
        As[aCol + 1][aRow] = av.y;
        As[aCol + 2][aRow] = av.z;
        As[aCol + 3][aRow] = av.w;
        float4 bv = *(const float4*)(Bz + (long)(k0 + bRow) * N + colBase + bCol);
        *(float4*)&Bs[bRow][bCol] = bv;
        __syncthreads();

#pragma unroll
        for (int kk = 0; kk < 16; kk++) {
            float4 a = *(const float4*)&As[kk][ty << 2];
            float4 b = *(const float4*)&Bs[kk][tx << 2];
            acc[0][0] = fmaf(a.x, b.x, acc[0][0]);
            acc[0][1] = fmaf(a.x, b.y, acc[0][1]);
            acc[0][2] = fmaf(a.x, b.z, acc[0][2]);
            acc[0][3] = fmaf(a.x, b.w, acc[0][3]);
            acc[1][0] = fmaf(a.y, b.x, acc[1][0]);
            acc[1][1] = fmaf(a.y, b.y, acc[1][1]);
            acc[1][2] = fmaf(a.y, b.z, acc[1][2]);
            acc[1][3] = fmaf(a.y, b.w, acc[1][3]);
            acc[2][0] = fmaf(a.z, b.x, acc[2][0]);
            acc[2][1] = fmaf(a.z, b.y, acc[2][1]);
            acc[2][2] = fmaf(a.z, b.z, acc[2][2]);
            acc[2][3] = fmaf(a.z, b.w, acc[2][3]);
            acc[3][0] = fmaf(a.w, b.x, acc[3][0]);
            acc[3][1] = fmaf(a.w, b.y, acc[3][1]);
            acc[3][2] = fmaf(a.w, b.z, acc[3][2]);
            acc[3][3] = fmaf(a.w, b.w, acc[3][3]);
        }
        __syncthreads();
    }

#pragma unroll
    for (int i = 0; i < 4; i++) {
        int r = rowBase + (ty << 2) + i;
#pragma unroll
        for (int j = 0; j < 4; j++) {
            int c = colBase + (tx << 2) + j;
            float v = acc[i][j];
            if (EPI) v = eluf(v + bias[c]);
            Cz[(long)r * N + c] = v;
        }
    }
}

// ---------------- per-dim head (batch-split x2) ----------------
#define HEAD_SMEM_FLOATS (16384 + 4 * 128 + 8 * 256 + 16)
#define HEAD_SMEM_BYTES  (HEAD_SMEM_FLOATS * 4)

__global__ void head_kernel(const float* __restrict__ z, const int* __restrict__ perm,
                            const float* __restrict__ Wz, const float* __restrict__ b1,
                            const float* __restrict__ W2, const float* __restrict__ b2,
                            const float* __restrict__ W3, const float* __restrict__ b3)
{
    extern __shared__ __align__(16) float smf[];
    float* W2s = smf;
    float* Wzs = smf + 16384;
    float* b1s = Wzs + 128;
    float* b2s = b1s + 128;
    float* W3s = b2s + 128;
    float* a1b = W3s + 128;
    float* red = a1b + 8 * 256;

    const int d = blockIdx.x;
    const int split = blockIdx.y;
    const int tid = threadIdx.x;
    const int lane = tid & 31;
    const int warp = tid >> 5;

    const float* W2d = W2 + (size_t)d * HDIM * HDIM;
    for (int i = tid; i < (HDIM * HDIM) / 4; i += 256)
        ((float4*)W2s)[i] = ((const float4*)W2d)[i];
    if (tid < HDIM) {
        Wzs[tid] = Wz[d * HDIM + tid];
        b1s[tid] = b1[d * HDIM + tid];
        b2s[tid] = b2[d * HDIM + tid];
        W3s[tid] = W3[d * HDIM + tid];
    }
    __syncthreads();

    const float b3d = b3[d];
    float* a1j = a1b + warp * 256;
    float* a1m = a1j + 128;
    const float* hb = g_hWh + (size_t)d * BB * HDIM;

    float sumj = 0.f, sume = 0.f;

    for (int it = 0; it < 32; it++) {
        const int b = split * 256 + it * 8 + warp;
        const int pb = perm[b];
        const float zb = z[b * DDIM + d];
        const float* hj = hb + (size_t)b * HDIM;
        const float* hm = hb + (size_t)pb * HDIM;

#pragma unroll
        for (int i = 0; i < 4; i++) {
            int h = lane + 32 * i;
            float w = fmaf(zb, Wzs[h], b1s[h]);
            a1j[h] = eluf(hj[h] + w);
            a1m[h] = eluf(hm[h] + w);
        }
        __syncwarp();

        float aj0 = 0.f, aj1 = 0.f, aj2 = 0.f, aj3 = 0.f;
        float am0 = 0.f, am1 = 0.f, am2 = 0.f, am3 = 0.f;
#pragma unroll 8
        for (int h2 = 0; h2 < HDIM; h2++) {
            float xj = a1j[h2];
            float xm = a1m[h2];
            float4 w = ((const float4*)(W2s + h2 * HDIM))[lane];
            aj0 = fmaf(xj, w.x, aj0); am0 = fmaf(xm, w.x, am0);
            aj1 = fmaf(xj, w.y, aj1); am1 = fmaf(xm, w.y, am1);
            aj2 = fmaf(xj, w.z, aj2); am2 = fmaf(xm, w.z, am2);
            aj3 = fmaf(xj, w.w, aj3); am3 = fmaf(xm, w.w, am3);
        }

        const int k0 = lane * 4;
        float pj = 0.f, pm = 0.f;
        aj0 = eluf(aj0 + b2s[k0 + 0]); pj = fmaf(aj0, W3s[k0 + 0], pj);
        aj1 = eluf(aj1 + b2s[k0 + 1]); pj = fmaf(aj1, W3s[k0 + 1], pj);
        aj2 = eluf(aj2 + b2s[k0 + 2]); pj = fmaf(aj2, W3s[k0 + 2], pj);
        aj3 = eluf(aj3 + b2s[k0 + 3]); pj = fmaf(aj3, W3s[k0 + 3], pj);
        am0 = eluf(am0 + b2s[k0 + 0]); pm = fmaf(am0, W3s[k0 + 0], pm);
        am1 = eluf(am1 + b2s[k0 + 1]); pm = fmaf(am1, W3s[k0 + 1], pm);
        am2 = eluf(am2 + b2s[k0 + 2]); pm = fmaf(am2, W3s[k0 + 2], pm);
        am3 = eluf(am3 + b2s[k0 + 3]); pm = fmaf(am3, W3s[k0 + 3], pm);

#pragma unroll
        for (int off = 16; off; off >>= 1) {
            pj += __shfl_xor_sync(0xffffffffu, pj, off);
            pm += __shfl_xor_sync(0xffffffffu, pm, off);
        }
        sumj += pj + b3d;
        sume += expf(pm + b3d);
        __syncwarp();
    }

    if (lane == 0) { red[warp] = sumj; red[8 + warp] = sume; }
    __syncthreads();
    if (tid == 0) {
        float sj = 0.f, se = 0.f;
#pragma unroll
        for (int w = 0; w < 8; w++) { sj += red[w]; se += red[8 + w]; }
        g_js[d * 2 + split] = sj;
        g_es[d * 2 + split] = se;
    }
}

__global__ void finalize_kernel(float* __restrict__ out)
{
    int t = threadIdx.x;  // 32 threads
    float acc = 0.f;
    for (int d = t; d < DDIM; d += 32) {
        float js = g_js[2 * d] + g_js[2 * d + 1];
        float es = g_es[2 * d] + g_es[2 * d + 1];
        acc += js * (1.f / BB) - logf(es * (1.f / BB));
    }
#pragma unroll
    for (int off = 16; off; off >>= 1)
        acc += __shfl_xor_sync(0xffffffffu, acc, off);
    if (t == 0) out[0] = -acc * (1.f / DDIM);
}

// ---------------------------------------------------------------------------
extern "C" void kernel_launch(void* const* d_in, const int* in_sizes, int n_in,
                              void* d_out, int out_size)
{
    const float* x   = (const float*)d_in[0];
    const float* z   = (const float*)d_in[1];
    const int*   perm= (const int*)  d_in[2];
    const float* Wg1 = (const float*)d_in[3];
    const float* bg1 = (const float*)d_in[4];
    const float* Wg2 = (const float*)d_in[5];
    const float* bg2 = (const float*)d_in[6];
    const float* Wh  = (const float*)d_in[7];
    const float* Wz  = (const float*)d_in[8];
    const float* b1  = (const float*)d_in[9];
    const float* W2  = (const float*)d_in[10];
    const float* b2  = (const float*)d_in[11];
    const float* W3  = (const float*)d_in[12];
    const float* b3  = (const float*)d_in[13];

    float* h1;  cudaGetSymbolAddress((void**)&h1,  g_h1);
    float* h;   cudaGetSymbolAddress((void**)&h,   g_h);
    float* hwh; cudaGetSymbolAddress((void**)&hwh, g_hWh);

    // bf16 hi/lo conversions
    conv_x_kernel<<<(BB * XDIM) / 4 / 256, 256>>>((const float4*)x);
    conv_wt_kernel<<<dim3(XDIM / 64, G1D / 32), 256>>>(Wg1);

    // K1: bf16-split HMMA GEMM -> partials
    cudaFuncSetAttribute(gemm_k1_kernel,
                         cudaFuncAttributeMaxDynamicSharedMemorySize, GEMM_SMEM);
    gemm_k1_kernel<<<dim3(G1D / BN, BB / BM, KS), 256, GEMM_SMEM>>>();

    // reduce partials + bias + elu
    reduce_h1_kernel<<<(BB * G1D) / 256, 256>>>(bg1);

    // K2: h = elu(h1 @ Wg2 + bg2)
    sgemm64<1><<<dim3(PDIM / 64, BB / 64, 1), 256>>>(
        h1, Wg2, bg2, h, BB, PDIM, G1D, 0, 0);

    // K3: hWh[d] = h @ Wh[d]
    sgemm64<0><<<dim3(HDIM / 64, BB / 64, DDIM), 256>>>(
        h, Wh, nullptr, hwh, BB, HDIM, PDIM,
        (long)PDIM * HDIM, (long)BB * HDIM);

    // K4: heads, batch-split x2
    cudaFuncSetAttribute(head_kernel,
                         cudaFuncAttributeMaxDynamicSharedMemorySize,
                         HEAD_SMEM_BYTES);
    head_kernel<<<dim3(DDIM, 2), 256, HEAD_SMEM_BYTES>>>(z, perm, Wz, b1, W2, b2, W3, b3);

    finalize_kernel<<<1, 32>>>((float*)d_out);
}

// round 4
// speedup vs baseline: 3.4597x; 1.0936x over previous
#include <cuda_runtime.h>
#include <cuda_bf16.h>
#include <math.h>
#include <stdint.h>

// Problem dims
#define BB   512
#define XDIM 32768
#define PDIM 512
#define DDIM 64
#define HDIM 128
#define G1D  1024

// HMMA GEMM config (shared by K1/K2/K3)
#define BM 128
#define BN 128
#define BK 32                   // bf16 elems per stage
#define PITCH 40                // smem row pitch in bf16 (80 bytes)
#define MAT_BYTES (128 * PITCH * 2)   // 10240
#define STG_BYTES (4 * MAT_BYTES)     // 40960

// K1 specifics
#define KS     4
#define KCHUNK (XDIM / KS)      // 8192
#define NIT1 (KCHUNK / BK)      // 256
#define K1_SMEM (3 * STG_BYTES)       // 122880 (3-stage)
#define GEMM_SMEM (2 * STG_BYTES)     // 81920  (2-stage, K2/K3)

// ---------------- device scratch (no allocations allowed) ----------------
__device__ __nv_bfloat16 g_xhi[BB * XDIM];     // 32 MB
__device__ __nv_bfloat16 g_xlo[BB * XDIM];     // 32 MB
__device__ __nv_bfloat16 g_wthi[G1D * XDIM];   // 64 MB  (Wg1^T [N][K])
__device__ __nv_bfloat16 g_wtlo[G1D * XDIM];   // 64 MB
__device__ float g_part[KS * BB * G1D];        // 8 MB   (K-split partials)
__device__ __nv_bfloat16 g_h1hi[BB * G1D];     // 1 MB
__device__ __nv_bfloat16 g_h1lo[BB * G1D];     // 1 MB
__device__ __nv_bfloat16 g_wg2thi[PDIM * G1D]; // 1 MB (Wg2^T [512][1024])
__device__ __nv_bfloat16 g_wg2tlo[PDIM * G1D]; // 1 MB
__device__ __nv_bfloat16 g_hhi[BB * PDIM];     // 0.5 MB
__device__ __nv_bfloat16 g_hlo[BB * PDIM];     // 0.5 MB
__device__ __nv_bfloat16 g_whthi[DDIM * HDIM * PDIM];  // 8.4 MB ([d][h][p])
__device__ __nv_bfloat16 g_whtlo[DDIM * HDIM * PDIM];  // 8.4 MB
__device__ float g_hWh[DDIM * BB * HDIM];      // 16.8 MB  [d][b][h]
__device__ float g_js[2 * DDIM];
__device__ float g_es[2 * DDIM];

__device__ __forceinline__ float eluf(float x) {
    return x > 0.f ? x : expm1f(x);
}

__device__ __forceinline__ uint32_t smem_u32(const void* p) {
    uint32_t a;
    asm("{ .reg .u64 t; cvta.to.shared.u64 t, %1; cvt.u32.u64 %0, t; }"
        : "=r"(a) : "l"(p));
    return a;
}

#define CP16(dst, src) \
    asm volatile("cp.async.cg.shared.global [%0], [%1], 16;" \
                 :: "r"(dst), "l"(src) : "memory")
#define CP_COMMIT() asm volatile("cp.async.commit_group;" ::: "memory")
#define CP_WAIT1()  asm volatile("cp.async.wait_group 1;" ::: "memory")
#define CP_WAIT0()  asm volatile("cp.async.wait_group 0;" ::: "memory")

__device__ __forceinline__ void ldmx4(uint32_t* r, uint32_t addr) {
    asm volatile("ldmatrix.sync.aligned.m8n8.x4.shared.b16 {%0,%1,%2,%3}, [%4];"
                 : "=r"(r[0]), "=r"(r[1]), "=r"(r[2]), "=r"(r[3]) : "r"(addr));
}
__device__ __forceinline__ void mma16816(float* c, const uint32_t* a,
                                         uint32_t b0, uint32_t b1) {
    asm volatile(
        "mma.sync.aligned.m16n8k16.row.col.f32.bf16.bf16.f32 "
        "{%0,%1,%2,%3}, {%4,%5,%6,%7}, {%8,%9}, {%0,%1,%2,%3};"
        : "+f"(c[0]), "+f"(c[1]), "+f"(c[2]), "+f"(c[3])
        : "r"(a[0]), "r"(a[1]), "r"(a[2]), "r"(a[3]), "r"(b0), "r"(b1));
}

__device__ __forceinline__ void hilo(float v, __nv_bfloat16& h, __nv_bfloat16& l) {
    h = __float2bfloat16(v);
    l = __float2bfloat16(v - __bfloat162float(h));
}

// ---------------- conversion kernels ----------------
__global__ void conv_x_kernel(const float4* __restrict__ x) {
    int i = blockIdx.x * 256 + threadIdx.x;
    float4 v = x[i];
    __nv_bfloat16 h0, h1, h2, h3, l0, l1, l2, l3;
    hilo(v.x, h0, l0); hilo(v.y, h1, l1);
    hilo(v.z, h2, l2); hilo(v.w, h3, l3);
    __nv_bfloat162* ph = (__nv_bfloat162*)g_xhi;
    __nv_bfloat162* pl = (__nv_bfloat162*)g_xlo;
    __nv_bfloat162 a; a.x = h0; a.y = h1;
    __nv_bfloat162 b; b.x = h2; b.y = h3;
    ph[2 * i] = a; ph[2 * i + 1] = b;
    a.x = l0; a.y = l1; b.x = l2; b.y = l3;
    pl[2 * i] = a; pl[2 * i + 1] = b;
}

// Transpose-convert Wg1 [K][N] fp32 -> wthi/wtlo [N][K] bf16 (specialized, hot)
__global__ void conv_wt_kernel(const float* __restrict__ W) {
    __shared__ float s[64][33];
    const int kt = blockIdx.x * 64;
    const int nt = blockIdx.y * 32;
    const int tx = threadIdx.x & 31, ty = threadIdx.x >> 5;
    for (int r = ty; r < 64; r += 8)
        s[r][tx] = W[(size_t)(kt + r) * G1D + nt + tx];
    __syncthreads();
    for (int n = ty; n < 32; n += 8) {
        float a = s[tx * 2][n], b = s[tx * 2 + 1][n];
        __nv_bfloat16 ah, al, bh, bl;
        hilo(a, ah, al); hilo(b, bh, bl);
        __nv_bfloat162 vh; vh.x = ah; vh.y = bh;
        __nv_bfloat162 vl; vl.x = al; vl.y = bl;
        ((__nv_bfloat162*)(g_wthi + (size_t)(nt + n) * XDIM + kt))[tx] = vh;
        ((__nv_bfloat162*)(g_wtlo + (size_t)(nt + n) * XDIM + kt))[tx] = vl;
    }
}

// Generic transpose-convert: src [R][C] fp32 (batch stride R*C) -> dst [C][R] bf16 hi/lo
__global__ void transconv_kernel(const float* __restrict__ src,
                                 __nv_bfloat16* __restrict__ dhi,
                                 __nv_bfloat16* __restrict__ dlo,
                                 int R, int C) {
    __shared__ float s[32][33];
    const size_t zoff = (size_t)blockIdx.z * R * C;
    const int rt = blockIdx.y * 32, ct = blockIdx.x * 32;
    const int tx = threadIdx.x & 31, ty = threadIdx.x >> 5;  // 32 x 8
    for (int r = ty; r < 32; r += 8)
        s[r][tx] = src[zoff + (size_t)(rt + r) * C + ct + tx];
    __syncthreads();
    for (int c = ty; c < 32; c += 8) {
        float v = s[tx][c];
        __nv_bfloat16 h, l;
        hilo(v, h, l);
        dhi[zoff + (size_t)(ct + c) * R + rt + tx] = h;
        dlo[zoff + (size_t)(ct + c) * R + rt + tx] = l;
    }
}

// ---------------- K1: bf16-split HMMA GEMM (3-stage) ----------------
__device__ __forceinline__ void k1_load_stage(uint32_t sb, int stage,
                                              int mBase, int nBase, int k0,
                                              int tid) {
    uint32_t st = sb + stage * STG_BYTES;
#pragma unroll
    for (int t = 0; t < 2; t++) {
        int ci = tid + t * 256;
        int r = ci >> 2, ch = ci & 3;
        uint32_t so = (uint32_t)(r * (PITCH * 2) + ch * 16);
        size_t goA = (size_t)(mBase + r) * XDIM + k0 + ch * 8;
        size_t goB = (size_t)(nBase + r) * XDIM + k0 + ch * 8;
        CP16(st + 0 * MAT_BYTES + so, g_xhi + goA);
        CP16(st + 1 * MAT_BYTES + so, g_xlo + goA);
        CP16(st + 2 * MAT_BYTES + so, g_wthi + goB);
        CP16(st + 3 * MAT_BYTES + so, g_wtlo + goB);
    }
}

__global__ void __launch_bounds__(256, 1) gemm_k1_kernel() {
    extern __shared__ char sm[];
    const uint32_t sb = smem_u32(sm);
    const int tid = threadIdx.x;
    const int lane = tid & 31;
    const int wid = tid >> 5;
    const int warpM = wid >> 2;
    const int warpN = wid & 3;

    const int nBase = blockIdx.x * BN;
    const int mBase = blockIdx.y * BM;
    const int kBase = blockIdx.z * KCHUNK;

    const uint32_t laneOff =
        (uint32_t)(((lane & 7) + ((lane >> 3) & 1) * 8) * (PITCH * 2) +
                   (lane >> 4) * 16);

    float acc[4][4][4];
#pragma unroll
    for (int i = 0; i < 4; i++)
#pragma unroll
        for (int j = 0; j < 4; j++)
#pragma unroll
            for (int k = 0; k < 4; k++) acc[i][j][k] = 0.f;

    k1_load_stage(sb, 0, mBase, nBase, kBase, tid);
    CP_COMMIT();
    k1_load_stage(sb, 1, mBase, nBase, kBase + BK, tid);
    CP_COMMIT();

#pragma unroll 1
    for (int it = 0; it < NIT1; it++) {
        if (it + 1 < NIT1) CP_WAIT1(); else CP_WAIT0();
        __syncthreads();
        if (it + 2 < NIT1) {
            int s2 = (it + 2) % 3;
            k1_load_stage(sb, s2, mBase, nBase, kBase + (it + 2) * BK, tid);
            CP_COMMIT();
        }

        uint32_t st = sb + (uint32_t)(it % 3) * STG_BYTES;
        uint32_t aBaseH = st + 0 * MAT_BYTES + (uint32_t)(warpM * 64) * (PITCH * 2) + laneOff;
        uint32_t aBaseL = st + 1 * MAT_BYTES + (uint32_t)(warpM * 64) * (PITCH * 2) + laneOff;
        uint32_t bBaseH = st + 2 * MAT_BYTES + (uint32_t)(warpN * 32) * (PITCH * 2) + laneOff;
        uint32_t bBaseL = st + 3 * MAT_BYTES + (uint32_t)(warpN * 32) * (PITCH * 2) + laneOff;

#pragma unroll
        for (int ks = 0; ks < 2; ks++) {
            const uint32_t kb = ks * 32;
            uint32_t ah[4][4], al[4][4], bh[2][4], bl[2][4];
#pragma unroll
            for (int mt = 0; mt < 4; mt++) {
                ldmx4(ah[mt], aBaseH + (uint32_t)(mt * 16) * (PITCH * 2) + kb);
                ldmx4(al[mt], aBaseL + (uint32_t)(mt * 16) * (PITCH * 2) + kb);
            }
#pragma unroll
            for (int p = 0; p < 2; p++) {
                ldmx4(bh[p], bBaseH + (uint32_t)(p * 16) * (PITCH * 2) + kb);
                ldmx4(bl[p], bBaseL + (uint32_t)(p * 16) * (PITCH * 2) + kb);
            }
#pragma unroll
            for (int mt = 0; mt < 4; mt++) {
#pragma unroll
                for (int nt = 0; nt < 4; nt++) {
                    const int p = nt >> 1, q = nt & 1;
                    mma16816(acc[mt][nt], ah[mt], bh[p][q], bh[p][q + 2]);
                    mma16816(acc[mt][nt], ah[mt], bl[p][q], bl[p][q + 2]);
                    mma16816(acc[mt][nt], al[mt], bh[p][q], bh[p][q + 2]);
                }
            }
        }
        __syncthreads();
    }

    float* base = g_part + (size_t)blockIdx.z * (BB * G1D);
#pragma unroll
    for (int mt = 0; mt < 4; mt++) {
        int m0 = mBase + warpM * 64 + mt * 16 + (lane >> 2);
#pragma unroll
        for (int nt = 0; nt < 4; nt++) {
            int n0 = nBase + warpN * 32 + nt * 8 + (lane & 3) * 2;
            *(float2*)(base + (size_t)m0 * G1D + n0) =
                make_float2(acc[mt][nt][0], acc[mt][nt][1]);
            *(float2*)(base + (size_t)(m0 + 8) * G1D + n0) =
                make_float2(acc[mt][nt][2], acc[mt][nt][3]);
        }
    }
}

// partials -> h1 = elu(sum + bias), emitted as bf16 hi/lo
__global__ void reduce_h1_kernel(const float* __restrict__ bg1) {
    const int i = blockIdx.x * 256 + threadIdx.x;
    float s = 0.f;
#pragma unroll
    for (int k = 0; k < KS; k++) s += g_part[k * (BB * G1D) + i];
    float v = eluf(s + bg1[i & (G1D - 1)]);
    __nv_bfloat16 h, l;
    hilo(v, h, l);
    g_h1hi[i] = h;
    g_h1lo[i] = l;
}

// ---------------- unified bf16-split HMMA GEMM (K2, K3) ----------------
// C[M,N](z) = A @ B^T, A [M][K] bf16 hi/lo, B [N][K] bf16 hi/lo.
// EPI=0: fp32 store to C. EPI=1: elu(acc+bias) -> bf16 hi/lo store.
template <int EPI>
__global__ void __launch_bounds__(256, 1) gemm_bs(
    const __nv_bfloat16* __restrict__ Ahi, const __nv_bfloat16* __restrict__ Alo,
    int lda,
    const __nv_bfloat16* __restrict__ Bhi, const __nv_bfloat16* __restrict__ Blo,
    int ldb, long sBz,
    float* __restrict__ C, __nv_bfloat16* __restrict__ Chi,
    __nv_bfloat16* __restrict__ Clo,
    const float* __restrict__ bias, int ldc, long sCz, int K)
{
    extern __shared__ char sm[];
    const uint32_t sb = smem_u32(sm);
    const int tid = threadIdx.x;
    const int lane = tid & 31;
    const int wid = tid >> 5;
    const int warpM = wid >> 2;
    const int warpN = wid & 3;

    const int nBase = blockIdx.x * BN;
    const int mBase = blockIdx.y * BM;
    const __nv_bfloat16* bhi = Bhi + (size_t)blockIdx.z * sBz;
    const __nv_bfloat16* blo = Blo + (size_t)blockIdx.z * sBz;

    const uint32_t laneOff =
        (uint32_t)(((lane & 7) + ((lane >> 3) & 1) * 8) * (PITCH * 2) +
                   (lane >> 4) * 16);
    const int NIT = K / BK;

    float acc[4][4][4];
#pragma unroll
    for (int i = 0; i < 4; i++)
#pragma unroll
        for (int j = 0; j < 4; j++)
#pragma unroll
            for (int k = 0; k < 4; k++) acc[i][j][k] = 0.f;

    // stage loader (lambda-ish macro)
#define BS_LOAD(stage, k0)                                                     \
    do {                                                                       \
        uint32_t st = sb + (uint32_t)(stage)*STG_BYTES;                        \
        _Pragma("unroll")                                                      \
        for (int t = 0; t < 2; t++) {                                          \
            int ci = tid + t * 256;                                            \
            int r = ci >> 2, ch = ci & 3;                                      \
            uint32_t so = (uint32_t)(r * (PITCH * 2) + ch * 16);               \
            size_t goA = (size_t)(mBase + r) * lda + (k0) + ch * 8;            \
            size_t goB = (size_t)(nBase + r) * ldb + (k0) + ch * 8;            \
            CP16(st + 0 * MAT_BYTES + so, Ahi + goA);                          \
            CP16(st + 1 * MAT_BYTES + so, Alo + goA);                          \
            CP16(st + 2 * MAT_BYTES + so, bhi + goB);                          \
            CP16(st + 3 * MAT_BYTES + so, blo + goB);                          \
        }                                                                      \
    } while (0)

    BS_LOAD(0, 0);
    CP_COMMIT();

#pragma unroll 1
    for (int it = 0; it < NIT; it++) {
        if (it + 1 < NIT) {
            BS_LOAD((it + 1) & 1, (it + 1) * BK);
            CP_COMMIT();
            CP_WAIT1();
        } else {
            CP_WAIT0();
        }
        __syncthreads();

        uint32_t st = sb + (uint32_t)(it & 1) * STG_BYTES;
        uint32_t aBaseH = st + 0 * MAT_BYTES + (uint32_t)(warpM * 64) * (PITCH * 2) + laneOff;
        uint32_t aBaseL = st + 1 * MAT_BYTES + (uint32_t)(warpM * 64) * (PITCH * 2) + laneOff;
        uint32_t bBaseH = st + 2 * MAT_BYTES + (uint32_t)(warpN * 32) * (PITCH * 2) + laneOff;
        uint32_t bBaseL = st + 3 * MAT_BYTES + (uint32_t)(warpN * 32) * (PITCH * 2) + laneOff;

#pragma unroll
        for (int ks = 0; ks < 2; ks++) {
            const uint32_t kb = ks * 32;
            uint32_t ah[4][4], al[4][4], bh[2][4], bl[2][4];
#pragma unroll
            for (int mt = 0; mt < 4; mt++) {
                ldmx4(ah[mt], aBaseH + (uint32_t)(mt * 16) * (PITCH * 2) + kb);
                ldmx4(al[mt], aBaseL + (uint32_t)(mt * 16) * (PITCH * 2) + kb);
            }
#pragma unroll
            for (int p = 0; p < 2; p++) {
                ldmx4(bh[p], bBaseH + (uint32_t)(p * 16) * (PITCH * 2) + kb);
                ldmx4(bl[p], bBaseL + (uint32_t)(p * 16) * (PITCH * 2) + kb);
            }
#pragma unroll
            for (int mt = 0; mt < 4; mt++) {
#pragma unroll
                for (int nt = 0; nt < 4; nt++) {
                    const int p = nt >> 1, q = nt & 1;
                    mma16816(acc[mt][nt], ah[mt], bh[p][q], bh[p][q + 2]);
                    mma16816(acc[mt][nt], ah[mt], bl[p][q], bl[p][q + 2]);
                    mma16816(acc[mt][nt], al[mt], bh[p][q], bh[p][q + 2]);
                }
            }
        }
        __syncthreads();
    }
#undef BS_LOAD

#pragma unroll
    for (int mt = 0; mt < 4; mt++) {
        int m0 = mBase + warpM * 64 + mt * 16 + (lane >> 2);
#pragma unroll
        for (int nt = 0; nt < 4; nt++) {
            int n0 = nBase + warpN * 32 + nt * 8 + (lane & 3) * 2;
            if (EPI == 0) {
                float* Cz = C + (size_t)blockIdx.z * sCz;
                *(float2*)(Cz + (size_t)m0 * ldc + n0) =
                    make_float2(acc[mt][nt][0], acc[mt][nt][1]);
                *(float2*)(Cz + (size_t)(m0 + 8) * ldc + n0) =
                    make_float2(acc[mt][nt][2], acc[mt][nt][3]);
            } else {
                float bv0 = bias[n0], bv1 = bias[n0 + 1];
                float u0 = eluf(acc[mt][nt][0] + bv0);
                float u1 = eluf(acc[mt][nt][1] + bv1);
                float u2 = eluf(acc[mt][nt][2] + bv0);
                float u3 = eluf(acc[mt][nt][3] + bv1);
                __nv_bfloat16 h0, h1, h2, h3, l0, l1, l2, l3;
                hilo(u0, h0, l0); hilo(u1, h1, l1);
                hilo(u2, h2, l2); hilo(u3, h3, l3);
                __nv_bfloat162 vh, vl;
                vh.x = h0; vh.y = h1; vl.x = l0; vl.y = l1;
                *(__nv_bfloat162*)(Chi + (size_t)m0 * ldc + n0) = vh;
                *(__nv_bfloat162*)(Clo + (size_t)m0 * ldc + n0) = vl;
                vh.x = h2; vh.y = h3; vl.x = l2; vl.y = l3;
                *(__nv_bfloat162*)(Chi + (size_t)(m0 + 8) * ldc + n0) = vh;
                *(__nv_bfloat162*)(Clo + (size_t)(m0 + 8) * ldc + n0) = vl;
            }
        }
    }
}

// ---------------- per-dim head (batch-split x2, 2 rows/warp/pass) ----------
#define HEAD_SMEM_FLOATS (16384 + 4 * 128 + 8 * 512 + 16)
#define HEAD_SMEM_BYTES  (HEAD_SMEM_FLOATS * 4)

__global__ void head_kernel(const float* __restrict__ z, const int* __restrict__ perm,
                            const float* __restrict__ Wz, const float* __restrict__ b1,
                            const float* __restrict__ W2, const float* __restrict__ b2,
                            const float* __restrict__ W3, const float* __restrict__ b3)
{
    extern __shared__ __align__(16) float smf[];
    float* W2s = smf;                  // 16384
    float* Wzs = smf + 16384;          // 128
    float* b1s = Wzs + 128;
    float* b2s = b1s + 128;
    float* W3s = b2s + 128;
    float* a1b = W3s + 128;            // 8 warps * 512 (128 float4 each)
    float* red = a1b + 8 * 512;        // 16

    const int d = blockIdx.x;
    const int split = blockIdx.y;
    const int tid = threadIdx.x;
    const int lane = tid & 31;
    const int warp = tid >> 5;

    const float* W2d = W2 + (size_t)d * HDIM * HDIM;
    for (int i = tid; i < (HDIM * HDIM) / 4; i += 256)
        ((float4*)W2s)[i] = ((const float4*)W2d)[i];
    if (tid < HDIM) {
        Wzs[tid] = Wz[d * HDIM + tid];
        b1s[tid] = b1[d * HDIM + tid];
        b2s[tid] = b2[d * HDIM + tid];
        W3s[tid] = W3[d * HDIM + tid];
    }
    __syncthreads();

    const float b3d = b3[d];
    float4* a1v = (float4*)(a1b + warp * 512);   // [128] float4: {j0, m0, j1, m1}
    const float* hb = g_hWh + (size_t)d * BB * HDIM;

    float sumj = 0.f, sume = 0.f;

    for (int it = 0; it < 16; it++) {
        const int b0 = split * 256 + it * 16 + warp * 2;
        const int b1i = b0 + 1;
        const int pb0 = perm[b0], pb1 = perm[b1i];
        const float zb0 = z[b0 * DDIM + d];
        const float zb1 = z[b1i * DDIM + d];
        const float* hj0 = hb + (size_t)b0 * HDIM;
        const float* hm0 = hb + (size_t)pb0 * HDIM;
        const float* hj1 = hb + (size_t)b1i * HDIM;
        const float* hm1 = hb + (size_t)pb1 * HDIM;

#pragma unroll
        for (int i = 0; i < 4; i++) {
            int h = lane + 32 * i;
            float w0 = fmaf(zb0, Wzs[h], b1s[h]);
            float w1 = fmaf(zb1, Wzs[h], b1s[h]);
            float4 v;
            v.x = eluf(hj0[h] + w0);
            v.y = eluf(hm0[h] + w0);
            v.z = eluf(hj1[h] + w1);
            v.w = eluf(hm1[h] + w1);
            a1v[h] = v;
        }
        __syncwarp();

        float a0[4] = {0.f, 0.f, 0.f, 0.f};
        float a1_[4] = {0.f, 0.f, 0.f, 0.f};
        float a2[4] = {0.f, 0.f, 0.f, 0.f};
        float a3[4] = {0.f, 0.f, 0.f, 0.f};
#pragma unroll 8
        for (int h2 = 0; h2 < HDIM; h2++) {
            float4 xa = a1v[h2];
            float4 w = ((const float4*)(W2s + h2 * HDIM))[lane];
            a0[0] = fmaf(xa.x, w.x, a0[0]); a0[1] = fmaf(xa.x, w.y, a0[1]);
            a0[2] = fmaf(xa.x, w.z, a0[2]); a0[3] = fmaf(xa.x, w.w, a0[3]);
            a1_[0] = fmaf(xa.y, w.x, a1_[0]); a1_[1] = fmaf(xa.y, w.y, a1_[1]);
            a1_[2] = fmaf(xa.y, w.z, a1_[2]); a1_[3] = fmaf(xa.y, w.w, a1_[3]);
            a2[0] = fmaf(xa.z, w.x, a2[0]); a2[1] = fmaf(xa.z, w.y, a2[1]);
            a2[2] = fmaf(xa.z, w.z, a2[2]); a2[3] = fmaf(xa.z, w.w, a2[3]);
            a3[0] = fmaf(xa.w, w.x, a3[0]); a3[1] = fmaf(xa.w, w.y, a3[1]);
            a3[2] = fmaf(xa.w, w.z, a3[2]); a3[3] = fmaf(xa.w, w.w, a3[3]);
        }

        const int k0 = lane * 4;
        float pj0 = 0.f, pm0 = 0.f, pj1 = 0.f, pm1 = 0.f;
#pragma unroll
        for (int c = 0; c < 4; c++) {
            float bb = b2s[k0 + c], ww = W3s[k0 + c];
            pj0 = fmaf(eluf(a0[c] + bb), ww, pj0);
            pm0 = fmaf(eluf(a1_[c] + bb), ww, pm0);
            pj1 = fmaf(eluf(a2[c] + bb), ww, pj1);
            pm1 = fmaf(eluf(a3[c] + bb), ww, pm1);
        }
#pragma unroll
        for (int off = 16; off; off >>= 1) {
            pj0 += __shfl_xor_sync(0xffffffffu, pj0, off);
            pm0 += __shfl_xor_sync(0xffffffffu, pm0, off);
            pj1 += __shfl_xor_sync(0xffffffffu, pj1, off);
            pm1 += __shfl_xor_sync(0xffffffffu, pm1, off);
        }
        sumj += pj0 + pj1 + 2.f * b3d;
        sume += expf(pm0 + b3d) + expf(pm1 + b3d);
        __syncwarp();
    }

    if (lane == 0) { red[warp] = sumj; red[8 + warp] = sume; }
    __syncthreads();
    if (tid == 0) {
        float sj = 0.f, se = 0.f;
#pragma unroll
        for (int w = 0; w < 8; w++) { sj += red[w]; se += red[8 + w]; }
        g_js[d * 2 + split] = sj;
        g_es[d * 2 + split] = se;
    }
}

__global__ void finalize_kernel(float* __restrict__ out)
{
    int t = threadIdx.x;
    float acc = 0.f;
    for (int d = t; d < DDIM; d += 32) {
        float js = g_js[2 * d] + g_js[2 * d + 1];
        float es = g_es[2 * d] + g_es[2 * d + 1];
        acc += js * (1.f / BB) - logf(es * (1.f / BB));
    }
#pragma unroll
    for (int off = 16; off; off >>= 1)
        acc += __shfl_xor_sync(0xffffffffu, acc, off);
    if (t == 0) out[0] = -acc * (1.f / DDIM);
}

// ---------------------------------------------------------------------------
extern "C" void kernel_launch(void* const* d_in, const int* in_sizes, int n_in,
                              void* d_out, int out_size)
{
    const float* x   = (const float*)d_in[0];
    const float* z   = (const float*)d_in[1];
    const int*   perm= (const int*)  d_in[2];
    const float* Wg1 = (const float*)d_in[3];
    const float* bg1 = (const float*)d_in[4];
    const float* Wg2 = (const float*)d_in[5];
    const float* bg2 = (const float*)d_in[6];
    const float* Wh  = (const float*)d_in[7];
    const float* Wz  = (const float*)d_in[8];
    const float* b1  = (const float*)d_in[9];
    const float* W2  = (const float*)d_in[10];
    const float* b2  = (const float*)d_in[11];
    const float* W3  = (const float*)d_in[12];
    const float* b3  = (const float*)d_in[13];

    __nv_bfloat16 *h1hi, *h1lo, *wg2thi, *wg2tlo, *hhi, *hlo, *whthi, *whtlo;
    float* hwh;
    cudaGetSymbolAddress((void**)&h1hi,   g_h1hi);
    cudaGetSymbolAddress((void**)&h1lo,   g_h1lo);
    cudaGetSymbolAddress((void**)&wg2thi, g_wg2thi);
    cudaGetSymbolAddress((void**)&wg2tlo, g_wg2tlo);
    cudaGetSymbolAddress((void**)&hhi,    g_hhi);
    cudaGetSymbolAddress((void**)&hlo,    g_hlo);
    cudaGetSymbolAddress((void**)&whthi,  g_whthi);
    cudaGetSymbolAddress((void**)&whtlo,  g_whtlo);
    cudaGetSymbolAddress((void**)&hwh,    g_hWh);

    // conversions
    conv_x_kernel<<<(BB * XDIM) / 4 / 256, 256>>>((const float4*)x);
    conv_wt_kernel<<<dim3(XDIM / 64, G1D / 32), 256>>>(Wg1);
    // Wg2 [1024][512] -> [512][1024]
    transconv_kernel<<<dim3(PDIM / 32, G1D / 32, 1), 256>>>(Wg2, wg2thi, wg2tlo,
                                                            G1D, PDIM);
    // Wh [d][512][128] -> [d][128][512]
    transconv_kernel<<<dim3(HDIM / 32, PDIM / 32, DDIM), 256>>>(Wh, whthi, whtlo,
                                                                PDIM, HDIM);

    // K1: bf16-split HMMA GEMM -> partials
    cudaFuncSetAttribute(gemm_k1_kernel,
                         cudaFuncAttributeMaxDynamicSharedMemorySize, K1_SMEM);
    gemm_k1_kernel<<<dim3(G1D / BN, BB / BM, KS), 256, K1_SMEM>>>();

    // reduce partials + bias + elu -> h1 bf16 hi/lo
    reduce_h1_kernel<<<(BB * G1D) / 256, 256>>>(bg1);

    // K2: h = elu(h1 @ Wg2 + bg2) -> bf16 hi/lo
    cudaFuncSetAttribute(gemm_bs<1>,
                         cudaFuncAttributeMaxDynamicSharedMemorySize, GEMM_SMEM);
    gemm_bs<1><<<dim3(PDIM / BN, BB / BM, 1), 256, GEMM_SMEM>>>(
        h1hi, h1lo, G1D, wg2thi, wg2tlo, G1D, 0,
        nullptr, hhi, hlo, bg2, PDIM, 0, G1D);

    // K3: hWh[d] = h @ WhT[d]  (fp32 out)
    cudaFuncSetAttribute(gemm_bs<0>,
                         cudaFuncAttributeMaxDynamicSharedMemorySize, GEMM_SMEM);
    gemm_bs<0><<<dim3(HDIM / BN, BB / BM, DDIM), 256, GEMM_SMEM>>>(
        hhi, hlo, PDIM, whthi, whtlo, PDIM, (long)HDIM * PDIM,
        hwh, nullptr, nullptr, nullptr, HDIM, (long)BB * HDIM, PDIM);

    // K4: heads
    cudaFuncSetAttribute(head_kernel,
                         cudaFuncAttributeMaxDynamicSharedMemorySize,
                         HEAD_SMEM_BYTES);
    head_kernel<<<dim3(DDIM, 2), 256, HEAD_SMEM_BYTES>>>(z, perm, Wz, b1, W2, b2,
                                                         W3, b3);

    finalize_kernel<<<1, 32>>>((float*)d_out);
}

// round 5
// speedup vs baseline: 3.6853x; 1.0652x over previous
#include <cuda_runtime.h>
#include <cuda_bf16.h>
#include <math.h>
#include <stdint.h>

// Problem dims
#define BB   512
#define XDIM 32768
#define PDIM 512
#define DDIM 64
#define HDIM 128
#define G1D  1024

// HMMA GEMM config (shared)
#define BM 128
#define BN 128
#define BK 32                   // bf16 elems per stage
#define PITCH 40                // smem row pitch in bf16 (80 bytes)
#define MAT_BYTES (128 * PITCH * 2)   // 10240
#define STG_BYTES (4 * MAT_BYTES)     // 40960

// K1 specifics
#define KS     4
#define KCHUNK (XDIM / KS)      // 8192
#define NIT1 (KCHUNK / BK)      // 256
#define K1_SMEM (3 * STG_BYTES)       // 122880 (3-stage)
#define GEMM_SMEM (2 * STG_BYTES)     // 81920  (2-stage)

// ---------------- device scratch (no allocations allowed) ----------------
__device__ __nv_bfloat16 g_xhi[BB * XDIM];     // 32 MB
__device__ __nv_bfloat16 g_xlo[BB * XDIM];     // 32 MB
__device__ __nv_bfloat16 g_wthi[G1D * XDIM];   // 64 MB  (Wg1^T [N][K])
__device__ __nv_bfloat16 g_wtlo[G1D * XDIM];   // 64 MB
__device__ float g_part[KS * BB * G1D];        // 8 MB
__device__ __nv_bfloat16 g_h1hi[BB * G1D];     // 1 MB
__device__ __nv_bfloat16 g_h1lo[BB * G1D];     // 1 MB
__device__ __nv_bfloat16 g_wg2thi[PDIM * G1D]; // 1 MB
__device__ __nv_bfloat16 g_wg2tlo[PDIM * G1D]; // 1 MB
__device__ __nv_bfloat16 g_hhi[BB * PDIM];     // 0.5 MB
__device__ __nv_bfloat16 g_hlo[BB * PDIM];     // 0.5 MB
__device__ __nv_bfloat16 g_whthi[DDIM * HDIM * PDIM];  // 8.4 MB ([d][h][p])
__device__ __nv_bfloat16 g_whtlo[DDIM * HDIM * PDIM];  // 8.4 MB
__device__ float g_hWh[DDIM * BB * HDIM];      // 16.8 MB  [d][b][h]
__device__ __nv_bfloat16 g_w2thi[DDIM * HDIM * HDIM];  // 2.1 MB ([d][k][h])
__device__ __nv_bfloat16 g_w2tlo[DDIM * HDIM * HDIM];  // 2.1 MB
__device__ __nv_bfloat16 g_a1hi[DDIM * 2 * BB * HDIM]; // 16.8 MB [d][1024][128]
__device__ __nv_bfloat16 g_a1lo[DDIM * 2 * BB * HDIM]; // 16.8 MB
__device__ float g_a2[DDIM * 2 * BB * HDIM];   // 33.6 MB [d][1024][128]
__device__ float g_js[DDIM * 8];
__device__ float g_es[DDIM * 8];

__device__ __forceinline__ float eluf(float x) {
    return x > 0.f ? x : expm1f(x);
}

__device__ __forceinline__ uint32_t smem_u32(const void* p) {
    uint32_t a;
    asm("{ .reg .u64 t; cvta.to.shared.u64 t, %1; cvt.u32.u64 %0, t; }"
        : "=r"(a) : "l"(p));
    return a;
}

#define CP16(dst, src) \
    asm volatile("cp.async.cg.shared.global [%0], [%1], 16;" \
                 :: "r"(dst), "l"(src) : "memory")
#define CP_COMMIT() asm volatile("cp.async.commit_group;" ::: "memory")
#define CP_WAIT1()  asm volatile("cp.async.wait_group 1;" ::: "memory")
#define CP_WAIT0()  asm volatile("cp.async.wait_group 0;" ::: "memory")

__device__ __forceinline__ void ldmx4(uint32_t* r, uint32_t addr) {
    asm volatile("ldmatrix.sync.aligned.m8n8.x4.shared.b16 {%0,%1,%2,%3}, [%4];"
                 : "=r"(r[0]), "=r"(r[1]), "=r"(r[2]), "=r"(r[3]) : "r"(addr));
}
__device__ __forceinline__ void mma16816(float* c, const uint32_t* a,
                                         uint32_t b0, uint32_t b1) {
    asm volatile(
        "mma.sync.aligned.m16n8k16.row.col.f32.bf16.bf16.f32 "
        "{%0,%1,%2,%3}, {%4,%5,%6,%7}, {%8,%9}, {%0,%1,%2,%3};"
        : "+f"(c[0]), "+f"(c[1]), "+f"(c[2]), "+f"(c[3])
        : "r"(a[0]), "r"(a[1]), "r"(a[2]), "r"(a[3]), "r"(b0), "r"(b1));
}

__device__ __forceinline__ void hilo(float v, __nv_bfloat16& h, __nv_bfloat16& l) {
    h = __float2bfloat16(v);
    l = __float2bfloat16(v - __bfloat162float(h));
}

// ---------------- conversion kernels ----------------
__global__ void conv_x_kernel(const float4* __restrict__ x) {
    int i = blockIdx.x * 256 + threadIdx.x;
    float4 v = x[i];
    __nv_bfloat16 h0, h1, h2, h3, l0, l1, l2, l3;
    hilo(v.x, h0, l0); hilo(v.y, h1, l1);
    hilo(v.z, h2, l2); hilo(v.w, h3, l3);
    __nv_bfloat162* ph = (__nv_bfloat162*)g_xhi;
    __nv_bfloat162* pl = (__nv_bfloat162*)g_xlo;
    __nv_bfloat162 a; a.x = h0; a.y = h1;
    __nv_bfloat162 b; b.x = h2; b.y = h3;
    ph[2 * i] = a; ph[2 * i + 1] = b;
    a.x = l0; a.y = l1; b.x = l2; b.y = l3;
    pl[2 * i] = a; pl[2 * i + 1] = b;
}

// Transpose-convert Wg1 [K][N] fp32 -> wthi/wtlo [N][K] bf16
__global__ void conv_wt_kernel(const float* __restrict__ W) {
    __shared__ float s[64][33];
    const int kt = blockIdx.x * 64;
    const int nt = blockIdx.y * 32;
    const int tx = threadIdx.x & 31, ty = threadIdx.x >> 5;
    for (int r = ty; r < 64; r += 8)
        s[r][tx] = W[(size_t)(kt + r) * G1D + nt + tx];
    __syncthreads();
    for (int n = ty; n < 32; n += 8) {
        float a = s[tx * 2][n], b = s[tx * 2 + 1][n];
        __nv_bfloat16 ah, al, bh, bl;
        hilo(a, ah, al); hilo(b, bh, bl);
        __nv_bfloat162 vh; vh.x = ah; vh.y = bh;
        __nv_bfloat162 vl; vl.x = al; vl.y = bl;
        ((__nv_bfloat162*)(g_wthi + (size_t)(nt + n) * XDIM + kt))[tx] = vh;
        ((__nv_bfloat162*)(g_wtlo + (size_t)(nt + n) * XDIM + kt))[tx] = vl;
    }
}

// Generic transpose-convert: src [R][C] fp32 (batch) -> dst [C][R] bf16 hi/lo
__global__ void transconv_kernel(const float* __restrict__ src,
                                 __nv_bfloat16* __restrict__ dhi,
                                 __nv_bfloat16* __restrict__ dlo,
                                 int R, int C) {
    __shared__ float s[32][33];
    const size_t zoff = (size_t)blockIdx.z * R * C;
    const int rt = blockIdx.y * 32, ct = blockIdx.x * 32;
    const int tx = threadIdx.x & 31, ty = threadIdx.x >> 5;
    for (int r = ty; r < 32; r += 8)
        s[r][tx] = src[zoff + (size_t)(rt + r) * C + ct + tx];
    __syncthreads();
    for (int c = ty; c < 32; c += 8) {
        float v = s[tx][c];
        __nv_bfloat16 h, l;
        hilo(v, h, l);
        dhi[zoff + (size_t)(ct + c) * R + rt + tx] = h;
        dlo[zoff + (size_t)(ct + c) * R + rt + tx] = l;
    }
}

// ---------------- K1: bf16-split HMMA GEMM (3-stage) ----------------
__device__ __forceinline__ void k1_load_stage(uint32_t sb, int stage,
                                              int mBase, int nBase, int k0,
                                              int tid) {
    uint32_t st = sb + stage * STG_BYTES;
#pragma unroll
    for (int t = 0; t < 2; t++) {
        int ci = tid + t * 256;
        int r = ci >> 2, ch = ci & 3;
        uint32_t so = (uint32_t)(r * (PITCH * 2) + ch * 16);
        size_t goA = (size_t)(mBase + r) * XDIM + k0 + ch * 8;
        size_t goB = (size_t)(nBase + r) * XDIM + k0 + ch * 8;
        CP16(st + 0 * MAT_BYTES + so, g_xhi + goA);
        CP16(st + 1 * MAT_BYTES + so, g_xlo + goA);
        CP16(st + 2 * MAT_BYTES + so, g_wthi + goB);
        CP16(st + 3 * MAT_BYTES + so, g_wtlo + goB);
    }
}

__global__ void __launch_bounds__(256, 1) gemm_k1_kernel() {
    extern __shared__ char sm[];
    const uint32_t sb = smem_u32(sm);
    const int tid = threadIdx.x;
    const int lane = tid & 31;
    const int wid = tid >> 5;
    const int warpM = wid >> 2;
    const int warpN = wid & 3;

    const int nBase = blockIdx.x * BN;
    const int mBase = blockIdx.y * BM;
    const int kBase = blockIdx.z * KCHUNK;

    const uint32_t laneOff =
        (uint32_t)(((lane & 7) + ((lane >> 3) & 1) * 8) * (PITCH * 2) +
                   (lane >> 4) * 16);

    float acc[4][4][4];
#pragma unroll
    for (int i = 0; i < 4; i++)
#pragma unroll
        for (int j = 0; j < 4; j++)
#pragma unroll
            for (int k = 0; k < 4; k++) acc[i][j][k] = 0.f;

    k1_load_stage(sb, 0, mBase, nBase, kBase, tid);
    CP_COMMIT();
    k1_load_stage(sb, 1, mBase, nBase, kBase + BK, tid);
    CP_COMMIT();

#pragma unroll 1
    for (int it = 0; it < NIT1; it++) {
        if (it + 1 < NIT1) CP_WAIT1(); else CP_WAIT0();
        __syncthreads();
        if (it + 2 < NIT1) {
            int s2 = (it + 2) % 3;
            k1_load_stage(sb, s2, mBase, nBase, kBase + (it + 2) * BK, tid);
            CP_COMMIT();
        }

        uint32_t st = sb + (uint32_t)(it % 3) * STG_BYTES;
        uint32_t aBaseH = st + 0 * MAT_BYTES + (uint32_t)(warpM * 64) * (PITCH * 2) + laneOff;
        uint32_t aBaseL = st + 1 * MAT_BYTES + (uint32_t)(warpM * 64) * (PITCH * 2) + laneOff;
        uint32_t bBaseH = st + 2 * MAT_BYTES + (uint32_t)(warpN * 32) * (PITCH * 2) + laneOff;
        uint32_t bBaseL = st + 3 * MAT_BYTES + (uint32_t)(warpN * 32) * (PITCH * 2) + laneOff;

#pragma unroll
        for (int ks = 0; ks < 2; ks++) {
            const uint32_t kb = ks * 32;
            uint32_t ah[4][4], al[4][4], bh[2][4], bl[2][4];
#pragma unroll
            for (int mt = 0; mt < 4; mt++) {
                ldmx4(ah[mt], aBaseH + (uint32_t)(mt * 16) * (PITCH * 2) + kb);
                ldmx4(al[mt], aBaseL + (uint32_t)(mt * 16) * (PITCH * 2) + kb);
            }
#pragma unroll
            for (int p = 0; p < 2; p++) {
                ldmx4(bh[p], bBaseH + (uint32_t)(p * 16) * (PITCH * 2) + kb);
                ldmx4(bl[p], bBaseL + (uint32_t)(p * 16) * (PITCH * 2) + kb);
            }
#pragma unroll
            for (int mt = 0; mt < 4; mt++) {
#pragma unroll
                for (int nt = 0; nt < 4; nt++) {
                    const int p = nt >> 1, q = nt & 1;
                    mma16816(acc[mt][nt], ah[mt], bh[p][q], bh[p][q + 2]);
                    mma16816(acc[mt][nt], ah[mt], bl[p][q], bl[p][q + 2]);
                    mma16816(acc[mt][nt], al[mt], bh[p][q], bh[p][q + 2]);
                }
            }
        }
        __syncthreads();
    }

    float* base = g_part + (size_t)blockIdx.z * (BB * G1D);
#pragma unroll
    for (int mt = 0; mt < 4; mt++) {
        int m0 = mBase + warpM * 64 + mt * 16 + (lane >> 2);
#pragma unroll
        for (int nt = 0; nt < 4; nt++) {
            int n0 = nBase + warpN * 32 + nt * 8 + (lane & 3) * 2;
            *(float2*)(base + (size_t)m0 * G1D + n0) =
                make_float2(acc[mt][nt][0], acc[mt][nt][1]);
            *(float2*)(base + (size_t)(m0 + 8) * G1D + n0) =
                make_float2(acc[mt][nt][2], acc[mt][nt][3]);
        }
    }
}

// partials -> h1 = elu(sum + bias), bf16 hi/lo
__global__ void reduce_h1_kernel(const float* __restrict__ bg1) {
    const int i = blockIdx.x * 256 + threadIdx.x;
    float s = 0.f;
#pragma unroll
    for (int k = 0; k < KS; k++) s += g_part[k * (BB * G1D) + i];
    float v = eluf(s + bg1[i & (G1D - 1)]);
    __nv_bfloat16 h, l;
    hilo(v, h, l);
    g_h1hi[i] = h;
    g_h1lo[i] = l;
}

// ---------------- unified bf16-split HMMA GEMM ----------------
// C[M,N](z) = A(z) @ B(z)^T. EPI=0: fp32 C. EPI=1: elu(acc+bias) -> bf16 hi/lo.
template <int EPI>
__global__ void __launch_bounds__(256, 1) gemm_bs(
    const __nv_bfloat16* __restrict__ Ahi, const __nv_bfloat16* __restrict__ Alo,
    int lda, long sAz,
    const __nv_bfloat16* __restrict__ Bhi, const __nv_bfloat16* __restrict__ Blo,
    int ldb, long sBz,
    float* __restrict__ C, __nv_bfloat16* __restrict__ Chi,
    __nv_bfloat16* __restrict__ Clo,
    const float* __restrict__ bias, int ldc, long sCz, int K)
{
    extern __shared__ char sm[];
    const uint32_t sb = smem_u32(sm);
    const int tid = threadIdx.x;
    const int lane = tid & 31;
    const int wid = tid >> 5;
    const int warpM = wid >> 2;
    const int warpN = wid & 3;

    const int nBase = blockIdx.x * BN;
    const int mBase = blockIdx.y * BM;
    const __nv_bfloat16* ahiz = Ahi + (size_t)blockIdx.z * sAz;
    const __nv_bfloat16* aloz = Alo + (size_t)blockIdx.z * sAz;
    const __nv_bfloat16* bhi = Bhi + (size_t)blockIdx.z * sBz;
    const __nv_bfloat16* blo = Blo + (size_t)blockIdx.z * sBz;

    const uint32_t laneOff =
        (uint32_t)(((lane & 7) + ((lane >> 3) & 1) * 8) * (PITCH * 2) +
                   (lane >> 4) * 16);
    const int NIT = K / BK;

    float acc[4][4][4];
#pragma unroll
    for (int i = 0; i < 4; i++)
#pragma unroll
        for (int j = 0; j < 4; j++)
#pragma unroll
            for (int k = 0; k < 4; k++) acc[i][j][k] = 0.f;

#define BS_LOAD(stage, k0)                                                     \
    do {                                                                       \
        uint32_t st = sb + (uint32_t)(stage)*STG_BYTES;                        \
        _Pragma("unroll")                                                      \
        for (int t = 0; t < 2; t++) {                                          \
            int ci = tid + t * 256;                                            \
            int r = ci >> 2, ch = ci & 3;                                      \
            uint32_t so = (uint32_t)(r * (PITCH * 2) + ch * 16);               \
            size_t goA = (size_t)(mBase + r) * lda + (k0) + ch * 8;            \
            size_t goB = (size_t)(nBase + r) * ldb + (k0) + ch * 8;            \
            CP16(st + 0 * MAT_BYTES + so, ahiz + goA);                         \
            CP16(st + 1 * MAT_BYTES + so, aloz + goA);                         \
            CP16(st + 2 * MAT_BYTES + so, bhi + goB);                          \
            CP16(st + 3 * MAT_BYTES + so, blo + goB);                          \
        }                                                                      \
    } while (0)

    BS_LOAD(0, 0);
    CP_COMMIT();

#pragma unroll 1
    for (int it = 0; it < NIT; it++) {
        if (it + 1 < NIT) {
            BS_LOAD((it + 1) & 1, (it + 1) * BK);
            CP_COMMIT();
            CP_WAIT1();
        } else {
            CP_WAIT0();
        }
        __syncthreads();

        uint32_t st = sb + (uint32_t)(it & 1) * STG_BYTES;
        uint32_t aBaseH = st + 0 * MAT_BYTES + (uint32_t)(warpM * 64) * (PITCH * 2) + laneOff;
        uint32_t aBaseL = st + 1 * MAT_BYTES + (uint32_t)(warpM * 64) * (PITCH * 2) + laneOff;
        uint32_t bBaseH = st + 2 * MAT_BYTES + (uint32_t)(warpN * 32) * (PITCH * 2) + laneOff;
        uint32_t bBaseL = st + 3 * MAT_BYTES + (uint32_t)(warpN * 32) * (PITCH * 2) + laneOff;

#pragma unroll
        for (int ks = 0; ks < 2; ks++) {
            const uint32_t kb = ks * 32;
            uint32_t ah[4][4], al[4][4], bh[2][4], bl[2][4];
#pragma unroll
            for (int mt = 0; mt < 4; mt++) {
                ldmx4(ah[mt], aBaseH + (uint32_t)(mt * 16) * (PITCH * 2) + kb);
                ldmx4(al[mt], aBaseL + (uint32_t)(mt * 16) * (PITCH * 2) + kb);
            }
#pragma unroll
            for (int p = 0; p < 2; p++) {
                ldmx4(bh[p], bBaseH + (uint32_t)(p * 16) * (PITCH * 2) + kb);
                ldmx4(bl[p], bBaseL + (uint32_t)(p * 16) * (PITCH * 2) + kb);
            }
#pragma unroll
            for (int mt = 0; mt < 4; mt++) {
#pragma unroll
                for (int nt = 0; nt < 4; nt++) {
                    const int p = nt >> 1, q = nt & 1;
                    mma16816(acc[mt][nt], ah[mt], bh[p][q], bh[p][q + 2]);
                    mma16816(acc[mt][nt], ah[mt], bl[p][q], bl[p][q + 2]);
                    mma16816(acc[mt][nt], al[mt], bh[p][q], bh[p][q + 2]);
                }
            }
        }
        __syncthreads();
    }
#undef BS_LOAD

#pragma unroll
    for (int mt = 0; mt < 4; mt++) {
        int m0 = mBase + warpM * 64 + mt * 16 + (lane >> 2);
#pragma unroll
        for (int nt = 0; nt < 4; nt++) {
            int n0 = nBase + warpN * 32 + nt * 8 + (lane & 3) * 2;
            if (EPI == 0) {
                float* Cz = C + (size_t)blockIdx.z * sCz;
                *(float2*)(Cz + (size_t)m0 * ldc + n0) =
                    make_float2(acc[mt][nt][0], acc[mt][nt][1]);
                *(float2*)(Cz + (size_t)(m0 + 8) * ldc + n0) =
                    make_float2(acc[mt][nt][2], acc[mt][nt][3]);
            } else {
                float bv0 = bias[n0], bv1 = bias[n0 + 1];
                float u0 = eluf(acc[mt][nt][0] + bv0);
                float u1 = eluf(acc[mt][nt][1] + bv1);
                float u2 = eluf(acc[mt][nt][2] + bv0);
                float u3 = eluf(acc[mt][nt][3] + bv1);
                __nv_bfloat16 h0, h1, h2, h3, l0, l1, l2, l3;
                hilo(u0, h0, l0); hilo(u1, h1, l1);
                hilo(u2, h2, l2); hilo(u3, h3, l3);
                __nv_bfloat162 vh, vl;
                vh.x = h0; vh.y = h1; vl.x = l0; vl.y = l1;
                *(__nv_bfloat162*)(Chi + (size_t)m0 * ldc + n0) = vh;
                *(__nv_bfloat162*)(Clo + (size_t)m0 * ldc + n0) = vl;
                vh.x = h2; vh.y = h3; vl.x = l2; vl.y = l3;
                *(__nv_bfloat162*)(Chi + (size_t)(m0 + 8) * ldc + n0) = vh;
                *(__nv_bfloat162*)(Clo + (size_t)(m0 + 8) * ldc + n0) = vl;
            }
        }
    }
}

// ---------------- head stage 1: a1 = elu(hWh + z*Wz + b1), joint + marg -----
// a1 layout [d][1024][128]: rows 0..511 joint (b), rows 512..1023 marg (perm).
__global__ void a1_kernel(const float* __restrict__ z, const int* __restrict__ perm,
                          const float* __restrict__ Wz, const float* __restrict__ b1)
{
    __shared__ float4 wzs[32], b1s[32];
    const int d = blockIdx.x;
    const int by = blockIdx.y;       // 8 chunks of 64 b-rows
    const int tid = threadIdx.x;

    if (tid < 32) {
        wzs[tid] = ((const float4*)(Wz + (size_t)d * HDIM))[tid];
        b1s[tid] = ((const float4*)(b1 + (size_t)d * HDIM))[tid];
    }
    __syncthreads();

    const float* hb = g_hWh + (size_t)d * BB * HDIM;
    __nv_bfloat16* a1h = g_a1hi + (size_t)d * 2 * BB * HDIM;
    __nv_bfloat16* a1l = g_a1lo + (size_t)d * 2 * BB * HDIM;

#pragma unroll
    for (int u = 0; u < 8; u++) {
        const int unit = tid + u * 256;        // 0..2047
        const int bl_ = unit >> 5;             // 0..63
        const int h4 = unit & 31;              // 0..31
        const int b = by * 64 + bl_;
        const int pb = perm[b];
        const float zb = z[(size_t)b * DDIM + d];

        float4 wz = wzs[h4], bb = b1s[h4];
        float4 w;
        w.x = fmaf(zb, wz.x, bb.x); w.y = fmaf(zb, wz.y, bb.y);
        w.z = fmaf(zb, wz.z, bb.z); w.w = fmaf(zb, wz.w, bb.w);

        float4 hj = ((const float4*)(hb + (size_t)b * HDIM))[h4];
        float4 hm = ((const float4*)(hb + (size_t)pb * HDIM))[h4];

        float j0 = eluf(hj.x + w.x), j1 = eluf(hj.y + w.y);
        float j2 = eluf(hj.z + w.z), j3 = eluf(hj.w + w.w);
        float m0 = eluf(hm.x + w.x), m1 = eluf(hm.y + w.y);
        float m2 = eluf(hm.z + w.z), m3 = eluf(hm.w + w.w);

        __nv_bfloat16 h0, h1, h2, h3, l0, l1, l2, l3;
        hilo(j0, h0, l0); hilo(j1, h1, l1); hilo(j2, h2, l2); hilo(j3, h3, l3);
        __nv_bfloat162 p0, p1;
        p0.x = h0; p0.y = h1; p1.x = h2; p1.y = h3;
        ((__nv_bfloat162*)(a1h + (size_t)b * HDIM))[h4 * 2] = p0;
        ((__nv_bfloat162*)(a1h + (size_t)b * HDIM))[h4 * 2 + 1] = p1;
        p0.x = l0; p0.y = l1; p1.x = l2; p1.y = l3;
        ((__nv_bfloat162*)(a1l + (size_t)b * HDIM))[h4 * 2] = p0;
        ((__nv_bfloat162*)(a1l + (size_t)b * HDIM))[h4 * 2 + 1] = p1;

        hilo(m0, h0, l0); hilo(m1, h1, l1); hilo(m2, h2, l2); hilo(m3, h3, l3);
        p0.x = h0; p0.y = h1; p1.x = h2; p1.y = h3;
        ((__nv_bfloat162*)(a1h + (size_t)(BB + b) * HDIM))[h4 * 2] = p0;
        ((__nv_bfloat162*)(a1h + (size_t)(BB + b) * HDIM))[h4 * 2 + 1] = p1;
        p0.x = l0; p0.y = l1; p1.x = l2; p1.y = l3;
        ((__nv_bfloat162*)(a1l + (size_t)(BB + b) * HDIM))[h4 * 2] = p0;
        ((__nv_bfloat162*)(a1l + (size_t)(BB + b) * HDIM))[h4 * 2 + 1] = p1;
    }
}

// ---------------- head stage 3: score + reductions ----------------
// grid (DDIM, 8): each block does 128 rows of a2[d]; chunks 0-3 joint, 4-7 marg.
__global__ void head_final_kernel(const float* __restrict__ b2,
                                  const float* __restrict__ W3,
                                  const float* __restrict__ b3)
{
    __shared__ float b2s[HDIM], w3s[HDIM], red[16];
    const int d = blockIdx.x;
    const int chunk = blockIdx.y;
    const int tid = threadIdx.x;
    const int lane = tid & 31;
    const int warp = tid >> 5;

    if (tid < HDIM) {
        b2s[tid] = b2[(size_t)d * HDIM + tid];
        w3s[tid] = W3[(size_t)d * HDIM + tid];
    }
    __syncthreads();

    const float b3d = b3[d];
    const bool joint = (chunk < 4);
    const float* a2 = g_a2 + (size_t)d * 2 * BB * HDIM + (size_t)chunk * 128 * HDIM;

    float sacc = 0.f;
    const int k0 = lane * 4;
    float bb0 = b2s[k0], bb1 = b2s[k0 + 1], bb2 = b2s[k0 + 2], bb3 = b2s[k0 + 3];
    float w0 = w3s[k0], w1 = w3s[k0 + 1], w2 = w3s[k0 + 2], w3v = w3s[k0 + 3];

#pragma unroll 4
    for (int i = 0; i < 16; i++) {
        const int r = warp * 16 + i;
        float4 v = ((const float4*)(a2 + (size_t)r * HDIM))[lane];
        float p = eluf(v.x + bb0) * w0 + eluf(v.y + bb1) * w1 +
                  eluf(v.z + bb2) * w2 + eluf(v.w + bb3) * w3v;
#pragma unroll
        for (int off = 16; off; off >>= 1)
            p += __shfl_xor_sync(0xffffffffu, p, off);
        float score = p + b3d;
        sacc += joint ? score : expf(score);
    }

    if (lane == 0) red[warp] = sacc;
    __syncthreads();
    if (tid == 0) {
        float s = 0.f;
#pragma unroll
        for (int w = 0; w < 8; w++) s += red[w];
        if (joint) { g_js[d * 8 + chunk] = s; g_es[d * 8 + chunk] = 0.f; }
        else       { g_js[d * 8 + chunk] = 0.f; g_es[d * 8 + chunk] = s; }
    }
}

__global__ void finalize_kernel(float* __restrict__ out)
{
    int t = threadIdx.x;
    float acc = 0.f;
    for (int d = t; d < DDIM; d += 32) {
        float js = 0.f, es = 0.f;
#pragma unroll
        for (int c = 0; c < 8; c++) { js += g_js[d * 8 + c]; es += g_es[d * 8 + c]; }
        acc += js * (1.f / BB) - logf(es * (1.f / BB));
    }
#pragma unroll
    for (int off = 16; off; off >>= 1)
        acc += __shfl_xor_sync(0xffffffffu, acc, off);
    if (t == 0) out[0] = -acc * (1.f / DDIM);
}

// ---------------------------------------------------------------------------
extern "C" void kernel_launch(void* const* d_in, const int* in_sizes, int n_in,
                              void* d_out, int out_size)
{
    const float* x   = (const float*)d_in[0];
    const float* z   = (const float*)d_in[1];
    const int*   perm= (const int*)  d_in[2];
    const float* Wg1 = (const float*)d_in[3];
    const float* bg1 = (const float*)d_in[4];
    const float* Wg2 = (const float*)d_in[5];
    const float* bg2 = (const float*)d_in[6];
    const float* Wh  = (const float*)d_in[7];
    const float* Wz  = (const float*)d_in[8];
    const float* b1  = (const float*)d_in[9];
    const float* W2  = (const float*)d_in[10];
    const float* b2  = (const float*)d_in[11];
    const float* W3  = (const float*)d_in[12];
    const float* b3  = (const float*)d_in[13];

    __nv_bfloat16 *h1hi, *h1lo, *wg2thi, *wg2tlo, *hhi, *hlo, *whthi, *whtlo;
    __nv_bfloat16 *w2thi, *w2tlo, *a1hi, *a1lo;
    float *hwh, *a2;
    cudaGetSymbolAddress((void**)&h1hi,   g_h1hi);
    cudaGetSymbolAddress((void**)&h1lo,   g_h1lo);
    cudaGetSymbolAddress((void**)&wg2thi, g_wg2thi);
    cudaGetSymbolAddress((void**)&wg2tlo, g_wg2tlo);
    cudaGetSymbolAddress((void**)&hhi,    g_hhi);
    cudaGetSymbolAddress((void**)&hlo,    g_hlo);
    cudaGetSymbolAddress((void**)&whthi,  g_whthi);
    cudaGetSymbolAddress((void**)&whtlo,  g_whtlo);
    cudaGetSymbolAddress((void**)&w2thi,  g_w2thi);
    cudaGetSymbolAddress((void**)&w2tlo,  g_w2tlo);
    cudaGetSymbolAddress((void**)&a1hi,   g_a1hi);
    cudaGetSymbolAddress((void**)&a1lo,   g_a1lo);
    cudaGetSymbolAddress((void**)&hwh,    g_hWh);
    cudaGetSymbolAddress((void**)&a2,     g_a2);

    // conversions
    conv_x_kernel<<<(BB * XDIM) / 4 / 256, 256>>>((const float4*)x);
    conv_wt_kernel<<<dim3(XDIM / 64, G1D / 32), 256>>>(Wg1);
    transconv_kernel<<<dim3(PDIM / 32, G1D / 32, 1), 256>>>(Wg2, wg2thi, wg2tlo,
                                                            G1D, PDIM);
    transconv_kernel<<<dim3(HDIM / 32, PDIM / 32, DDIM), 256>>>(Wh, whthi, whtlo,
                                                                PDIM, HDIM);
    // W2 [d][in][out] -> [d][out][in]
    transconv_kernel<<<dim3(HDIM / 32, HDIM / 32, DDIM), 256>>>(W2, w2thi, w2tlo,
                                                                HDIM, HDIM);

    // K1
    cudaFuncSetAttribute(gemm_k1_kernel,
                         cudaFuncAttributeMaxDynamicSharedMemorySize, K1_SMEM);
    gemm_k1_kernel<<<dim3(G1D / BN, BB / BM, KS), 256, K1_SMEM>>>();
    reduce_h1_kernel<<<(BB * G1D) / 256, 256>>>(bg1);

    cudaFuncSetAttribute(gemm_bs<1>,
                         cudaFuncAttributeMaxDynamicSharedMemorySize, GEMM_SMEM);
    cudaFuncSetAttribute(gemm_bs<0>,
                         cudaFuncAttributeMaxDynamicSharedMemorySize, GEMM_SMEM);

    // K2: h = elu(h1 @ Wg2 + bg2) -> bf16 hi/lo
    gemm_bs<1><<<dim3(PDIM / BN, BB / BM, 1), 256, GEMM_SMEM>>>(
        h1hi, h1lo, G1D, 0, wg2thi, wg2tlo, G1D, 0,
        nullptr, hhi, hlo, bg2, PDIM, 0, G1D);

    // K3: hWh[d] = h @ WhT[d]  (fp32)
    gemm_bs<0><<<dim3(HDIM / BN, BB / BM, DDIM), 256, GEMM_SMEM>>>(
        hhi, hlo, PDIM, 0, whthi, whtlo, PDIM, (long)HDIM * PDIM,
        hwh, nullptr, nullptr, nullptr, HDIM, (long)BB * HDIM, PDIM);

    // head stage 1: a1 (joint + marg) bf16 hi/lo
    a1_kernel<<<dim3(DDIM, BB / 64), 256>>>(z, perm, Wz, b1);

    // head stage 2: a2 = a1 @ W2T[d]  (fp32, pre-bias)
    gemm_bs<0><<<dim3(1, (2 * BB) / BM, DDIM), 256, GEMM_SMEM>>>(
        a1hi, a1lo, HDIM, (long)2 * BB * HDIM,
        w2thi, w2tlo, HDIM, (long)HDIM * HDIM,
        a2, nullptr, nullptr, nullptr, HDIM, (long)2 * BB * HDIM, HDIM);

    // head stage 3: scores + reductions
    head_final_kernel<<<dim3(DDIM, 8), 256>>>(b2, W3, b3);

    finalize_kernel<<<1, 32>>>((float*)d_out);
}

// round 6
// speedup vs baseline: 3.9350x; 1.0678x over previous
#include <cuda_runtime.h>
#include <cuda_bf16.h>
#include <math.h>
#include <stdint.h>

// Problem dims
#define BB   512
#define XDIM 32768
#define PDIM 512
#define DDIM 64
#define HDIM 128
#define G1D  1024

// Shared HMMA config
#define BM 128
#define BK 32                   // bf16 per k-stage
#define PITCH 40                // smem row pitch bf16 (80 B)
#define ROWB (PITCH * 2)        // 80

// gemm_bs (BN=128) layout
#define MAT_BYTES (128 * ROWB)        // 10240
#define STG_BYTES (4 * MAT_BYTES)     // 40960
#define GEMM_SMEM (2 * STG_BYTES)     // 81920

// K1 (BN=256, KS=8, 3-stage)
#define K1_BN 256
#define K1_KS 8
#define K1_KCHUNK (XDIM / K1_KS)      // 4096
#define K1_NIT (K1_KCHUNK / BK)       // 128
#define MAT_A 10240
#define MAT_B (256 * ROWB)            // 20480
#define K1_STG (2 * MAT_A + 2 * MAT_B)  // 61440
#define K1_SMEM (3 * K1_STG)            // 184320
#define K1_AH 0
#define K1_AL MAT_A
#define K1_BH (2 * MAT_A)
#define K1_BL (2 * MAT_A + MAT_B)

// ---------------- device scratch ----------------
__device__ __nv_bfloat16 g_xhi[BB * XDIM];
__device__ __nv_bfloat16 g_xlo[BB * XDIM];
__device__ __nv_bfloat16 g_wthi[G1D * XDIM];
__device__ __nv_bfloat16 g_wtlo[G1D * XDIM];
__device__ float g_part[K1_KS * BB * G1D];     // 16 MB
__device__ __nv_bfloat16 g_h1hi[BB * G1D];
__device__ __nv_bfloat16 g_h1lo[BB * G1D];
__device__ __nv_bfloat16 g_wg2thi[PDIM * G1D];
__device__ __nv_bfloat16 g_wg2tlo[PDIM * G1D];
__device__ __nv_bfloat16 g_hhi[BB * PDIM];
__device__ __nv_bfloat16 g_hlo[BB * PDIM];
__device__ __nv_bfloat16 g_whthi[DDIM * HDIM * PDIM];
__device__ __nv_bfloat16 g_whtlo[DDIM * HDIM * PDIM];
__device__ float g_hWh[DDIM * BB * HDIM];
__device__ __nv_bfloat16 g_w2thi[DDIM * HDIM * HDIM];
__device__ __nv_bfloat16 g_w2tlo[DDIM * HDIM * HDIM];
__device__ __nv_bfloat16 g_a1hi[DDIM * 2 * BB * HDIM];
__device__ __nv_bfloat16 g_a1lo[DDIM * 2 * BB * HDIM];
__device__ float g_js[DDIM * 8];
__device__ float g_es[DDIM * 8];

__device__ __forceinline__ float eluf(float x) {
    return x > 0.f ? x : expm1f(x);
}
__device__ __forceinline__ uint32_t smem_u32(const void* p) {
    uint32_t a;
    asm("{ .reg .u64 t; cvta.to.shared.u64 t, %1; cvt.u32.u64 %0, t; }"
        : "=r"(a) : "l"(p));
    return a;
}
#define CP16(dst, src) \
    asm volatile("cp.async.cg.shared.global [%0], [%1], 16;" \
                 :: "r"(dst), "l"(src) : "memory")
#define CP_COMMIT() asm volatile("cp.async.commit_group;" ::: "memory")
#define CP_WAIT1()  asm volatile("cp.async.wait_group 1;" ::: "memory")
#define CP_WAIT0()  asm volatile("cp.async.wait_group 0;" ::: "memory")

__device__ __forceinline__ void ldmx4(uint32_t* r, uint32_t addr) {
    asm volatile("ldmatrix.sync.aligned.m8n8.x4.shared.b16 {%0,%1,%2,%3}, [%4];"
                 : "=r"(r[0]), "=r"(r[1]), "=r"(r[2]), "=r"(r[3]) : "r"(addr));
}
__device__ __forceinline__ void mma16816(float* c, const uint32_t* a,
                                         uint32_t b0, uint32_t b1) {
    asm volatile(
        "mma.sync.aligned.m16n8k16.row.col.f32.bf16.bf16.f32 "
        "{%0,%1,%2,%3}, {%4,%5,%6,%7}, {%8,%9}, {%0,%1,%2,%3};"
        : "+f"(c[0]), "+f"(c[1]), "+f"(c[2]), "+f"(c[3])
        : "r"(a[0]), "r"(a[1]), "r"(a[2]), "r"(a[3]), "r"(b0), "r"(b1));
}
__device__ __forceinline__ void hilo(float v, __nv_bfloat16& h, __nv_bfloat16& l) {
    h = __float2bfloat16(v);
    l = __float2bfloat16(v - __bfloat162float(h));
}

// ---------------- conversions ----------------
__global__ void conv_x_kernel(const float4* __restrict__ x) {
    int i = blockIdx.x * 256 + threadIdx.x;
    float4 v = x[i];
    __nv_bfloat16 h0, h1, h2, h3, l0, l1, l2, l3;
    hilo(v.x, h0, l0); hilo(v.y, h1, l1);
    hilo(v.z, h2, l2); hilo(v.w, h3, l3);
    __nv_bfloat162* ph = (__nv_bfloat162*)g_xhi;
    __nv_bfloat162* pl = (__nv_bfloat162*)g_xlo;
    __nv_bfloat162 a; a.x = h0; a.y = h1;
    __nv_bfloat162 b; b.x = h2; b.y = h3;
    ph[2 * i] = a; ph[2 * i + 1] = b;
    a.x = l0; a.y = l1; b.x = l2; b.y = l3;
    pl[2 * i] = a; pl[2 * i + 1] = b;
}

__global__ void conv_wt_kernel(const float* __restrict__ W) {
    __shared__ float s[64][33];
    const int kt = blockIdx.x * 64;
    const int nt = blockIdx.y * 32;
    const int tx = threadIdx.x & 31, ty = threadIdx.x >> 5;
    for (int r = ty; r < 64; r += 8)
        s[r][tx] = W[(size_t)(kt + r) * G1D + nt + tx];
    __syncthreads();
    for (int n = ty; n < 32; n += 8) {
        float a = s[tx * 2][n], b = s[tx * 2 + 1][n];
        __nv_bfloat16 ah, al, bh, bl;
        hilo(a, ah, al); hilo(b, bh, bl);
        __nv_bfloat162 vh; vh.x = ah; vh.y = bh;
        __nv_bfloat162 vl; vl.x = al; vl.y = bl;
        ((__nv_bfloat162*)(g_wthi + (size_t)(nt + n) * XDIM + kt))[tx] = vh;
        ((__nv_bfloat162*)(g_wtlo + (size_t)(nt + n) * XDIM + kt))[tx] = vl;
    }
}

__global__ void transconv_kernel(const float* __restrict__ src,
                                 __nv_bfloat16* __restrict__ dhi,
                                 __nv_bfloat16* __restrict__ dlo,
                                 int R, int C) {
    __shared__ float s[32][33];
    const size_t zoff = (size_t)blockIdx.z * R * C;
    const int rt = blockIdx.y * 32, ct = blockIdx.x * 32;
    const int tx = threadIdx.x & 31, ty = threadIdx.x >> 5;
    for (int r = ty; r < 32; r += 8)
        s[r][tx] = src[zoff + (size_t)(rt + r) * C + ct + tx];
    __syncthreads();
    for (int c = ty; c < 32; c += 8) {
        float v = s[tx][c];
        __nv_bfloat16 h, l;
        hilo(v, h, l);
        dhi[zoff + (size_t)(ct + c) * R + rt + tx] = h;
        dlo[zoff + (size_t)(ct + c) * R + rt + tx] = l;
    }
}

// ---------------- K1: bf16-split HMMA, BM=128 BN=256, 3-stage ----------------
__device__ __forceinline__ void k1_load_stage(uint32_t sb, int stage,
                                              int mBase, int nBase, int k0,
                                              int tid) {
    uint32_t st = sb + (uint32_t)stage * K1_STG;
#pragma unroll
    for (int t = 0; t < 2; t++) {          // A: 128 rows x 4 chunks
        int ci = tid + t * 256;
        int r = ci >> 2, ch = ci & 3;
        uint32_t so = (uint32_t)(r * ROWB + ch * 16);
        size_t go = (size_t)(mBase + r) * XDIM + k0 + ch * 8;
        CP16(st + K1_AH + so, g_xhi + go);
        CP16(st + K1_AL + so, g_xlo + go);
    }
#pragma unroll
    for (int t = 0; t < 4; t++) {          // B: 256 rows x 4 chunks
        int ci = tid + t * 256;
        int r = ci >> 2, ch = ci & 3;
        uint32_t so = (uint32_t)(r * ROWB + ch * 16);
        size_t go = (size_t)(nBase + r) * XDIM + k0 + ch * 8;
        CP16(st + K1_BH + so, g_wthi + go);
        CP16(st + K1_BL + so, g_wtlo + go);
    }
}

__global__ void __launch_bounds__(256, 1) gemm_k1_kernel() {
    extern __shared__ char sm[];
    const uint32_t sb = smem_u32(sm);
    const int tid = threadIdx.x;
    const int lane = tid & 31;
    const int wid = tid >> 5;
    const int warpM = wid >> 2;   // 0..1 -> 64 rows
    const int warpN = wid & 3;    // 0..3 -> 64 cols

    const int nBase = blockIdx.x * K1_BN;
    const int mBase = blockIdx.y * BM;
    const int kBase = blockIdx.z * K1_KCHUNK;

    const uint32_t laneOff =
        (uint32_t)(((lane & 7) + ((lane >> 3) & 1) * 8) * ROWB + (lane >> 4) * 16);

    float acc[4][8][4];
#pragma unroll
    for (int i = 0; i < 4; i++)
#pragma unroll
        for (int j = 0; j < 8; j++)
#pragma unroll
            for (int k = 0; k < 4; k++) acc[i][j][k] = 0.f;

    k1_load_stage(sb, 0, mBase, nBase, kBase, tid);
    CP_COMMIT();
    k1_load_stage(sb, 1, mBase, nBase, kBase + BK, tid);
    CP_COMMIT();

#pragma unroll 1
    for (int it = 0; it < K1_NIT; it++) {
        if (it + 1 < K1_NIT) CP_WAIT1(); else CP_WAIT0();
        __syncthreads();
        if (it + 2 < K1_NIT) {
            k1_load_stage(sb, (it + 2) % 3, mBase, nBase,
                          kBase + (it + 2) * BK, tid);
            CP_COMMIT();
        }

        uint32_t st = sb + (uint32_t)(it % 3) * K1_STG;
        uint32_t aH = st + K1_AH + (uint32_t)(warpM * 64) * ROWB + laneOff;
        uint32_t aL = st + K1_AL + (uint32_t)(warpM * 64) * ROWB + laneOff;
        uint32_t bH = st + K1_BH + (uint32_t)(warpN * 64) * ROWB + laneOff;
        uint32_t bL = st + K1_BL + (uint32_t)(warpN * 64) * ROWB + laneOff;

#pragma unroll
        for (int ks = 0; ks < 2; ks++) {
            const uint32_t kb = ks * 32;
            uint32_t ah[4][4], al[4][4], bh[4][4], bl[4][4];
#pragma unroll
            for (int mt = 0; mt < 4; mt++) {
                ldmx4(ah[mt], aH + (uint32_t)(mt * 16) * ROWB + kb);
                ldmx4(al[mt], aL + (uint32_t)(mt * 16) * ROWB + kb);
            }
#pragma unroll
            for (int p = 0; p < 4; p++) {
                ldmx4(bh[p], bH + (uint32_t)(p * 16) * ROWB + kb);
                ldmx4(bl[p], bL + (uint32_t)(p * 16) * ROWB + kb);
            }
#pragma unroll
            for (int mt = 0; mt < 4; mt++) {
#pragma unroll
                for (int nt = 0; nt < 8; nt++) {
                    const int p = nt >> 1, q = nt & 1;
                    mma16816(acc[mt][nt], ah[mt], bh[p][q], bh[p][q + 2]);
                    mma16816(acc[mt][nt], ah[mt], bl[p][q], bl[p][q + 2]);
                    mma16816(acc[mt][nt], al[mt], bh[p][q], bh[p][q + 2]);
                }
            }
        }
        __syncthreads();
    }

    float* base = g_part + (size_t)blockIdx.z * (BB * G1D);
#pragma unroll
    for (int mt = 0; mt < 4; mt++) {
        int m0 = mBase + warpM * 64 + mt * 16 + (lane >> 2);
#pragma unroll
        for (int nt = 0; nt < 8; nt++) {
            int n0 = nBase + warpN * 64 + nt * 8 + (lane & 3) * 2;
            *(float2*)(base + (size_t)m0 * G1D + n0) =
                make_float2(acc[mt][nt][0], acc[mt][nt][1]);
            *(float2*)(base + (size_t)(m0 + 8) * G1D + n0) =
                make_float2(acc[mt][nt][2], acc[mt][nt][3]);
        }
    }
}

// partials -> h1 = elu(sum + bias), bf16 hi/lo
__global__ void reduce_h1_kernel(const float* __restrict__ bg1) {
    const int i = blockIdx.x * 256 + threadIdx.x;
    float s = 0.f;
#pragma unroll
    for (int k = 0; k < K1_KS; k++) s += g_part[k * (BB * G1D) + i];
    float v = eluf(s + bg1[i & (G1D - 1)]);
    __nv_bfloat16 h, l;
    hilo(v, h, l);
    g_h1hi[i] = h;
    g_h1lo[i] = l;
}

// ---------------- unified bf16-split HMMA GEMM (BN=128) ----------------
// EPI=0: fp32 C. EPI=1: elu(acc+bias)->bf16 hi/lo. EPI=2: fused head epilogue
// (scores + joint/exp reductions; grid (1, 8 chunks, DDIM)).
template <int EPI>
__global__ void __launch_bounds__(256, 1) gemm_bs(
    const __nv_bfloat16* __restrict__ Ahi, const __nv_bfloat16* __restrict__ Alo,
    int lda, long sAz,
    const __nv_bfloat16* __restrict__ Bhi, const __nv_bfloat16* __restrict__ Blo,
    int ldb, long sBz,
    float* __restrict__ C, __nv_bfloat16* __restrict__ Chi,
    __nv_bfloat16* __restrict__ Clo,
    const float* __restrict__ bias, int ldc, long sCz, int K,
    const float* __restrict__ b2, const float* __restrict__ W3,
    const float* __restrict__ b3)
{
    extern __shared__ char sm[];
    __shared__ float red[128][5];
    __shared__ float wr[8];
    const uint32_t sb = smem_u32(sm);
    const int tid = threadIdx.x;
    const int lane = tid & 31;
    const int wid = tid >> 5;
    const int warpM = wid >> 2;
    const int warpN = wid & 3;

    const int nBase = blockIdx.x * 128;
    const int mBase = blockIdx.y * BM;
    const __nv_bfloat16* ahiz = Ahi + (size_t)blockIdx.z * sAz;
    const __nv_bfloat16* aloz = Alo + (size_t)blockIdx.z * sAz;
    const __nv_bfloat16* bhi = Bhi + (size_t)blockIdx.z * sBz;
    const __nv_bfloat16* blo = Blo + (size_t)blockIdx.z * sBz;

    const uint32_t laneOff =
        (uint32_t)(((lane & 7) + ((lane >> 3) & 1) * 8) * ROWB + (lane >> 4) * 16);
    const int NIT = K / BK;

    float acc[4][4][4];
#pragma unroll
    for (int i = 0; i < 4; i++)
#pragma unroll
        for (int j = 0; j < 4; j++)
#pragma unroll
            for (int k = 0; k < 4; k++) acc[i][j][k] = 0.f;

#define BS_LOAD(stage, k0)                                                     \
    do {                                                                       \
        uint32_t st = sb + (uint32_t)(stage)*STG_BYTES;                        \
        _Pragma("unroll")                                                      \
        for (int t = 0; t < 2; t++) {                                          \
            int ci = tid + t * 256;                                            \
            int r = ci >> 2, ch = ci & 3;                                      \
            uint32_t so = (uint32_t)(r * ROWB + ch * 16);                      \
            size_t goA = (size_t)(mBase + r) * lda + (k0) + ch * 8;            \
            size_t goB = (size_t)(nBase + r) * ldb + (k0) + ch * 8;            \
            CP16(st + 0 * MAT_BYTES + so, ahiz + goA);                         \
            CP16(st + 1 * MAT_BYTES + so, aloz + goA);                         \
            CP16(st + 2 * MAT_BYTES + so, bhi + goB);                          \
            CP16(st + 3 * MAT_BYTES + so, blo + goB);                          \
        }                                                                      \
    } while (0)

    BS_LOAD(0, 0);
    CP_COMMIT();

#pragma unroll 1
    for (int it = 0; it < NIT; it++) {
        if (it + 1 < NIT) {
            BS_LOAD((it + 1) & 1, (it + 1) * BK);
            CP_COMMIT();
            CP_WAIT1();
        } else {
            CP_WAIT0();
        }
        __syncthreads();

        uint32_t st = sb + (uint32_t)(it & 1) * STG_BYTES;
        uint32_t aH = st + 0 * MAT_BYTES + (uint32_t)(warpM * 64) * ROWB + laneOff;
        uint32_t aL = st + 1 * MAT_BYTES + (uint32_t)(warpM * 64) * ROWB + laneOff;
        uint32_t bH = st + 2 * MAT_BYTES + (uint32_t)(warpN * 32) * ROWB + laneOff;
        uint32_t bL = st + 3 * MAT_BYTES + (uint32_t)(warpN * 32) * ROWB + laneOff;

#pragma unroll
        for (int ks = 0; ks < 2; ks++) {
            const uint32_t kb = ks * 32;
            uint32_t ah[4][4], al[4][4], bh[2][4], bl[2][4];
#pragma unroll
            for (int mt = 0; mt < 4; mt++) {
                ldmx4(ah[mt], aH + (uint32_t)(mt * 16) * ROWB + kb);
                ldmx4(al[mt], aL + (uint32_t)(mt * 16) * ROWB + kb);
            }
#pragma unroll
            for (int p = 0; p < 2; p++) {
                ldmx4(bh[p], bH + (uint32_t)(p * 16) * ROWB + kb);
                ldmx4(bl[p], bL + (uint32_t)(p * 16) * ROWB + kb);
            }
#pragma unroll
            for (int mt = 0; mt < 4; mt++) {
#pragma unroll
                for (int nt = 0; nt < 4; nt++) {
                    const int p = nt >> 1, q = nt & 1;
                    mma16816(acc[mt][nt], ah[mt], bh[p][q], bh[p][q + 2]);
                    mma16816(acc[mt][nt], ah[mt], bl[p][q], bl[p][q + 2]);
                    mma16816(acc[mt][nt], al[mt], bh[p][q], bh[p][q + 2]);
                }
            }
        }
        __syncthreads();
    }
#undef BS_LOAD

    if (EPI == 2) {
        // fused head epilogue: score_r = sum_n elu(a2[r][n]+b2[n])*W3[n] + b3
        const float* b2z = b2 + (size_t)blockIdx.z * HDIM;
        const float* w3z = W3 + (size_t)blockIdx.z * HDIM;
        const float b3d = b3[blockIdx.z];
        const bool joint = (blockIdx.y < 4);
#pragma unroll
        for (int mt = 0; mt < 4; mt++) {
            float s0 = 0.f, s1 = 0.f;
#pragma unroll
            for (int nt = 0; nt < 4; nt++) {
                int n0 = warpN * 32 + nt * 8 + (lane & 3) * 2;
                float w0 = __ldg(w3z + n0), w1 = __ldg(w3z + n0 + 1);
                float c0 = __ldg(b2z + n0), c1 = __ldg(b2z + n0 + 1);
                s0 += eluf(acc[mt][nt][0] + c0) * w0 + eluf(acc[mt][nt][1] + c1) * w1;
                s1 += eluf(acc[mt][nt][2] + c0) * w0 + eluf(acc[mt][nt][3] + c1) * w1;
            }
            s0 += __shfl_xor_sync(0xffffffffu, s0, 1);
            s0 += __shfl_xor_sync(0xffffffffu, s0, 2);
            s1 += __shfl_xor_sync(0xffffffffu, s1, 1);
            s1 += __shfl_xor_sync(0xffffffffu, s1, 2);
            if ((lane & 3) == 0) {
                int r0 = warpM * 64 + mt * 16 + (lane >> 2);
                red[r0][warpN] = s0;
                red[r0 + 8][warpN] = s1;
            }
        }
        __syncthreads();
        float val = 0.f;
        if (tid < 128) {
            float s = red[tid][0] + red[tid][1] + red[tid][2] + red[tid][3] + b3d;
            val = joint ? s : expf(s);
        }
#pragma unroll
        for (int off = 16; off; off >>= 1)
            val += __shfl_xor_sync(0xffffffffu, val, off);
        if (lane == 0) wr[wid] = val;
        __syncthreads();
        if (tid == 0) {
            float s = wr[0] + wr[1] + wr[2] + wr[3];
            int slot = blockIdx.z * 8 + blockIdx.y;
            if (joint) { g_js[slot] = s; g_es[slot] = 0.f; }
            else       { g_js[slot] = 0.f; g_es[slot] = s; }
        }
        return;
    }

#pragma unroll
    for (int mt = 0; mt < 4; mt++) {
        int m0 = mBase + warpM * 64 + mt * 16 + (lane >> 2);
#pragma unroll
        for (int nt = 0; nt < 4; nt++) {
            int n0 = nBase + warpN * 32 + nt * 8 + (lane & 3) * 2;
            if (EPI == 0) {
                float* Cz = C + (size_t)blockIdx.z * sCz;
                *(float2*)(Cz + (size_t)m0 * ldc + n0) =
                    make_float2(acc[mt][nt][0], acc[mt][nt][1]);
                *(float2*)(Cz + (size_t)(m0 + 8) * ldc + n0) =
                    make_float2(acc[mt][nt][2], acc[mt][nt][3]);
            } else if (EPI == 1) {
                float bv0 = bias[n0], bv1 = bias[n0 + 1];
                float u0 = eluf(acc[mt][nt][0] + bv0);
                float u1 = eluf(acc[mt][nt][1] + bv1);
                float u2 = eluf(acc[mt][nt][2] + bv0);
                float u3 = eluf(acc[mt][nt][3] + bv1);
                __nv_bfloat16 h0, h1, h2, h3, l0, l1, l2, l3;
                hilo(u0, h0, l0); hilo(u1, h1, l1);
                hilo(u2, h2, l2); hilo(u3, h3, l3);
                __nv_bfloat162 vh, vl;
                vh.x = h0; vh.y = h1; vl.x = l0; vl.y = l1;
                *(__nv_bfloat162*)(Chi + (size_t)m0 * ldc + n0) = vh;
                *(__nv_bfloat162*)(Clo + (size_t)m0 * ldc + n0) = vl;
                vh.x = h2; vh.y = h3; vl.x = l2; vl.y = l3;
                *(__nv_bfloat162*)(Chi + (size_t)(m0 + 8) * ldc + n0) = vh;
                *(__nv_bfloat162*)(Clo + (size_t)(m0 + 8) * ldc + n0) = vl;
            }
        }
    }
}

// ---------------- head stage 1: a1 = elu(hWh + z*Wz + b1) -------------------
__global__ void a1_kernel(const float* __restrict__ z, const int* __restrict__ perm,
                          const float* __restrict__ Wz, const float* __restrict__ b1)
{
    __shared__ float4 wzs[32], b1s[32];
    const int d = blockIdx.x;
    const int by = blockIdx.y;
    const int tid = threadIdx.x;

    if (tid < 32) {
        wzs[tid] = ((const float4*)(Wz + (size_t)d * HDIM))[tid];
        b1s[tid] = ((const float4*)(b1 + (size_t)d * HDIM))[tid];
    }
    __syncthreads();

    const float* hb = g_hWh + (size_t)d * BB * HDIM;
    __nv_bfloat16* a1h = g_a1hi + (size_t)d * 2 * BB * HDIM;
    __nv_bfloat16* a1l = g_a1lo + (size_t)d * 2 * BB * HDIM;

#pragma unroll
    for (int u = 0; u < 8; u++) {
        const int unit = tid + u * 256;
        const int bl_ = unit >> 5;
        const int h4 = unit & 31;
        const int b = by * 64 + bl_;
        const int pb = perm[b];
        const float zb = z[(size_t)b * DDIM + d];

        float4 wz = wzs[h4], bb = b1s[h4];
        float4 w;
        w.x = fmaf(zb, wz.x, bb.x); w.y = fmaf(zb, wz.y, bb.y);
        w.z = fmaf(zb, wz.z, bb.z); w.w = fmaf(zb, wz.w, bb.w);

        float4 hj = ((const float4*)(hb + (size_t)b * HDIM))[h4];
        float4 hm = ((const float4*)(hb + (size_t)pb * HDIM))[h4];

        float j0 = eluf(hj.x + w.x), j1 = eluf(hj.y + w.y);
        float j2 = eluf(hj.z + w.z), j3 = eluf(hj.w + w.w);
        float m0 = eluf(hm.x + w.x), m1 = eluf(hm.y + w.y);
        float m2 = eluf(hm.z + w.z), m3 = eluf(hm.w + w.w);

        __nv_bfloat16 h0, h1, h2, h3, l0, l1, l2, l3;
        hilo(j0, h0, l0); hilo(j1, h1, l1); hilo(j2, h2, l2); hilo(j3, h3, l3);
        __nv_bfloat162 p0, p1;
        p0.x = h0; p0.y = h1; p1.x = h2; p1.y = h3;
        ((__nv_bfloat162*)(a1h + (size_t)b * HDIM))[h4 * 2] = p0;
        ((__nv_bfloat162*)(a1h + (size_t)b * HDIM))[h4 * 2 + 1] = p1;
        p0.x = l0; p0.y = l1; p1.x = l2; p1.y = l3;
        ((__nv_bfloat162*)(a1l + (size_t)b * HDIM))[h4 * 2] = p0;
        ((__nv_bfloat162*)(a1l + (size_t)b * HDIM))[h4 * 2 + 1] = p1;

        hilo(m0, h0, l0); hilo(m1, h1, l1); hilo(m2, h2, l2); hilo(m3, h3, l3);
        p0.x = h0; p0.y = h1; p1.x = h2; p1.y = h3;
        ((__nv_bfloat162*)(a1h + (size_t)(BB + b) * HDIM))[h4 * 2] = p0;
        ((__nv_bfloat162*)(a1h + (size_t)(BB + b) * HDIM))[h4 * 2 + 1] = p1;
        p0.x = l0; p0.y = l1; p1.x = l2; p1.y = l3;
        ((__nv_bfloat162*)(a1l + (size_t)(BB + b) * HDIM))[h4 * 2] = p0;
        ((__nv_bfloat162*)(a1l + (size_t)(BB + b) * HDIM))[h4 * 2 + 1] = p1;
    }
}

__global__ void finalize_kernel(float* __restrict__ out)
{
    int t = threadIdx.x;
    float acc = 0.f;
    for (int d = t; d < DDIM; d += 32) {
        float js = 0.f, es = 0.f;
#pragma unroll
        for (int c = 0; c < 8; c++) { js += g_js[d * 8 + c]; es += g_es[d * 8 + c]; }
        acc += js * (1.f / BB) - logf(es * (1.f / BB));
    }
#pragma unroll
    for (int off = 16; off; off >>= 1)
        acc += __shfl_xor_sync(0xffffffffu, acc, off);
    if (t == 0) out[0] = -acc * (1.f / DDIM);
}

// ---------------------------------------------------------------------------
extern "C" void kernel_launch(void* const* d_in, const int* in_sizes, int n_in,
                              void* d_out, int out_size)
{
    const float* x   = (const float*)d_in[0];
    const float* z   = (const float*)d_in[1];
    const int*   perm= (const int*)  d_in[2];
    const float* Wg1 = (const float*)d_in[3];
    const float* bg1 = (const float*)d_in[4];
    const float* Wg2 = (const float*)d_in[5];
    const float* bg2 = (const float*)d_in[6];
    const float* Wh  = (const float*)d_in[7];
    const float* Wz  = (const float*)d_in[8];
    const float* b1  = (const float*)d_in[9];
    const float* W2  = (const float*)d_in[10];
    const float* b2  = (const float*)d_in[11];
    const float* W3  = (const float*)d_in[12];
    const float* b3  = (const float*)d_in[13];

    __nv_bfloat16 *h1hi, *h1lo, *wg2thi, *wg2tlo, *hhi, *hlo, *whthi, *whtlo;
    __nv_bfloat16 *w2thi, *w2tlo, *a1hi, *a1lo;
    float* hwh;
    cudaGetSymbolAddress((void**)&h1hi,   g_h1hi);
    cudaGetSymbolAddress((void**)&h1lo,   g_h1lo);
    cudaGetSymbolAddress((void**)&wg2thi, g_wg2thi);
    cudaGetSymbolAddress((void**)&wg2tlo, g_wg2tlo);
    cudaGetSymbolAddress((void**)&hhi,    g_hhi);
    cudaGetSymbolAddress((void**)&hlo,    g_hlo);
    cudaGetSymbolAddress((void**)&whthi,  g_whthi);
    cudaGetSymbolAddress((void**)&whtlo,  g_whtlo);
    cudaGetSymbolAddress((void**)&w2thi,  g_w2thi);
    cudaGetSymbolAddress((void**)&w2tlo,  g_w2tlo);
    cudaGetSymbolAddress((void**)&a1hi,   g_a1hi);
    cudaGetSymbolAddress((void**)&a1lo,   g_a1lo);
    cudaGetSymbolAddress((void**)&hwh,    g_hWh);

    // conversions
    conv_x_kernel<<<(BB * XDIM) / 4 / 256, 256>>>((const float4*)x);
    conv_wt_kernel<<<dim3(XDIM / 64, G1D / 32), 256>>>(Wg1);
    transconv_kernel<<<dim3(PDIM / 32, G1D / 32, 1), 256>>>(Wg2, wg2thi, wg2tlo,
                                                            G1D, PDIM);
    transconv_kernel<<<dim3(HDIM / 32, PDIM / 32, DDIM), 256>>>(Wh, whthi, whtlo,
                                                                PDIM, HDIM);
    transconv_kernel<<<dim3(HDIM / 32, HDIM / 32, DDIM), 256>>>(W2, w2thi, w2tlo,
                                                                HDIM, HDIM);

    // K1
    cudaFuncSetAttribute(gemm_k1_kernel,
                         cudaFuncAttributeMaxDynamicSharedMemorySize, K1_SMEM);
    gemm_k1_kernel<<<dim3(G1D / K1_BN, BB / BM, K1_KS), 256, K1_SMEM>>>();
    reduce_h1_kernel<<<(BB * G1D) / 256, 256>>>(bg1);

    cudaFuncSetAttribute(gemm_bs<0>,
                         cudaFuncAttributeMaxDynamicSharedMemorySize, GEMM_SMEM);
    cudaFuncSetAttribute(gemm_bs<1>,
                         cudaFuncAttributeMaxDynamicSharedMemorySize, GEMM_SMEM);
    cudaFuncSetAttribute(gemm_bs<2>,
                         cudaFuncAttributeMaxDynamicSharedMemorySize, GEMM_SMEM);

    // K2: h = elu(h1 @ Wg2 + bg2) -> bf16 hi/lo
    gemm_bs<1><<<dim3(PDIM / 128, BB / BM, 1), 256, GEMM_SMEM>>>(
        h1hi, h1lo, G1D, 0, wg2thi, wg2tlo, G1D, 0,
        nullptr, hhi, hlo, bg2, PDIM, 0, G1D, nullptr, nullptr, nullptr);

    // K3: hWh[d] = h @ WhT[d]  (fp32)
    gemm_bs<0><<<dim3(1, BB / BM, DDIM), 256, GEMM_SMEM>>>(
        hhi, hlo, PDIM, 0, whthi, whtlo, PDIM, (long)HDIM * PDIM,
        hwh, nullptr, nullptr, nullptr, HDIM, (long)BB * HDIM, PDIM,
        nullptr, nullptr, nullptr);

    // head stage 1: a1 (joint + marg) bf16 hi/lo
    a1_kernel<<<dim3(DDIM, BB / 64), 256>>>(z, perm, Wz, b1);

    // head stage 2+3 fused: a2 GEMM + scores + reductions
    gemm_bs<2><<<dim3(1, (2 * BB) / BM, DDIM), 256, GEMM_SMEM>>>(
        a1hi, a1lo, HDIM, (long)2 * BB * HDIM,
        w2thi, w2tlo, HDIM, (long)HDIM * HDIM,
        nullptr, nullptr, nullptr, nullptr, HDIM, 0, HDIM, b2, W3, b3);

    finalize_kernel<<<1, 32>>>((float*)d_out);
}

// round 7
// speedup vs baseline: 4.0568x; 1.0309x over previous
#include <cuda_runtime.h>
#include <cuda_bf16.h>
#include <math.h>
#include <stdint.h>

// Problem dims
#define BB   512
#define XDIM 32768
#define PDIM 512
#define DDIM 64
#define HDIM 128
#define G1D  1024

// Shared HMMA config
#define BM 128
#define BK 32
#define PITCH 40
#define ROWB (PITCH * 2)        // 80

// gemm_bs (BN=128)
#define MAT_BYTES (128 * ROWB)        // 10240
#define STG_BYTES (4 * MAT_BYTES)     // 40960
#define GEMM_SMEM (2 * STG_BYTES)     // 81920

// K1 (BN=256, KS=8, 3-stage)
#define K1_BN 256
#define K1_KS 8
#define K1_KCHUNK (XDIM / K1_KS)
#define K1_NIT (K1_KCHUNK / BK)
#define MAT_A 10240
#define MAT_B (256 * ROWB)
#define K1_STG (2 * MAT_A + 2 * MAT_B)
#define K1_SMEM (3 * K1_STG)
#define K1_AH 0
#define K1_AL MAT_A
#define K1_BH (2 * MAT_A)
#define K1_BL (2 * MAT_A + MAT_B)

// ---------------- device scratch ----------------
__device__ __nv_bfloat16 g_xhi[BB * XDIM];
__device__ __nv_bfloat16 g_xlo[BB * XDIM];
__device__ __nv_bfloat16 g_wthi[G1D * XDIM];
__device__ __nv_bfloat16 g_wtlo[G1D * XDIM];
__device__ float g_part[K1_KS * BB * G1D];
__device__ __nv_bfloat16 g_h1hi[BB * G1D];
__device__ __nv_bfloat16 g_h1lo[BB * G1D];
__device__ __nv_bfloat16 g_wg2thi[PDIM * G1D];
__device__ __nv_bfloat16 g_wg2tlo[PDIM * G1D];
__device__ __nv_bfloat16 g_hhi[BB * PDIM];
__device__ __nv_bfloat16 g_hlo[BB * PDIM];
__device__ __nv_bfloat16 g_whthi[DDIM * HDIM * PDIM];
__device__ __nv_bfloat16 g_whtlo[DDIM * HDIM * PDIM];
__device__ float g_hWh[DDIM * BB * HDIM];
__device__ __nv_bfloat16 g_w2thi[DDIM * HDIM * HDIM];
__device__ __nv_bfloat16 g_w2tlo[DDIM * HDIM * HDIM];
__device__ float g_js[DDIM * 8];
__device__ float g_es[DDIM * 8];

__device__ __forceinline__ float eluf(float x) {
    return x > 0.f ? x : expm1f(x);
}
__device__ __forceinline__ uint32_t smem_u32(const void* p) {
    uint32_t a;
    asm("{ .reg .u64 t; cvta.to.shared.u64 t, %1; cvt.u32.u64 %0, t; }"
        : "=r"(a) : "l"(p));
    return a;
}
#define CP16(dst, src) \
    asm volatile("cp.async.cg.shared.global [%0], [%1], 16;" \
                 :: "r"(dst), "l"(src) : "memory")
#define CP_COMMIT() asm volatile("cp.async.commit_group;" ::: "memory")
#define CP_WAIT1()  asm volatile("cp.async.wait_group 1;" ::: "memory")
#define CP_WAIT0()  asm volatile("cp.async.wait_group 0;" ::: "memory")

__device__ __forceinline__ void ldmx4(uint32_t* r, uint32_t addr) {
    asm volatile("ldmatrix.sync.aligned.m8n8.x4.shared.b16 {%0,%1,%2,%3}, [%4];"
                 : "=r"(r[0]), "=r"(r[1]), "=r"(r[2]), "=r"(r[3]) : "r"(addr));
}
__device__ __forceinline__ void mma16816(float* c, const uint32_t* a,
                                         uint32_t b0, uint32_t b1) {
    asm volatile(
        "mma.sync.aligned.m16n8k16.row.col.f32.bf16.bf16.f32 "
        "{%0,%1,%2,%3}, {%4,%5,%6,%7}, {%8,%9}, {%0,%1,%2,%3};"
        : "+f"(c[0]), "+f"(c[1]), "+f"(c[2]), "+f"(c[3])
        : "r"(a[0]), "r"(a[1]), "r"(a[2]), "r"(a[3]), "r"(b0), "r"(b1));
}
__device__ __forceinline__ void hilo(float v, __nv_bfloat16& h, __nv_bfloat16& l) {
    h = __float2bfloat16(v);
    l = __float2bfloat16(v - __bfloat162float(h));
}

// ---------------- conversions ----------------
__global__ void conv_x_kernel(const float4* __restrict__ x) {
    int i = blockIdx.x * 256 + threadIdx.x;
    float4 v = x[i];
    __nv_bfloat16 h0, h1, h2, h3, l0, l1, l2, l3;
    hilo(v.x, h0, l0); hilo(v.y, h1, l1);
    hilo(v.z, h2, l2); hilo(v.w, h3, l3);
    __nv_bfloat162* ph = (__nv_bfloat162*)g_xhi;
    __nv_bfloat162* pl = (__nv_bfloat162*)g_xlo;
    __nv_bfloat162 a; a.x = h0; a.y = h1;
    __nv_bfloat162 b; b.x = h2; b.y = h3;
    ph[2 * i] = a; ph[2 * i + 1] = b;
    a.x = l0; a.y = l1; b.x = l2; b.y = l3;
    pl[2 * i] = a; pl[2 * i + 1] = b;
}

__global__ void conv_wt_kernel(const float* __restrict__ W) {
    __shared__ float s[64][33];
    const int kt = blockIdx.x * 64;
    const int nt = blockIdx.y * 32;
    const int tx = threadIdx.x & 31, ty = threadIdx.x >> 5;
    for (int r = ty; r < 64; r += 8)
        s[r][tx] = W[(size_t)(kt + r) * G1D + nt + tx];
    __syncthreads();
    for (int n = ty; n < 32; n += 8) {
        float a = s[tx * 2][n], b = s[tx * 2 + 1][n];
        __nv_bfloat16 ah, al, bh, bl;
        hilo(a, ah, al); hilo(b, bh, bl);
        __nv_bfloat162 vh; vh.x = ah; vh.y = bh;
        __nv_bfloat162 vl; vl.x = al; vl.y = bl;
        ((__nv_bfloat162*)(g_wthi + (size_t)(nt + n) * XDIM + kt))[tx] = vh;
        ((__nv_bfloat162*)(g_wtlo + (size_t)(nt + n) * XDIM + kt))[tx] = vl;
    }
}

__global__ void transconv_kernel(const float* __restrict__ src,
                                 __nv_bfloat16* __restrict__ dhi,
                                 __nv_bfloat16* __restrict__ dlo,
                                 int R, int C) {
    __shared__ float s[32][33];
    const size_t zoff = (size_t)blockIdx.z * R * C;
    const int rt = blockIdx.y * 32, ct = blockIdx.x * 32;
    const int tx = threadIdx.x & 31, ty = threadIdx.x >> 5;
    for (int r = ty; r < 32; r += 8)
        s[r][tx] = src[zoff + (size_t)(rt + r) * C + ct + tx];
    __syncthreads();
    for (int c = ty; c < 32; c += 8) {
        float v = s[tx][c];
        __nv_bfloat16 h, l;
        hilo(v, h, l);
        dhi[zoff + (size_t)(ct + c) * R + rt + tx] = h;
        dlo[zoff + (size_t)(ct + c) * R + rt + tx] = l;
    }
}

// ---------------- K1: bf16-split HMMA, BM=128 BN=256, 3-stage ----------------
__device__ __forceinline__ void k1_load_stage(uint32_t sb, int stage,
                                              int mBase, int nBase, int k0,
                                              int tid) {
    uint32_t st = sb + (uint32_t)stage * K1_STG;
#pragma unroll
    for (int t = 0; t < 2; t++) {
        int ci = tid + t * 256;
        int r = ci >> 2, ch = ci & 3;
        uint32_t so = (uint32_t)(r * ROWB + ch * 16);
        size_t go = (size_t)(mBase + r) * XDIM + k0 + ch * 8;
        CP16(st + K1_AH + so, g_xhi + go);
        CP16(st + K1_AL + so, g_xlo + go);
    }
#pragma unroll
    for (int t = 0; t < 4; t++) {
        int ci = tid + t * 256;
        int r = ci >> 2, ch = ci & 3;
        uint32_t so = (uint32_t)(r * ROWB + ch * 16);
        size_t go = (size_t)(nBase + r) * XDIM + k0 + ch * 8;
        CP16(st + K1_BH + so, g_wthi + go);
        CP16(st + K1_BL + so, g_wtlo + go);
    }
}

__global__ void __launch_bounds__(256, 1) gemm_k1_kernel() {
    extern __shared__ char sm[];
    const uint32_t sb = smem_u32(sm);
    const int tid = threadIdx.x;
    const int lane = tid & 31;
    const int wid = tid >> 5;
    const int warpM = wid >> 2;
    const int warpN = wid & 3;

    const int nBase = blockIdx.x * K1_BN;
    const int mBase = blockIdx.y * BM;
    const int kBase = blockIdx.z * K1_KCHUNK;

    const uint32_t laneOff =
        (uint32_t)(((lane & 7) + ((lane >> 3) & 1) * 8) * ROWB + (lane >> 4) * 16);

    float acc[4][8][4];
#pragma unroll
    for (int i = 0; i < 4; i++)
#pragma unroll
        for (int j = 0; j < 8; j++)
#pragma unroll
            for (int k = 0; k < 4; k++) acc[i][j][k] = 0.f;

    k1_load_stage(sb, 0, mBase, nBase, kBase, tid);
    CP_COMMIT();
    k1_load_stage(sb, 1, mBase, nBase, kBase + BK, tid);
    CP_COMMIT();

#pragma unroll 1
    for (int it = 0; it < K1_NIT; it++) {
        if (it + 1 < K1_NIT) CP_WAIT1(); else CP_WAIT0();
        __syncthreads();
        if (it + 2 < K1_NIT) {
            k1_load_stage(sb, (it + 2) % 3, mBase, nBase,
                          kBase + (it + 2) * BK, tid);
            CP_COMMIT();
        }

        uint32_t st = sb + (uint32_t)(it % 3) * K1_STG;
        uint32_t aH = st + K1_AH + (uint32_t)(warpM * 64) * ROWB + laneOff;
        uint32_t aL = st + K1_AL + (uint32_t)(warpM * 64) * ROWB + laneOff;
        uint32_t bH = st + K1_BH + (uint32_t)(warpN * 64) * ROWB + laneOff;
        uint32_t bL = st + K1_BL + (uint32_t)(warpN * 64) * ROWB + laneOff;

#pragma unroll
        for (int ks = 0; ks < 2; ks++) {
            const uint32_t kb = ks * 32;
            uint32_t ah[4][4], al[4][4], bh[4][4], bl[4][4];
#pragma unroll
            for (int mt = 0; mt < 4; mt++) {
                ldmx4(ah[mt], aH + (uint32_t)(mt * 16) * ROWB + kb);
                ldmx4(al[mt], aL + (uint32_t)(mt * 16) * ROWB + kb);
            }
#pragma unroll
            for (int p = 0; p < 4; p++) {
                ldmx4(bh[p], bH + (uint32_t)(p * 16) * ROWB + kb);
                ldmx4(bl[p], bL + (uint32_t)(p * 16) * ROWB + kb);
            }
#pragma unroll
            for (int mt = 0; mt < 4; mt++) {
#pragma unroll
                for (int nt = 0; nt < 8; nt++) {
                    const int p = nt >> 1, q = nt & 1;
                    mma16816(acc[mt][nt], ah[mt], bh[p][q], bh[p][q + 2]);
                    mma16816(acc[mt][nt], ah[mt], bl[p][q], bl[p][q + 2]);
                    mma16816(acc[mt][nt], al[mt], bh[p][q], bh[p][q + 2]);
                }
            }
        }
        __syncthreads();
    }

    float* base = g_part + (size_t)blockIdx.z * (BB * G1D);
#pragma unroll
    for (int mt = 0; mt < 4; mt++) {
        int m0 = mBase + warpM * 64 + mt * 16 + (lane >> 2);
#pragma unroll
        for (int nt = 0; nt < 8; nt++) {
            int n0 = nBase + warpN * 64 + nt * 8 + (lane & 3) * 2;
            *(float2*)(base + (size_t)m0 * G1D + n0) =
                make_float2(acc[mt][nt][0], acc[mt][nt][1]);
            *(float2*)(base + (size_t)(m0 + 8) * G1D + n0) =
                make_float2(acc[mt][nt][2], acc[mt][nt][3]);
        }
    }
}

// partials -> h1 = elu(sum + bias), bf16 hi/lo
__global__ void reduce_h1_kernel(const float* __restrict__ bg1) {
    const int i = blockIdx.x * 256 + threadIdx.x;
    float s = 0.f;
#pragma unroll
    for (int k = 0; k < K1_KS; k++) s += g_part[k * (BB * G1D) + i];
    float v = eluf(s + bg1[i & (G1D - 1)]);
    __nv_bfloat16 h, l;
    hilo(v, h, l);
    g_h1hi[i] = h;
    g_h1lo[i] = l;
}

// ---------------- unified bf16-split HMMA GEMM (BN=128) ----------------
// EPI=0: fp32 C. EPI=1: elu(acc+bias)->bf16 hi/lo.
// EPI=2: fused head — A computed on the fly from hWh/z/perm/Wz/b1 (a1 fusion),
//        epilogue does scores + joint/exp reductions. grid (1, 8, DDIM).
template <int EPI>
__global__ void __launch_bounds__(256, 2) gemm_bs(
    const __nv_bfloat16* __restrict__ Ahi, const __nv_bfloat16* __restrict__ Alo,
    int lda, long sAz,
    const __nv_bfloat16* __restrict__ Bhi, const __nv_bfloat16* __restrict__ Blo,
    int ldb, long sBz,
    float* __restrict__ C, __nv_bfloat16* __restrict__ Chi,
    __nv_bfloat16* __restrict__ Clo,
    const float* __restrict__ bias, int ldc, long sCz, int K,
    const float* __restrict__ b2, const float* __restrict__ W3,
    const float* __restrict__ b3,
    const float* __restrict__ hwhp, const float* __restrict__ zv,
    const int* __restrict__ permp, const float* __restrict__ Wzp,
    const float* __restrict__ b1p)
{
    extern __shared__ char sm[];
    __shared__ float red[128][5];
    __shared__ float wr[8];
    __shared__ float s_wz[HDIM], s_b1[HDIM];
    const uint32_t sb = smem_u32(sm);
    const int tid = threadIdx.x;
    const int lane = tid & 31;
    const int wid = tid >> 5;
    const int warpM = wid >> 2;
    const int warpN = wid & 3;

    const int nBase = blockIdx.x * 128;
    const int mBase = blockIdx.y * BM;
    const __nv_bfloat16* ahiz = Ahi + (size_t)blockIdx.z * sAz;
    const __nv_bfloat16* aloz = Alo + (size_t)blockIdx.z * sAz;
    const __nv_bfloat16* bhi = Bhi + (size_t)blockIdx.z * sBz;
    const __nv_bfloat16* blo = Blo + (size_t)blockIdx.z * sBz;

    if (EPI == 2) {
        if (tid < HDIM) {
            s_wz[tid] = Wzp[(size_t)blockIdx.z * HDIM + tid];
            s_b1[tid] = b1p[(size_t)blockIdx.z * HDIM + tid];
        }
        __syncthreads();
    }

    const uint32_t laneOff =
        (uint32_t)(((lane & 7) + ((lane >> 3) & 1) * 8) * ROWB + (lane >> 4) * 16);
    const int NIT = K / BK;

    float acc[4][4][4];
#pragma unroll
    for (int i = 0; i < 4; i++)
#pragma unroll
        for (int j = 0; j < 4; j++)
#pragma unroll
            for (int k = 0; k < 4; k++) acc[i][j][k] = 0.f;

    // A-loader for EPI2: compute a1 = elu(hWh[src] + z_b*Wz + b1), hi/lo split.
#define A_COMPUTE(stage, k0)                                                   \
    do {                                                                       \
        uint32_t stoff = (uint32_t)(stage) * STG_BYTES;                        \
        const float* hwh_d = hwhp + (size_t)blockIdx.z * BB * HDIM;            \
        _Pragma("unroll")                                                      \
        for (int t = 0; t < 2; t++) {                                          \
            int u = tid + t * 256;                                             \
            int r = u >> 2, ch = u & 3;                                        \
            int gm = mBase + r;                                                \
            int b = (gm < BB) ? gm : gm - BB;                                  \
            int src = (gm < BB) ? b : __ldg(permp + b);                        \
            float zb = __ldg(zv + (size_t)b * DDIM + blockIdx.z);              \
            const float* hr = hwh_d + (size_t)src * HDIM + (k0) + ch * 8;      \
            float4 v0 = __ldg((const float4*)hr);                              \
            float4 v1 = __ldg((const float4*)(hr + 4));                        \
            float hv[8] = {v0.x, v0.y, v0.z, v0.w, v1.x, v1.y, v1.z, v1.w};    \
            uint32_t hp[4], lp[4];                                             \
            _Pragma("unroll")                                                  \
            for (int j = 0; j < 4; j++) {                                      \
                int kk = (k0) + ch * 8 + 2 * j;                                \
                float a0 = eluf(hv[2*j]   + fmaf(zb, s_wz[kk],   s_b1[kk]));   \
                float a1v = eluf(hv[2*j+1] + fmaf(zb, s_wz[kk+1], s_b1[kk+1]));\
                __nv_bfloat16 hh0, ll0, hh1, ll1;                              \
                hilo(a0, hh0, ll0); hilo(a1v, hh1, ll1);                       \
                __nv_bfloat162 ph; ph.x = hh0; ph.y = hh1;                     \
                __nv_bfloat162 pl; pl.x = ll0; pl.y = ll1;                     \
                hp[j] = *(uint32_t*)&ph; lp[j] = *(uint32_t*)&pl;              \
            }                                                                  \
            uint32_t so = (uint32_t)(r * ROWB + ch * 16);                      \
            *(uint4*)(sm + stoff + 0 * MAT_BYTES + so) =                       \
                make_uint4(hp[0], hp[1], hp[2], hp[3]);                        \
            *(uint4*)(sm + stoff + 1 * MAT_BYTES + so) =                       \
                make_uint4(lp[0], lp[1], lp[2], lp[3]);                        \
        }                                                                      \
    } while (0)

#define BS_LOAD(stage, k0)                                                     \
    do {                                                                       \
        uint32_t st = sb + (uint32_t)(stage)*STG_BYTES;                        \
        if (EPI == 2) {                                                        \
            A_COMPUTE(stage, k0);                                              \
        } else {                                                               \
            _Pragma("unroll")                                                  \
            for (int t = 0; t < 2; t++) {                                      \
                int ci = tid + t * 256;                                        \
                int r = ci >> 2, ch = ci & 3;                                  \
                uint32_t so = (uint32_t)(r * ROWB + ch * 16);                  \
                size_t goA = (size_t)(mBase + r) * lda + (k0) + ch * 8;        \
                CP16(st + 0 * MAT_BYTES + so, ahiz + goA);                     \
                CP16(st + 1 * MAT_BYTES + so, aloz + goA);                     \
            }                                                                  \
        }                                                                      \
        _Pragma("unroll")                                                      \
        for (int t = 0; t < 2; t++) {                                          \
            int ci = tid + t * 256;                                            \
            int r = ci >> 2, ch = ci & 3;                                      \
            uint32_t so = (uint32_t)(r * ROWB + ch * 16);                      \
            size_t goB = (size_t)(nBase + r) * ldb + (k0) + ch * 8;            \
            CP16(st + 2 * MAT_BYTES + so, bhi + goB);                          \
            CP16(st + 3 * MAT_BYTES + so, blo + goB);                          \
        }                                                                      \
    } while (0)

    BS_LOAD(0, 0);
    CP_COMMIT();

#pragma unroll 1
    for (int it = 0; it < NIT; it++) {
        if (it + 1 < NIT) {
            BS_LOAD((it + 1) & 1, (it + 1) * BK);
            CP_COMMIT();
            CP_WAIT1();
        } else {
            CP_WAIT0();
        }
        __syncthreads();

        uint32_t st = sb + (uint32_t)(it & 1) * STG_BYTES;
        uint32_t aH = st + 0 * MAT_BYTES + (uint32_t)(warpM * 64) * ROWB + laneOff;
        uint32_t aL = st + 1 * MAT_BYTES + (uint32_t)(warpM * 64) * ROWB + laneOff;
        uint32_t bH = st + 2 * MAT_BYTES + (uint32_t)(warpN * 32) * ROWB + laneOff;
        uint32_t bL = st + 3 * MAT_BYTES + (uint32_t)(warpN * 32) * ROWB + laneOff;

#pragma unroll
        for (int ks = 0; ks < 2; ks++) {
            const uint32_t kb = ks * 32;
            uint32_t ah[4][4], al[4][4], bh[2][4], bl[2][4];
#pragma unroll
            for (int mt = 0; mt < 4; mt++) {
                ldmx4(ah[mt], aH + (uint32_t)(mt * 16) * ROWB + kb);
                ldmx4(al[mt], aL + (uint32_t)(mt * 16) * ROWB + kb);
            }
#pragma unroll
            for (int p = 0; p < 2; p++) {
                ldmx4(bh[p], bH + (uint32_t)(p * 16) * ROWB + kb);
                ldmx4(bl[p], bL + (uint32_t)(p * 16) * ROWB + kb);
            }
#pragma unroll
            for (int mt = 0; mt < 4; mt++) {
#pragma unroll
                for (int nt = 0; nt < 4; nt++) {
                    const int p = nt >> 1, q = nt & 1;
                    mma16816(acc[mt][nt], ah[mt], bh[p][q], bh[p][q + 2]);
                    mma16816(acc[mt][nt], ah[mt], bl[p][q], bl[p][q + 2]);
                    mma16816(acc[mt][nt], al[mt], bh[p][q], bh[p][q + 2]);
                }
            }
        }
        __syncthreads();
    }
#undef BS_LOAD
#undef A_COMPUTE

    if (EPI == 2) {
        const float* b2z = b2 + (size_t)blockIdx.z * HDIM;
        const float* w3z = W3 + (size_t)blockIdx.z * HDIM;
        const float b3d = b3[blockIdx.z];
        const bool joint = (blockIdx.y < 4);
#pragma unroll
        for (int mt = 0; mt < 4; mt++) {
            float s0 = 0.f, s1 = 0.f;
#pragma unroll
            for (int nt = 0; nt < 4; nt++) {
                int n0 = warpN * 32 + nt * 8 + (lane & 3) * 2;
                float w0 = __ldg(w3z + n0), w1 = __ldg(w3z + n0 + 1);
                float c0 = __ldg(b2z + n0), c1 = __ldg(b2z + n0 + 1);
                s0 += eluf(acc[mt][nt][0] + c0) * w0 + eluf(acc[mt][nt][1] + c1) * w1;
                s1 += eluf(acc[mt][nt][2] + c0) * w0 + eluf(acc[mt][nt][3] + c1) * w1;
            }
            s0 += __shfl_xor_sync(0xffffffffu, s0, 1);
            s0 += __shfl_xor_sync(0xffffffffu, s0, 2);
            s1 += __shfl_xor_sync(0xffffffffu, s1, 1);
            s1 += __shfl_xor_sync(0xffffffffu, s1, 2);
            if ((lane & 3) == 0) {
                int r0 = warpM * 64 + mt * 16 + (lane >> 2);
                red[r0][warpN] = s0;
                red[r0 + 8][warpN] = s1;
            }
        }
        __syncthreads();
        float val = 0.f;
        if (tid < 128) {
            float s = red[tid][0] + red[tid][1] + red[tid][2] + red[tid][3] + b3d;
            val = joint ? s : expf(s);
        }
#pragma unroll
        for (int off = 16; off; off >>= 1)
            val += __shfl_xor_sync(0xffffffffu, val, off);
        if (lane == 0) wr[wid] = val;
        __syncthreads();
        if (tid == 0) {
            float s = wr[0] + wr[1] + wr[2] + wr[3];
            int slot = blockIdx.z * 8 + blockIdx.y;
            if (joint) { g_js[slot] = s; g_es[slot] = 0.f; }
            else       { g_js[slot] = 0.f; g_es[slot] = s; }
        }
        return;
    }

#pragma unroll
    for (int mt = 0; mt < 4; mt++) {
        int m0 = mBase + warpM * 64 + mt * 16 + (lane >> 2);
#pragma unroll
        for (int nt = 0; nt < 4; nt++) {
            int n0 = nBase + warpN * 32 + nt * 8 + (lane & 3) * 2;
            if (EPI == 0) {
                float* Cz = C + (size_t)blockIdx.z * sCz;
                *(float2*)(Cz + (size_t)m0 * ldc + n0) =
                    make_float2(acc[mt][nt][0], acc[mt][nt][1]);
                *(float2*)(Cz + (size_t)(m0 + 8) * ldc + n0) =
                    make_float2(acc[mt][nt][2], acc[mt][nt][3]);
            } else if (EPI == 1) {
                float bv0 = bias[n0], bv1 = bias[n0 + 1];
                float u0 = eluf(acc[mt][nt][0] + bv0);
                float u1 = eluf(acc[mt][nt][1] + bv1);
                float u2 = eluf(acc[mt][nt][2] + bv0);
                float u3 = eluf(acc[mt][nt][3] + bv1);
                __nv_bfloat16 h0, h1, h2, h3, l0, l1, l2, l3;
                hilo(u0, h0, l0); hilo(u1, h1, l1);
                hilo(u2, h2, l2); hilo(u3, h3, l3);
                __nv_bfloat162 vh, vl;
                vh.x = h0; vh.y = h1; vl.x = l0; vl.y = l1;
                *(__nv_bfloat162*)(Chi + (size_t)m0 * ldc + n0) = vh;
                *(__nv_bfloat162*)(Clo + (size_t)m0 * ldc + n0) = vl;
                vh.x = h2; vh.y = h3; vl.x = l2; vl.y = l3;
                *(__nv_bfloat162*)(Chi + (size_t)(m0 + 8) * ldc + n0) = vh;
                *(__nv_bfloat162*)(Clo + (size_t)(m0 + 8) * ldc + n0) = vl;
            }
        }
    }
}

__global__ void finalize_kernel(float* __restrict__ out)
{
    int t = threadIdx.x;
    float acc = 0.f;
    for (int d = t; d < DDIM; d += 32) {
        float js = 0.f, es = 0.f;
#pragma unroll
        for (int c = 0; c < 8; c++) { js += g_js[d * 8 + c]; es += g_es[d * 8 + c]; }
        acc += js * (1.f / BB) - logf(es * (1.f / BB));
    }
#pragma unroll
    for (int off = 16; off; off >>= 1)
        acc += __shfl_xor_sync(0xffffffffu, acc, off);
    if (t == 0) out[0] = -acc * (1.f / DDIM);
}

// ---------------------------------------------------------------------------
extern "C" void kernel_launch(void* const* d_in, const int* in_sizes, int n_in,
                              void* d_out, int out_size)
{
    const float* x   = (const float*)d_in[0];
    const float* z   = (const float*)d_in[1];
    const int*   perm= (const int*)  d_in[2];
    const float* Wg1 = (const float*)d_in[3];
    const float* bg1 = (const float*)d_in[4];
    const float* Wg2 = (const float*)d_in[5];
    const float* bg2 = (const float*)d_in[6];
    const float* Wh  = (const float*)d_in[7];
    const float* Wz  = (const float*)d_in[8];
    const float* b1  = (const float*)d_in[9];
    const float* W2  = (const float*)d_in[10];
    const float* b2  = (const float*)d_in[11];
    const float* W3  = (const float*)d_in[12];
    const float* b3  = (const float*)d_in[13];

    __nv_bfloat16 *h1hi, *h1lo, *wg2thi, *wg2tlo, *hhi, *hlo, *whthi, *whtlo;
    __nv_bfloat16 *w2thi, *w2tlo;
    float* hwh;
    cudaGetSymbolAddress((void**)&h1hi,   g_h1hi);
    cudaGetSymbolAddress((void**)&h1lo,   g_h1lo);
    cudaGetSymbolAddress((void**)&wg2thi, g_wg2thi);
    cudaGetSymbolAddress((void**)&wg2tlo, g_wg2tlo);
    cudaGetSymbolAddress((void**)&hhi,    g_hhi);
    cudaGetSymbolAddress((void**)&hlo,    g_hlo);
    cudaGetSymbolAddress((void**)&whthi,  g_whthi);
    cudaGetSymbolAddress((void**)&whtlo,  g_whtlo);
    cudaGetSymbolAddress((void**)&w2thi,  g_w2thi);
    cudaGetSymbolAddress((void**)&w2tlo,  g_w2tlo);
    cudaGetSymbolAddress((void**)&hwh,    g_hWh);

    // conversions
    conv_x_kernel<<<(BB * XDIM) / 4 / 256, 256>>>((const float4*)x);
    conv_wt_kernel<<<dim3(XDIM / 64, G1D / 32), 256>>>(Wg1);
    transconv_kernel<<<dim3(PDIM / 32, G1D / 32, 1), 256>>>(Wg2, wg2thi, wg2tlo,
                                                            G1D, PDIM);
    transconv_kernel<<<dim3(HDIM / 32, PDIM / 32, DDIM), 256>>>(Wh, whthi, whtlo,
                                                                PDIM, HDIM);
    transconv_kernel<<<dim3(HDIM / 32, HDIM / 32, DDIM), 256>>>(W2, w2thi, w2tlo,
                                                                HDIM, HDIM);

    // K1
    cudaFuncSetAttribute(gemm_k1_kernel,
                         cudaFuncAttributeMaxDynamicSharedMemorySize, K1_SMEM);
    gemm_k1_kernel<<<dim3(G1D / K1_BN, BB / BM, K1_KS), 256, K1_SMEM>>>();
    reduce_h1_kernel<<<(BB * G1D) / 256, 256>>>(bg1);

    cudaFuncSetAttribute(gemm_bs<0>,
                         cudaFuncAttributeMaxDynamicSharedMemorySize, GEMM_SMEM);
    cudaFuncSetAttribute(gemm_bs<1>,
                         cudaFuncAttributeMaxDynamicSharedMemorySize, GEMM_SMEM);
    cudaFuncSetAttribute(gemm_bs<2>,
                         cudaFuncAttributeMaxDynamicSharedMemorySize, GEMM_SMEM);

    // K2: h = elu(h1 @ Wg2 + bg2) -> bf16 hi/lo
    gemm_bs<1><<<dim3(PDIM / 128, BB / BM, 1), 256, GEMM_SMEM>>>(
        h1hi, h1lo, G1D, 0, wg2thi, wg2tlo, G1D, 0,
        nullptr, hhi, hlo, bg2, PDIM, 0, G1D,
        nullptr, nullptr, nullptr, nullptr, nullptr, nullptr, nullptr, nullptr);

    // K3: hWh[d] = h @ WhT[d]  (fp32)
    gemm_bs<0><<<dim3(1, BB / BM, DDIM), 256, GEMM_SMEM>>>(
        hhi, hlo, PDIM, 0, whthi, whtlo, PDIM, (long)HDIM * PDIM,
        hwh, nullptr, nullptr, nullptr, HDIM, (long)BB * HDIM, PDIM,
        nullptr, nullptr, nullptr, nullptr, nullptr, nullptr, nullptr, nullptr);

    // head: fused a1 compute + a2 GEMM + scores + reductions
    gemm_bs<2><<<dim3(1, (2 * BB) / BM, DDIM), 256, GEMM_SMEM>>>(
        nullptr, nullptr, HDIM, 0,
        w2thi, w2tlo, HDIM, (long)HDIM * HDIM,
        nullptr, nullptr, nullptr, nullptr, HDIM, 0, HDIM,
        b2, W3, b3, hwh, z, perm, Wz, b1);

    finalize_kernel<<<1, 32>>>((float*)d_out);
}

// round 8
// speedup vs baseline: 5.1923x; 1.2799x over previous
#include <cuda_runtime.h>
#include <cuda_bf16.h>
#include <math.h>
#include <stdint.h>

// Problem dims
#define BB   512
#define XDIM 32768
#define PDIM 512
#define DDIM 64
#define HDIM 128
#define G1D  1024

// Shared HMMA config
#define BM 128
#define BK 32
#define PITCH 40
#define ROWB (PITCH * 2)        // 80

// gemm_bs (BN=128)
#define MAT_BYTES (128 * ROWB)        // 10240
#define STG_BYTES (4 * MAT_BYTES)     // 40960
#define GEMM_SMEM (2 * STG_BYTES)     // 81920

// K1 (BM=128, BN=256, KS=8, 3-stage, fused fp32->hi/lo loader)
#define K1_BN 256
#define K1_KS 8
#define K1_KCHUNK (XDIM / K1_KS)      // 4096
#define K1_NIT (K1_KCHUNK / BK)       // 128
#define K1_MAT_A 10240                // 128 rows x 80B
#define K1_B_PITCH 528                // 256 n x 2B + 16B pad
#define K1_MAT_B (32 * K1_B_PITCH)    // 16896
#define K1_AH 0
#define K1_AL K1_MAT_A
#define K1_BH (2 * K1_MAT_A)
#define K1_BL (2 * K1_MAT_A + K1_MAT_B)
#define K1_STG (2 * K1_MAT_A + 2 * K1_MAT_B)   // 54272
#define K1_SMEM (3 * K1_STG)                   // 162816

// ---------------- device scratch ----------------
__device__ float g_part[K1_KS * BB * G1D];     // 16 MB
__device__ __nv_bfloat16 g_h1hi[BB * G1D];
__device__ __nv_bfloat16 g_h1lo[BB * G1D];
__device__ __nv_bfloat16 g_wg2thi[PDIM * G1D];
__device__ __nv_bfloat16 g_wg2tlo[PDIM * G1D];
__device__ __nv_bfloat16 g_hhi[BB * PDIM];
__device__ __nv_bfloat16 g_hlo[BB * PDIM];
__device__ __nv_bfloat16 g_whthi[DDIM * HDIM * PDIM];
__device__ __nv_bfloat16 g_whtlo[DDIM * HDIM * PDIM];
__device__ float g_hWh[DDIM * BB * HDIM];
__device__ __nv_bfloat16 g_w2thi[DDIM * HDIM * HDIM];
__device__ __nv_bfloat16 g_w2tlo[DDIM * HDIM * HDIM];
__device__ float g_js[DDIM * 8];
__device__ float g_es[DDIM * 8];

__device__ __forceinline__ float eluf(float x) {
    return x > 0.f ? x : expm1f(x);
}
__device__ __forceinline__ uint32_t smem_u32(const void* p) {
    uint32_t a;
    asm("{ .reg .u64 t; cvta.to.shared.u64 t, %1; cvt.u32.u64 %0, t; }"
        : "=r"(a) : "l"(p));
    return a;
}
#define CP16(dst, src) \
    asm volatile("cp.async.cg.shared.global [%0], [%1], 16;" \
                 :: "r"(dst), "l"(src) : "memory")
#define CP_COMMIT() asm volatile("cp.async.commit_group;" ::: "memory")
#define CP_WAIT1()  asm volatile("cp.async.wait_group 1;" ::: "memory")
#define CP_WAIT0()  asm volatile("cp.async.wait_group 0;" ::: "memory")

__device__ __forceinline__ void ldmx4(uint32_t* r, uint32_t addr) {
    asm volatile("ldmatrix.sync.aligned.m8n8.x4.shared.b16 {%0,%1,%2,%3}, [%4];"
                 : "=r"(r[0]), "=r"(r[1]), "=r"(r[2]), "=r"(r[3]) : "r"(addr));
}
__device__ __forceinline__ void ldmx4t(uint32_t* r, uint32_t addr) {
    asm volatile("ldmatrix.sync.aligned.m8n8.x4.trans.shared.b16 {%0,%1,%2,%3}, [%4];"
                 : "=r"(r[0]), "=r"(r[1]), "=r"(r[2]), "=r"(r[3]) : "r"(addr));
}
__device__ __forceinline__ void mma16816(float* c, const uint32_t* a,
                                         uint32_t b0, uint32_t b1) {
    asm volatile(
        "mma.sync.aligned.m16n8k16.row.col.f32.bf16.bf16.f32 "
        "{%0,%1,%2,%3}, {%4,%5,%6,%7}, {%8,%9}, {%0,%1,%2,%3};"
        : "+f"(c[0]), "+f"(c[1]), "+f"(c[2]), "+f"(c[3])
        : "r"(a[0]), "r"(a[1]), "r"(a[2]), "r"(a[3]), "r"(b0), "r"(b1));
}
__device__ __forceinline__ void hilo(float v, __nv_bfloat16& h, __nv_bfloat16& l) {
    h = __float2bfloat16(v);
    l = __float2bfloat16(v - __bfloat162float(h));
}
// pack 8 fp32 -> 16B hi + 16B lo
__device__ __forceinline__ void pack8(const float* v, uint4& H, uint4& L) {
    uint32_t hw[4], lw[4];
#pragma unroll
    for (int j = 0; j < 4; j++) {
        __nv_bfloat16 h0, l0, h1, l1;
        hilo(v[2 * j], h0, l0);
        hilo(v[2 * j + 1], h1, l1);
        __nv_bfloat162 ph; ph.x = h0; ph.y = h1;
        __nv_bfloat162 pl; pl.x = l0; pl.y = l1;
        hw[j] = *(uint32_t*)&ph;
        lw[j] = *(uint32_t*)&pl;
    }
    H = make_uint4(hw[0], hw[1], hw[2], hw[3]);
    L = make_uint4(lw[0], lw[1], lw[2], lw[3]);
}

// ---------------- conversions (small weights only) ----------------
__global__ void transconv_kernel(const float* __restrict__ src,
                                 __nv_bfloat16* __restrict__ dhi,
                                 __nv_bfloat16* __restrict__ dlo,
                                 int R, int C) {
    __shared__ float s[32][33];
    const size_t zoff = (size_t)blockIdx.z * R * C;
    const int rt = blockIdx.y * 32, ct = blockIdx.x * 32;
    const int tx = threadIdx.x & 31, ty = threadIdx.x >> 5;
    for (int r = ty; r < 32; r += 8)
        s[r][tx] = src[zoff + (size_t)(rt + r) * C + ct + tx];
    __syncthreads();
    for (int c = ty; c < 32; c += 8) {
        float v = s[tx][c];
        __nv_bfloat16 h, l;
        hilo(v, h, l);
        dhi[zoff + (size_t)(ct + c) * R + rt + tx] = h;
        dlo[zoff + (size_t)(ct + c) * R + rt + tx] = l;
    }
}

// ---------------- K1: fused-convert bf16-split HMMA ----------------
__global__ void __launch_bounds__(256, 1) gemm_k1_kernel(
    const float* __restrict__ x, const float* __restrict__ Wg1)
{
    extern __shared__ char sm[];
    const uint32_t sb = smem_u32(sm);
    const int tid = threadIdx.x;
    const int lane = tid & 31;
    const int wid = tid >> 5;
    const int warpM = wid >> 2;   // 0..1 -> 64 rows
    const int warpN = wid & 3;    // 0..3 -> 64 cols

    const int nBase = blockIdx.x * K1_BN;
    const int mBase = blockIdx.y * BM;
    const int kBase = blockIdx.z * K1_KCHUNK;

    const uint32_t laneOffA =
        (uint32_t)(((lane & 7) + ((lane >> 3) & 1) * 8) * ROWB + (lane >> 4) * 16);
    const uint32_t laneOffB =
        (uint32_t)(((lane & 7) + ((lane >> 3) & 1) * 8) * K1_B_PITCH +
                   (lane >> 4) * 16);

    float acc[4][8][4];
#pragma unroll
    for (int i = 0; i < 4; i++)
#pragma unroll
        for (int j = 0; j < 8; j++)
#pragma unroll
            for (int k = 0; k < 4; k++) acc[i][j][k] = 0.f;

    float pfA[2][8], pfB[4][8];

    // issue LDGs for k-stage `itn` into prefetch regs
    auto LDG_STAGE = [&](int itn) {
        const int k0 = kBase + itn * BK;
#pragma unroll
        for (int t = 0; t < 2; t++) {
            int u = tid + t * 256;
            int m = u >> 2, kc = (u & 3) * 8;
            const float4* s = (const float4*)(x + (size_t)(mBase + m) * XDIM + k0 + kc);
            float4 v0 = __ldg(s), v1 = __ldg(s + 1);
            pfA[t][0] = v0.x; pfA[t][1] = v0.y; pfA[t][2] = v0.z; pfA[t][3] = v0.w;
            pfA[t][4] = v1.x; pfA[t][5] = v1.y; pfA[t][6] = v1.z; pfA[t][7] = v1.w;
        }
#pragma unroll
        for (int t = 0; t < 4; t++) {
            int u = tid + t * 256;
            int k = u >> 5, n8 = (u & 31) * 8;
            const float4* s = (const float4*)(Wg1 + (size_t)(k0 + k) * G1D + nBase + n8);
            float4 v0 = __ldg(s), v1 = __ldg(s + 1);
            pfB[t][0] = v0.x; pfB[t][1] = v0.y; pfB[t][2] = v0.z; pfB[t][3] = v0.w;
            pfB[t][4] = v1.x; pfB[t][5] = v1.y; pfB[t][6] = v1.z; pfB[t][7] = v1.w;
        }
    };
    // convert + store prefetch regs into smem stage
    auto STS_STAGE = [&](int stage) {
        char* st = sm + (size_t)stage * K1_STG;
#pragma unroll
        for (int t = 0; t < 2; t++) {
            int u = tid + t * 256;
            int m = u >> 2, kc = (u & 3) * 8;
            uint4 H, L;
            pack8(pfA[t], H, L);
            uint32_t so = (uint32_t)(m * ROWB + kc * 2);
            *(uint4*)(st + K1_AH + so) = H;
            *(uint4*)(st + K1_AL + so) = L;
        }
#pragma unroll
        for (int t = 0; t < 4; t++) {
            int u = tid + t * 256;
            int k = u >> 5, n8 = (u & 31) * 8;
            uint4 H, L;
            pack8(pfB[t], H, L);
            uint32_t so = (uint32_t)(k * K1_B_PITCH + n8 * 2);
            *(uint4*)(st + K1_BH + so) = H;
            *(uint4*)(st + K1_BL + so) = L;
        }
    };

    // preload stages 0 and 1
    LDG_STAGE(0); STS_STAGE(0);
    LDG_STAGE(1); STS_STAGE(1);
    __syncthreads();

#pragma unroll 1
    for (int it = 0; it < K1_NIT; it++) {
        const bool pf = (it + 2 < K1_NIT);
        if (pf) LDG_STAGE(it + 2);   // latency hidden under MMA block

        uint32_t st = sb + (uint32_t)(it % 3) * K1_STG;
        uint32_t aH = st + K1_AH + (uint32_t)(warpM * 64) * ROWB + laneOffA;
        uint32_t aL = st + K1_AL + (uint32_t)(warpM * 64) * ROWB + laneOffA;
        uint32_t bH = st + K1_BH + (uint32_t)(warpN * 64) * 2 + laneOffB;
        uint32_t bL = st + K1_BL + (uint32_t)(warpN * 64) * 2 + laneOffB;

#pragma unroll
        for (int ks = 0; ks < 2; ks++) {
            const uint32_t kbA = ks * 32;                 // 16 k * 2B in A rows
            const uint32_t kbB = ks * 16 * K1_B_PITCH;    // 16 k rows in B
            uint32_t ah[4][4], al[4][4], bh[4][4], bl[4][4];
#pragma unroll
            for (int mt = 0; mt < 4; mt++) {
                ldmx4(ah[mt], aH + (uint32_t)(mt * 16) * ROWB + kbA);
                ldmx4(al[mt], aL + (uint32_t)(mt * 16) * ROWB + kbA);
            }
#pragma unroll
            for (int p = 0; p < 4; p++) {                 // 4 x 16-n chunks
                ldmx4t(bh[p], bH + (uint32_t)(p * 32) + kbB);
                ldmx4t(bl[p], bL + (uint32_t)(p * 32) + kbB);
            }
#pragma unroll
            for (int mt = 0; mt < 4; mt++) {
#pragma unroll
                for (int nt = 0; nt < 8; nt++) {
                    const int t = nt >> 1, q = (nt & 1) * 2;
                    mma16816(acc[mt][nt], ah[mt], bh[t][q], bh[t][q + 1]);
                    mma16816(acc[mt][nt], ah[mt], bl[t][q], bl[t][q + 1]);
                    mma16816(acc[mt][nt], al[mt], bh[t][q], bh[t][q + 1]);
                }
            }
        }

        if (pf) STS_STAGE((it + 2) % 3);
        __syncthreads();
    }

    float* base = g_part + (size_t)blockIdx.z * (BB * G1D);
#pragma unroll
    for (int mt = 0; mt < 4; mt++) {
        int m0 = mBase + warpM * 64 + mt * 16 + (lane >> 2);
#pragma unroll
        for (int nt = 0; nt < 8; nt++) {
            int n0 = nBase + warpN * 64 + nt * 8 + (lane & 3) * 2;
            *(float2*)(base + (size_t)m0 * G1D + n0) =
                make_float2(acc[mt][nt][0], acc[mt][nt][1]);
            *(float2*)(base + (size_t)(m0 + 8) * G1D + n0) =
                make_float2(acc[mt][nt][2], acc[mt][nt][3]);
        }
    }
}

// partials -> h1 = elu(sum + bias), bf16 hi/lo
__global__ void reduce_h1_kernel(const float* __restrict__ bg1) {
    const int i = blockIdx.x * 256 + threadIdx.x;
    float s = 0.f;
#pragma unroll
    for (int k = 0; k < K1_KS; k++) s += g_part[k * (BB * G1D) + i];
    float v = eluf(s + bg1[i & (G1D - 1)]);
    __nv_bfloat16 h, l;
    hilo(v, h, l);
    g_h1hi[i] = h;
    g_h1lo[i] = l;
}

// ---------------- unified bf16-split HMMA GEMM (BN=128) ----------------
// EPI=0: fp32 C. EPI=1: elu(acc+bias)->bf16 hi/lo.
// EPI=2: fused head — A computed on the fly from hWh/z/perm/Wz/b1,
//        epilogue does scores + joint/exp reductions. grid (1, 8, DDIM).
template <int EPI>
__global__ void __launch_bounds__(256, 2) gemm_bs(
    const __nv_bfloat16* __restrict__ Ahi, const __nv_bfloat16* __restrict__ Alo,
    int lda, long sAz,
    const __nv_bfloat16* __restrict__ Bhi, const __nv_bfloat16* __restrict__ Blo,
    int ldb, long sBz,
    float* __restrict__ C, __nv_bfloat16* __restrict__ Chi,
    __nv_bfloat16* __restrict__ Clo,
    const float* __restrict__ bias, int ldc, long sCz, int K,
    const float* __restrict__ b2, const float* __restrict__ W3,
    const float* __restrict__ b3,
    const float* __restrict__ hwhp, const float* __restrict__ zv,
    const int* __restrict__ permp, const float* __restrict__ Wzp,
    const float* __restrict__ b1p)
{
    extern __shared__ char sm[];
    __shared__ float red[128][5];
    __shared__ float wr[8];
    __shared__ float s_wz[HDIM], s_b1[HDIM];
    const uint32_t sb = smem_u32(sm);
    const int tid = threadIdx.x;
    const int lane = tid & 31;
    const int wid = tid >> 5;
    const int warpM = wid >> 2;
    const int warpN = wid & 3;

    const int nBase = blockIdx.x * 128;
    const int mBase = blockIdx.y * BM;
    const __nv_bfloat16* ahiz = Ahi + (size_t)blockIdx.z * sAz;
    const __nv_bfloat16* aloz = Alo + (size_t)blockIdx.z * sAz;
    const __nv_bfloat16* bhi = Bhi + (size_t)blockIdx.z * sBz;
    const __nv_bfloat16* blo = Blo + (size_t)blockIdx.z * sBz;

    if (EPI == 2) {
        if (tid < HDIM) {
            s_wz[tid] = Wzp[(size_t)blockIdx.z * HDIM + tid];
            s_b1[tid] = b1p[(size_t)blockIdx.z * HDIM + tid];
        }
        __syncthreads();
    }

    const uint32_t laneOff =
        (uint32_t)(((lane & 7) + ((lane >> 3) & 1) * 8) * ROWB + (lane >> 4) * 16);
    const int NIT = K / BK;

    float acc[4][4][4];
#pragma unroll
    for (int i = 0; i < 4; i++)
#pragma unroll
        for (int j = 0; j < 4; j++)
#pragma unroll
            for (int k = 0; k < 4; k++) acc[i][j][k] = 0.f;

#define A_COMPUTE(stage, k0)                                                   \
    do {                                                                       \
        uint32_t stoff = (uint32_t)(stage) * STG_BYTES;                        \
        const float* hwh_d = hwhp + (size_t)blockIdx.z * BB * HDIM;            \
        _Pragma("unroll")                                                      \
        for (int t = 0; t < 2; t++) {                                          \
            int u = tid + t * 256;                                             \
            int r = u >> 2, ch = u & 3;                                        \
            int gm = mBase + r;                                                \
            int b = (gm < BB) ? gm : gm - BB;                                  \
            int src = (gm < BB) ? b : __ldg(permp + b);                        \
            float zb = __ldg(zv + (size_t)b * DDIM + blockIdx.z);              \
            const float* hr = hwh_d + (size_t)src * HDIM + (k0) + ch * 8;      \
            float4 v0 = __ldg((const float4*)hr);                              \
            float4 v1 = __ldg((const float4*)(hr + 4));                        \
            float hv[8] = {v0.x, v0.y, v0.z, v0.w, v1.x, v1.y, v1.z, v1.w};    \
            uint32_t hp[4], lp[4];                                             \
            _Pragma("unroll")                                                  \
            for (int j = 0; j < 4; j++) {                                      \
                int kk = (k0) + ch * 8 + 2 * j;                                \
                float a0 = eluf(hv[2*j]   + fmaf(zb, s_wz[kk],   s_b1[kk]));   \
                float a1v = eluf(hv[2*j+1] + fmaf(zb, s_wz[kk+1], s_b1[kk+1]));\
                __nv_bfloat16 hh0, ll0, hh1, ll1;                              \
                hilo(a0, hh0, ll0); hilo(a1v, hh1, ll1);                       \
                __nv_bfloat162 ph; ph.x = hh0; ph.y = hh1;                     \
                __nv_bfloat162 pl; pl.x = ll0; pl.y = ll1;                     \
                hp[j] = *(uint32_t*)&ph; lp[j] = *(uint32_t*)&pl;              \
            }                                                                  \
            uint32_t so = (uint32_t)(r * ROWB + ch * 16);                      \
            *(uint4*)(sm + stoff + 0 * MAT_BYTES + so) =                       \
                make_uint4(hp[0], hp[1], hp[2], hp[3]);                        \
            *(uint4*)(sm + stoff + 1 * MAT_BYTES + so) =                       \
                make_uint4(lp[0], lp[1], lp[2], lp[3]);                        \
        }                                                                      \
    } while (0)

#define BS_LOAD(stage, k0)                                                     \
    do {                                                                       \
        uint32_t st = sb + (uint32_t)(stage)*STG_BYTES;                        \
        if (EPI == 2) {                                                        \
            A_COMPUTE(stage, k0);                                              \
        } else {                                                               \
            _Pragma("unroll")                                                  \
            for (int t = 0; t < 2; t++) {                                      \
                int ci = tid + t * 256;                                        \
                int r = ci >> 2, ch = ci & 3;                                  \
                uint32_t so = (uint32_t)(r * ROWB + ch * 16);                  \
                size_t goA = (size_t)(mBase + r) * lda + (k0) + ch * 8;        \
                CP16(st + 0 * MAT_BYTES + so, ahiz + goA);                     \
                CP16(st + 1 * MAT_BYTES + so, aloz + goA);                     \
            }                                                                  \
        }                                                                      \
        _Pragma("unroll")                                                      \
        for (int t = 0; t < 2; t++) {                                          \
            int ci = tid + t * 256;                                            \
            int r = ci >> 2, ch = ci & 3;                                      \
            uint32_t so = (uint32_t)(r * ROWB + ch * 16);                      \
            size_t goB = (size_t)(nBase + r) * ldb + (k0) + ch * 8;            \
            CP16(st + 2 * MAT_BYTES + so, bhi + goB);                          \
            CP16(st + 3 * MAT_BYTES + so, blo + goB);                          \
        }                                                                      \
    } while (0)

    BS_LOAD(0, 0);
    CP_COMMIT();

#pragma unroll 1
    for (int it = 0; it < NIT; it++) {
        if (it + 1 < NIT) {
            BS_LOAD((it + 1) & 1, (it + 1) * BK);
            CP_COMMIT();
            CP_WAIT1();
        } else {
            CP_WAIT0();
        }
        __syncthreads();

        uint32_t st = sb + (uint32_t)(it & 1) * STG_BYTES;
        uint32_t aH = st + 0 * MAT_BYTES + (uint32_t)(warpM * 64) * ROWB + laneOff;
        uint32_t aL = st + 1 * MAT_BYTES + (uint32_t)(warpM * 64) * ROWB + laneOff;
        uint32_t bH = st + 2 * MAT_BYTES + (uint32_t)(warpN * 32) * ROWB + laneOff;
        uint32_t bL = st + 3 * MAT_BYTES + (uint32_t)(warpN * 32) * ROWB + laneOff;

#pragma unroll
        for (int ks = 0; ks < 2; ks++) {
            const uint32_t kb = ks * 32;
            uint32_t ah[4][4], al[4][4], bh[2][4], bl[2][4];
#pragma unroll
            for (int mt = 0; mt < 4; mt++) {
                ldmx4(ah[mt], aH + (uint32_t)(mt * 16) * ROWB + kb);
                ldmx4(al[mt], aL + (uint32_t)(mt * 16) * ROWB + kb);
            }
#pragma unroll
            for (int p = 0; p < 2; p++) {
                ldmx4(bh[p], bH + (uint32_t)(p * 16) * ROWB + kb);
                ldmx4(bl[p], bL + (uint32_t)(p * 16) * ROWB + kb);
            }
#pragma unroll
            for (int mt = 0; mt < 4; mt++) {
#pragma unroll
                for (int nt = 0; nt < 4; nt++) {
                    const int p = nt >> 1, q = nt & 1;
                    mma16816(acc[mt][nt], ah[mt], bh[p][q], bh[p][q + 2]);
                    mma16816(acc[mt][nt], ah[mt], bl[p][q], bl[p][q + 2]);
                    mma16816(acc[mt][nt], al[mt], bh[p][q], bh[p][q + 2]);
                }
            }
        }
        __syncthreads();
    }
#undef BS_LOAD
#undef A_COMPUTE

    if (EPI == 2) {
        const float* b2z = b2 + (size_t)blockIdx.z * HDIM;
        const float* w3z = W3 + (size_t)blockIdx.z * HDIM;
        const float b3d = b3[blockIdx.z];
        const bool joint = (blockIdx.y < 4);
#pragma unroll
        for (int mt = 0; mt < 4; mt++) {
            float s0 = 0.f, s1 = 0.f;
#pragma unroll
            for (int nt = 0; nt < 4; nt++) {
                int n0 = warpN * 32 + nt * 8 + (lane & 3) * 2;
                float w0 = __ldg(w3z + n0), w1 = __ldg(w3z + n0 + 1);
                float c0 = __ldg(b2z + n0), c1 = __ldg(b2z + n0 + 1);
                s0 += eluf(acc[mt][nt][0] + c0) * w0 + eluf(acc[mt][nt][1] + c1) * w1;
                s1 += eluf(acc[mt][nt][2] + c0) * w0 + eluf(acc[mt][nt][3] + c1) * w1;
            }
            s0 += __shfl_xor_sync(0xffffffffu, s0, 1);
            s0 += __shfl_xor_sync(0xffffffffu, s0, 2);
            s1 += __shfl_xor_sync(0xffffffffu, s1, 1);
            s1 += __shfl_xor_sync(0xffffffffu, s1, 2);
            if ((lane & 3) == 0) {
                int r0 = warpM * 64 + mt * 16 + (lane >> 2);
                red[r0][warpN] = s0;
                red[r0 + 8][warpN] = s1;
            }
        }
        __syncthreads();
        float val = 0.f;
        if (tid < 128) {
            float s = red[tid][0] + red[tid][1] + red[tid][2] + red[tid][3] + b3d;
            val = joint ? s : expf(s);
        }
#pragma unroll
        for (int off = 16; off; off >>= 1)
            val += __shfl_xor_sync(0xffffffffu, val, off);
        if (lane == 0) wr[wid] = val;
        __syncthreads();
        if (tid == 0) {
            float s = wr[0] + wr[1] + wr[2] + wr[3];
            int slot = blockIdx.z * 8 + blockIdx.y;
            if (joint) { g_js[slot] = s; g_es[slot] = 0.f; }
            else       { g_js[slot] = 0.f; g_es[slot] = s; }
        }
        return;
    }

#pragma unroll
    for (int mt = 0; mt < 4; mt++) {
        int m0 = mBase + warpM * 64 + mt * 16 + (lane >> 2);
#pragma unroll
        for (int nt = 0; nt < 4; nt++) {
            int n0 = nBase + warpN * 32 + nt * 8 + (lane & 3) * 2;
            if (EPI == 0) {
                float* Cz = C + (size_t)blockIdx.z * sCz;
                *(float2*)(Cz + (size_t)m0 * ldc + n0) =
                    make_float2(acc[mt][nt][0], acc[mt][nt][1]);
                *(float2*)(Cz + (size_t)(m0 + 8) * ldc + n0) =
                    make_float2(acc[mt][nt][2], acc[mt][nt][3]);
            } else if (EPI == 1) {
                float bv0 = bias[n0], bv1 = bias[n0 + 1];
                float u0 = eluf(acc[mt][nt][0] + bv0);
                float u1 = eluf(acc[mt][nt][1] + bv1);
                float u2 = eluf(acc[mt][nt][2] + bv0);
                float u3 = eluf(acc[mt][nt][3] + bv1);
                __nv_bfloat16 h0, h1, h2, h3, l0, l1, l2, l3;
                hilo(u0, h0, l0); hilo(u1, h1, l1);
                hilo(u2, h2, l2); hilo(u3, h3, l3);
                __nv_bfloat162 vh, vl;
                vh.x = h0; vh.y = h1; vl.x = l0; vl.y = l1;
                *(__nv_bfloat162*)(Chi + (size_t)m0 * ldc + n0) = vh;
                *(__nv_bfloat162*)(Clo + (size_t)m0 * ldc + n0) = vl;
                vh.x = h2; vh.y = h3; vl.x = l2; vl.y = l3;
                *(__nv_bfloat162*)(Chi + (size_t)(m0 + 8) * ldc + n0) = vh;
                *(__nv_bfloat162*)(Clo + (size_t)(m0 + 8) * ldc + n0) = vl;
            }
        }
    }
}

__global__ void finalize_kernel(float* __restrict__ out)
{
    int t = threadIdx.x;
    float acc = 0.f;
    for (int d = t; d < DDIM; d += 32) {
        float js = 0.f, es = 0.f;
#pragma unroll
        for (int c = 0; c < 8; c++) { js += g_js[d * 8 + c]; es += g_es[d * 8 + c]; }
        acc += js * (1.f / BB) - logf(es * (1.f / BB));
    }
#pragma unroll
    for (int off = 16; off; off >>= 1)
        acc += __shfl_xor_sync(0xffffffffu, acc, off);
    if (t == 0) out[0] = -acc * (1.f / DDIM);
}

// ---------------------------------------------------------------------------
extern "C" void kernel_launch(void* const* d_in, const int* in_sizes, int n_in,
                              void* d_out, int out_size)
{
    const float* x   = (const float*)d_in[0];
    const float* z   = (const float*)d_in[1];
    const int*   perm= (const int*)  d_in[2];
    const float* Wg1 = (const float*)d_in[3];
    const float* bg1 = (const float*)d_in[4];
    const float* Wg2 = (const float*)d_in[5];
    const float* bg2 = (const float*)d_in[6];
    const float* Wh  = (const float*)d_in[7];
    const float* Wz  = (const float*)d_in[8];
    const float* b1  = (const float*)d_in[9];
    const float* W2  = (const float*)d_in[10];
    const float* b2  = (const float*)d_in[11];
    const float* W3  = (const float*)d_in[12];
    const float* b3  = (const float*)d_in[13];

    __nv_bfloat16 *h1hi, *h1lo, *wg2thi, *wg2tlo, *hhi, *hlo, *whthi, *whtlo;
    __nv_bfloat16 *w2thi, *w2tlo;
    float* hwh;
    cudaGetSymbolAddress((void**)&h1hi,   g_h1hi);
    cudaGetSymbolAddress((void**)&h1lo,   g_h1lo);
    cudaGetSymbolAddress((void**)&wg2thi, g_wg2thi);
    cudaGetSymbolAddress((void**)&wg2tlo, g_wg2tlo);
    cudaGetSymbolAddress((void**)&hhi,    g_hhi);
    cudaGetSymbolAddress((void**)&hlo,    g_hlo);
    cudaGetSymbolAddress((void**)&whthi,  g_whthi);
    cudaGetSymbolAddress((void**)&whtlo,  g_whtlo);
    cudaGetSymbolAddress((void**)&w2thi,  g_w2thi);
    cudaGetSymbolAddress((void**)&w2tlo,  g_w2tlo);
    cudaGetSymbolAddress((void**)&hwh,    g_hWh);

    // small-weight conversions only (Wg1/x converted inside K1's loader)
    transconv_kernel<<<dim3(PDIM / 32, G1D / 32, 1), 256>>>(Wg2, wg2thi, wg2tlo,
                                                            G1D, PDIM);
    transconv_kernel<<<dim3(HDIM / 32, PDIM / 32, DDIM), 256>>>(Wh, whthi, whtlo,
                                                                PDIM, HDIM);
    transconv_kernel<<<dim3(HDIM / 32, HDIM / 32, DDIM), 256>>>(W2, w2thi, w2tlo,
                                                                HDIM, HDIM);

    // K1: fused fp32->hi/lo loader + bf16-split HMMA
    cudaFuncSetAttribute(gemm_k1_kernel,
                         cudaFuncAttributeMaxDynamicSharedMemorySize, K1_SMEM);
    gemm_k1_kernel<<<dim3(G1D / K1_BN, BB / BM, K1_KS), 256, K1_SMEM>>>(x, Wg1);
    reduce_h1_kernel<<<(BB * G1D) / 256, 256>>>(bg1);

    cudaFuncSetAttribute(gemm_bs<0>,
                         cudaFuncAttributeMaxDynamicSharedMemorySize, GEMM_SMEM);
    cudaFuncSetAttribute(gemm_bs<1>,
                         cudaFuncAttributeMaxDynamicSharedMemorySize, GEMM_SMEM);
    cudaFuncSetAttribute(gemm_bs<2>,
                         cudaFuncAttributeMaxDynamicSharedMemorySize, GEMM_SMEM);

    // K2: h = elu(h1 @ Wg2 + bg2) -> bf16 hi/lo
    gemm_bs<1><<<dim3(PDIM / 128, BB / BM, 1), 256, GEMM_SMEM>>>(
        h1hi, h1lo, G1D, 0, wg2thi, wg2tlo, G1D, 0,
        nullptr, hhi, hlo, bg2, PDIM, 0, G1D,
        nullptr, nullptr, nullptr, nullptr, nullptr, nullptr, nullptr, nullptr);

    // K3: hWh[d] = h @ WhT[d]  (fp32)
    gemm_bs<0><<<dim3(1, BB / BM, DDIM), 256, GEMM_SMEM>>>(
        hhi, hlo, PDIM, 0, whthi, whtlo, PDIM, (long)HDIM * PDIM,
        hwh, nullptr, nullptr, nullptr, HDIM, (long)BB * HDIM, PDIM,
        nullptr, nullptr, nullptr, nullptr, nullptr, nullptr, nullptr, nullptr);

    // head: fused a1 compute + a2 GEMM + scores + reductions
    gemm_bs<2><<<dim3(1, (2 * BB) / BM, DDIM), 256, GEMM_SMEM>>>(
        nullptr, nullptr, HDIM, 0,
        w2thi, w2tlo, HDIM, (long)HDIM * HDIM,
        nullptr, nullptr, nullptr, nullptr, HDIM, 0, HDIM,
        b2, W3, b3, hwh, z, perm, Wz, b1);

    finalize_kernel<<<1, 32>>>((float*)d_out);
}

// round 9
// speedup vs baseline: 5.2770x; 1.0163x over previous
#include <cuda_runtime.h>
#include <cuda_bf16.h>
#include <math.h>
#include <stdint.h>

// Problem dims
#define BB   512
#define XDIM 32768
#define PDIM 512
#define DDIM 64
#define HDIM 128
#define G1D  1024

// Shared HMMA config
#define BM 128
#define BK 32
#define PITCH 40
#define ROWB (PITCH * 2)        // 80

// gemm_bs (BN=128)
#define MAT_BYTES (128 * ROWB)        // 10240
#define STG_BYTES (4 * MAT_BYTES)     // 40960
#define GEMM_SMEM (2 * STG_BYTES)     // 81920

// K1 (BM=128, BN=256, KS=8, 3-stage, fused fp32->hi/lo loader)
#define K1_BN 256
#define K1_KS 8
#define K1_KCHUNK (XDIM / K1_KS)      // 4096
#define K1_NIT (K1_KCHUNK / BK)       // 128
#define K1_MAT_A 10240                // 128 rows x 80B
#define K1_B_PITCH 528                // 256 n x 2B + 16B pad
#define K1_MAT_B (32 * K1_B_PITCH)    // 16896
#define K1_AH 0
#define K1_AL K1_MAT_A
#define K1_BH (2 * K1_MAT_A)
#define K1_BL (2 * K1_MAT_A + K1_MAT_B)
#define K1_STG (2 * K1_MAT_A + 2 * K1_MAT_B)   // 54272
#define K1_SMEM (3 * K1_STG)                   // 162816

// ---------------- device scratch ----------------
__device__ float g_part[K1_KS * BB * G1D];     // 16 MB
__device__ __nv_bfloat16 g_h1hi[BB * G1D];
__device__ __nv_bfloat16 g_h1lo[BB * G1D];
__device__ __nv_bfloat16 g_wg2thi[PDIM * G1D];
__device__ __nv_bfloat16 g_wg2tlo[PDIM * G1D];
__device__ __nv_bfloat16 g_hhi[BB * PDIM];
__device__ __nv_bfloat16 g_hlo[BB * PDIM];
__device__ __nv_bfloat16 g_whthi[DDIM * HDIM * PDIM];
__device__ __nv_bfloat16 g_whtlo[DDIM * HDIM * PDIM];
__device__ float g_hWh[DDIM * BB * HDIM];
__device__ __nv_bfloat16 g_w2thi[DDIM * HDIM * HDIM];
__device__ __nv_bfloat16 g_w2tlo[DDIM * HDIM * HDIM];
__device__ float g_js[DDIM * 8];
__device__ float g_es[DDIM * 8];

__device__ __forceinline__ float eluf(float x) {
    return x > 0.f ? x : expm1f(x);
}
__device__ __forceinline__ uint32_t smem_u32(const void* p) {
    uint32_t a;
    asm("{ .reg .u64 t; cvta.to.shared.u64 t, %1; cvt.u32.u64 %0, t; }"
        : "=r"(a) : "l"(p));
    return a;
}
#define CP16(dst, src) \
    asm volatile("cp.async.cg.shared.global [%0], [%1], 16;" \
                 :: "r"(dst), "l"(src) : "memory")
#define CP_COMMIT() asm volatile("cp.async.commit_group;" ::: "memory")
#define CP_WAIT1()  asm volatile("cp.async.wait_group 1;" ::: "memory")
#define CP_WAIT0()  asm volatile("cp.async.wait_group 0;" ::: "memory")

__device__ __forceinline__ void ldmx4(uint32_t* r, uint32_t addr) {
    asm volatile("ldmatrix.sync.aligned.m8n8.x4.shared.b16 {%0,%1,%2,%3}, [%4];"
                 : "=r"(r[0]), "=r"(r[1]), "=r"(r[2]), "=r"(r[3]) : "r"(addr));
}
__device__ __forceinline__ void ldmx4t(uint32_t* r, uint32_t addr) {
    asm volatile("ldmatrix.sync.aligned.m8n8.x4.trans.shared.b16 {%0,%1,%2,%3}, [%4];"
                 : "=r"(r[0]), "=r"(r[1]), "=r"(r[2]), "=r"(r[3]) : "r"(addr));
}
__device__ __forceinline__ void mma16816(float* c, const uint32_t* a,
                                         uint32_t b0, uint32_t b1) {
    asm volatile(
        "mma.sync.aligned.m16n8k16.row.col.f32.bf16.bf16.f32 "
        "{%0,%1,%2,%3}, {%4,%5,%6,%7}, {%8,%9}, {%0,%1,%2,%3};"
        : "+f"(c[0]), "+f"(c[1]), "+f"(c[2]), "+f"(c[3])
        : "r"(a[0]), "r"(a[1]), "r"(a[2]), "r"(a[3]), "r"(b0), "r"(b1));
}
__device__ __forceinline__ void hilo(float v, __nv_bfloat16& h, __nv_bfloat16& l) {
    h = __float2bfloat16(v);
    l = __float2bfloat16(v - __bfloat162float(h));
}
// pack 8 fp32 -> 16B hi + 16B lo
__device__ __forceinline__ void pack8(const float* v, uint4& H, uint4& L) {
    uint32_t hw[4], lw[4];
#pragma unroll
    for (int j = 0; j < 4; j++) {
        __nv_bfloat16 h0, l0, h1, l1;
        hilo(v[2 * j], h0, l0);
        hilo(v[2 * j + 1], h1, l1);
        __nv_bfloat162 ph; ph.x = h0; ph.y = h1;
        __nv_bfloat162 pl; pl.x = l0; pl.y = l1;
        hw[j] = *(uint32_t*)&ph;
        lw[j] = *(uint32_t*)&pl;
    }
    H = make_uint4(hw[0], hw[1], hw[2], hw[3]);
    L = make_uint4(lw[0], lw[1], lw[2], lw[3]);
}

// ---------------- conversions (small weights only) ----------------
__global__ void transconv_kernel(const float* __restrict__ src,
                                 __nv_bfloat16* __restrict__ dhi,
                                 __nv_bfloat16* __restrict__ dlo,
                                 int R, int C) {
    __shared__ float s[32][33];
    const size_t zoff = (size_t)blockIdx.z * R * C;
    const int rt = blockIdx.y * 32, ct = blockIdx.x * 32;
    const int tx = threadIdx.x & 31, ty = threadIdx.x >> 5;
    for (int r = ty; r < 32; r += 8)
        s[r][tx] = src[zoff + (size_t)(rt + r) * C + ct + tx];
    __syncthreads();
    for (int c = ty; c < 32; c += 8) {
        float v = s[tx][c];
        __nv_bfloat16 h, l;
        hilo(v, h, l);
        dhi[zoff + (size_t)(ct + c) * R + rt + tx] = h;
        dlo[zoff + (size_t)(ct + c) * R + rt + tx] = l;
    }
}

// ---------------- K1: fused-convert bf16-split HMMA ----------------
__global__ void __launch_bounds__(256, 1) gemm_k1_kernel(
    const float* __restrict__ x, const float* __restrict__ Wg1)
{
    extern __shared__ char sm[];
    const uint32_t sb = smem_u32(sm);
    const int tid = threadIdx.x;
    const int lane = tid & 31;
    const int wid = tid >> 5;
    const int warpM = wid >> 2;   // 0..1 -> 64 rows
    const int warpN = wid & 3;    // 0..3 -> 64 cols

    const int nBase = blockIdx.x * K1_BN;
    const int mBase = blockIdx.y * BM;
    const int kBase = blockIdx.z * K1_KCHUNK;

    const uint32_t laneOffA =
        (uint32_t)(((lane & 7) + ((lane >> 3) & 1) * 8) * ROWB + (lane >> 4) * 16);
    const uint32_t laneOffB =
        (uint32_t)(((lane & 7) + ((lane >> 3) & 1) * 8) * K1_B_PITCH +
                   (lane >> 4) * 16);

    float acc[4][8][4];
#pragma unroll
    for (int i = 0; i < 4; i++)
#pragma unroll
        for (int j = 0; j < 8; j++)
#pragma unroll
            for (int k = 0; k < 4; k++) acc[i][j][k] = 0.f;

    float pfA[2][8], pfB[4][8];

    auto LDG_STAGE = [&](int itn) {
        const int k0 = kBase + itn * BK;
#pragma unroll
        for (int t = 0; t < 2; t++) {
            int u = tid + t * 256;
            int m = u >> 2, kc = (u & 3) * 8;
            const float4* s = (const float4*)(x + (size_t)(mBase + m) * XDIM + k0 + kc);
            float4 v0 = __ldg(s), v1 = __ldg(s + 1);
            pfA[t][0] = v0.x; pfA[t][1] = v0.y; pfA[t][2] = v0.z; pfA[t][3] = v0.w;
            pfA[t][4] = v1.x; pfA[t][5] = v1.y; pfA[t][6] = v1.z; pfA[t][7] = v1.w;
        }
#pragma unroll
        for (int t = 0; t < 4; t++) {
            int u = tid + t * 256;
            int k = u >> 5, n8 = (u & 31) * 8;
            const float4* s = (const float4*)(Wg1 + (size_t)(k0 + k) * G1D + nBase + n8);
            float4 v0 = __ldg(s), v1 = __ldg(s + 1);
            pfB[t][0] = v0.x; pfB[t][1] = v0.y; pfB[t][2] = v0.z; pfB[t][3] = v0.w;
            pfB[t][4] = v1.x; pfB[t][5] = v1.y; pfB[t][6] = v1.z; pfB[t][7] = v1.w;
        }
    };
    auto STS_STAGE = [&](int stage) {
        char* st = sm + (size_t)stage * K1_STG;
#pragma unroll
        for (int t = 0; t < 2; t++) {
            int u = tid + t * 256;
            int m = u >> 2, kc = (u & 3) * 8;
            uint4 H, L;
            pack8(pfA[t], H, L);
            uint32_t so = (uint32_t)(m * ROWB + kc * 2);
            *(uint4*)(st + K1_AH + so) = H;
            *(uint4*)(st + K1_AL + so) = L;
        }
#pragma unroll
        for (int t = 0; t < 4; t++) {
            int u = tid + t * 256;
            int k = u >> 5, n8 = (u & 31) * 8;
            uint4 H, L;
            pack8(pfB[t], H, L);
            uint32_t so = (uint32_t)(k * K1_B_PITCH + n8 * 2);
            *(uint4*)(st + K1_BH + so) = H;
            *(uint4*)(st + K1_BL + so) = L;
        }
    };

    LDG_STAGE(0); STS_STAGE(0);
    LDG_STAGE(1); STS_STAGE(1);
    __syncthreads();

#pragma unroll 1
    for (int it = 0; it < K1_NIT; it++) {
        const bool pf = (it + 2 < K1_NIT);
        if (pf) LDG_STAGE(it + 2);

        uint32_t st = sb + (uint32_t)(it % 3) * K1_STG;
        uint32_t aH = st + K1_AH + (uint32_t)(warpM * 64) * ROWB + laneOffA;
        uint32_t aL = st + K1_AL + (uint32_t)(warpM * 64) * ROWB + laneOffA;
        uint32_t bH = st + K1_BH + (uint32_t)(warpN * 64) * 2 + laneOffB;
        uint32_t bL = st + K1_BL + (uint32_t)(warpN * 64) * 2 + laneOffB;

#pragma unroll
        for (int ks = 0; ks < 2; ks++) {
            const uint32_t kbA = ks * 32;
            const uint32_t kbB = ks * 16 * K1_B_PITCH;
            uint32_t ah[4][4], al[4][4];
#pragma unroll
            for (int mt = 0; mt < 4; mt++) {
                ldmx4(ah[mt], aH + (uint32_t)(mt * 16) * ROWB + kbA);
                ldmx4(al[mt], aL + (uint32_t)(mt * 16) * ROWB + kbA);
            }
            // B fragments loaded per 16-col chunk and consumed immediately
#pragma unroll
            for (int p = 0; p < 4; p++) {
                uint32_t bh[4], bl[4];
                ldmx4t(bh, bH + (uint32_t)(p * 32) + kbB);
                ldmx4t(bl, bL + (uint32_t)(p * 32) + kbB);
#pragma unroll
                for (int mt = 0; mt < 4; mt++) {
                    mma16816(acc[mt][2 * p], ah[mt], bh[0], bh[1]);
                    mma16816(acc[mt][2 * p], ah[mt], bl[0], bl[1]);
                    mma16816(acc[mt][2 * p], al[mt], bh[0], bh[1]);
                    mma16816(acc[mt][2 * p + 1], ah[mt], bh[2], bh[3]);
                    mma16816(acc[mt][2 * p + 1], ah[mt], bl[2], bl[3]);
                    mma16816(acc[mt][2 * p + 1], al[mt], bh[2], bh[3]);
                }
            }
        }

        if (pf) STS_STAGE((it + 2) % 3);
        __syncthreads();
    }

    float* base = g_part + (size_t)blockIdx.z * (BB * G1D);
#pragma unroll
    for (int mt = 0; mt < 4; mt++) {
        int m0 = mBase + warpM * 64 + mt * 16 + (lane >> 2);
#pragma unroll
        for (int nt = 0; nt < 8; nt++) {
            int n0 = nBase + warpN * 64 + nt * 8 + (lane & 3) * 2;
            *(float2*)(base + (size_t)m0 * G1D + n0) =
                make_float2(acc[mt][nt][0], acc[mt][nt][1]);
            *(float2*)(base + (size_t)(m0 + 8) * G1D + n0) =
                make_float2(acc[mt][nt][2], acc[mt][nt][3]);
        }
    }
}

// partials -> h1 = elu(sum + bias), bf16 hi/lo (float4 over 4 consecutive cols)
__global__ void reduce_h1_kernel(const float* __restrict__ bg1) {
    const int i4 = blockIdx.x * 256 + threadIdx.x;   // float4 index
    float4 s = make_float4(0.f, 0.f, 0.f, 0.f);
#pragma unroll
    for (int k = 0; k < K1_KS; k++) {
        float4 v = ((const float4*)g_part)[k * (BB * G1D / 4) + i4];
        s.x += v.x; s.y += v.y; s.z += v.z; s.w += v.w;
    }
    const int c0 = (i4 * 4) & (G1D - 1);
    float4 b = *(const float4*)(bg1 + c0);
    float u0 = eluf(s.x + b.x), u1 = eluf(s.y + b.y);
    float u2 = eluf(s.z + b.z), u3 = eluf(s.w + b.w);
    __nv_bfloat16 h0, h1, h2, h3, l0, l1, l2, l3;
    hilo(u0, h0, l0); hilo(u1, h1, l1); hilo(u2, h2, l2); hilo(u3, h3, l3);
    __nv_bfloat162 vh0, vh1, vl0, vl1;
    vh0.x = h0; vh0.y = h1; vh1.x = h2; vh1.y = h3;
    vl0.x = l0; vl0.y = l1; vl1.x = l2; vl1.y = l3;
    ((__nv_bfloat162*)g_h1hi)[2 * i4] = vh0;
    ((__nv_bfloat162*)g_h1hi)[2 * i4 + 1] = vh1;
    ((__nv_bfloat162*)g_h1lo)[2 * i4] = vl0;
    ((__nv_bfloat162*)g_h1lo)[2 * i4 + 1] = vl1;
}

// ---------------- unified bf16-split HMMA GEMM (BN=128) ----------------
template <int EPI>
__global__ void __launch_bounds__(256, 2) gemm_bs(
    const __nv_bfloat16* __restrict__ Ahi, const __nv_bfloat16* __restrict__ Alo,
    int lda, long sAz,
    const __nv_bfloat16* __restrict__ Bhi, const __nv_bfloat16* __restrict__ Blo,
    int ldb, long sBz,
    float* __restrict__ C, __nv_bfloat16* __restrict__ Chi,
    __nv_bfloat16* __restrict__ Clo,
    const float* __restrict__ bias, int ldc, long sCz, int K,
    const float* __restrict__ b2, const float* __restrict__ W3,
    const float* __restrict__ b3,
    const float* __restrict__ hwhp, const float* __restrict__ zv,
    const int* __restrict__ permp, const float* __restrict__ Wzp,
    const float* __restrict__ b1p)
{
    extern __shared__ char sm[];
    __shared__ float red[128][5];
    __shared__ float wr[8];
    __shared__ float s_wz[HDIM], s_b1[HDIM];
    const uint32_t sb = smem_u32(sm);
    const int tid = threadIdx.x;
    const int lane = tid & 31;
    const int wid = tid >> 5;
    const int warpM = wid >> 2;
    const int warpN = wid & 3;

    const int nBase = blockIdx.x * 128;
    const int mBase = blockIdx.y * BM;
    const __nv_bfloat16* ahiz = Ahi + (size_t)blockIdx.z * sAz;
    const __nv_bfloat16* aloz = Alo + (size_t)blockIdx.z * sAz;
    const __nv_bfloat16* bhi = Bhi + (size_t)blockIdx.z * sBz;
    const __nv_bfloat16* blo = Blo + (size_t)blockIdx.z * sBz;

    if (EPI == 2) {
        if (tid < HDIM) {
            s_wz[tid] = Wzp[(size_t)blockIdx.z * HDIM + tid];
            s_b1[tid] = b1p[(size_t)blockIdx.z * HDIM + tid];
        }
        __syncthreads();
    }

    const uint32_t laneOff =
        (uint32_t)(((lane & 7) + ((lane >> 3) & 1) * 8) * ROWB + (lane >> 4) * 16);
    const int NIT = K / BK;

    float acc[4][4][4];
#pragma unroll
    for (int i = 0; i < 4; i++)
#pragma unroll
        for (int j = 0; j < 4; j++)
#pragma unroll
            for (int k = 0; k < 4; k++) acc[i][j][k] = 0.f;

#define A_COMPUTE(stage, k0)                                                   \
    do {                                                                       \
        uint32_t stoff = (uint32_t)(stage) * STG_BYTES;                        \
        const float* hwh_d = hwhp + (size_t)blockIdx.z * BB * HDIM;            \
        _Pragma("unroll")                                                      \
        for (int t = 0; t < 2; t++) {                                          \
            int u = tid + t * 256;                                             \
            int r = u >> 2, ch = u & 3;                                        \
            int gm = mBase + r;                                                \
            int b = (gm < BB) ? gm : gm - BB;                                  \
            int src = (gm < BB) ? b : __ldg(permp + b);                        \
            float zb = __ldg(zv + (size_t)b * DDIM + blockIdx.z);              \
            const float* hr = hwh_d + (size_t)src * HDIM + (k0) + ch * 8;      \
            float4 v0 = __ldg((const float4*)hr);                              \
            float4 v1 = __ldg((const float4*)(hr + 4));                        \
            float hv[8] = {v0.x, v0.y, v0.z, v0.w, v1.x, v1.y, v1.z, v1.w};    \
            uint32_t hp[4], lp[4];                                             \
            _Pragma("unroll")                                                  \
            for (int j = 0; j < 4; j++) {                                      \
                int kk = (k0) + ch * 8 + 2 * j;                                \
                float a0 = eluf(hv[2*j]   + fmaf(zb, s_wz[kk],   s_b1[kk]));   \
                float a1v = eluf(hv[2*j+1] + fmaf(zb, s_wz[kk+1], s_b1[kk+1]));\
                __nv_bfloat16 hh0, ll0, hh1, ll1;                              \
                hilo(a0, hh0, ll0); hilo(a1v, hh1, ll1);                       \
                __nv_bfloat162 ph; ph.x = hh0; ph.y = hh1;                     \
                __nv_bfloat162 pl; pl.x = ll0; pl.y = ll1;                     \
                hp[j] = *(uint32_t*)&ph; lp[j] = *(uint32_t*)&pl;              \
            }                                                                  \
            uint32_t so = (uint32_t)(r * ROWB + ch * 16);                      \
            *(uint4*)(sm + stoff + 0 * MAT_BYTES + so) =                       \
                make_uint4(hp[0], hp[1], hp[2], hp[3]);                        \
            *(uint4*)(sm + stoff + 1 * MAT_BYTES + so) =                       \
                make_uint4(lp[0], lp[1], lp[2], lp[3]);                        \
        }                                                                      \
    } while (0)

#define BS_LOAD(stage, k0)                                                     \
    do {                                                                       \
        uint32_t st = sb + (uint32_t)(stage)*STG_BYTES;                        \
        if (EPI == 2) {                                                        \
            A_COMPUTE(stage, k0);                                              \
        } else {                                                               \
            _Pragma("unroll")                                                  \
            for (int t = 0; t < 2; t++) {                                      \
                int ci = tid + t * 256;                                        \
                int r = ci >> 2, ch = ci & 3;                                  \
                uint32_t so = (uint32_t)(r * ROWB + ch * 16);                  \
                size_t goA = (size_t)(mBase + r) * lda + (k0) + ch * 8;        \
                CP16(st + 0 * MAT_BYTES + so, ahiz + goA);                     \
                CP16(st + 1 * MAT_BYTES + so, aloz + goA);                     \
            }                                                                  \
        }                                                                      \
        _Pragma("unroll")                                                      \
        for (int t = 0; t < 2; t++) {                                          \
            int ci = tid + t * 256;                                            \
            int r = ci >> 2, ch = ci & 3;                                      \
            uint32_t so = (uint32_t)(r * ROWB + ch * 16);                      \
            size_t goB = (size_t)(nBase + r) * ldb + (k0) + ch * 8;            \
            CP16(st + 2 * MAT_BYTES + so, bhi + goB);                          \
            CP16(st + 3 * MAT_BYTES + so, blo + goB);                          \
        }                                                                      \
    } while (0)

    BS_LOAD(0, 0);
    CP_COMMIT();

#pragma unroll 1
    for (int it = 0; it < NIT; it++) {
        if (it + 1 < NIT) {
            BS_LOAD((it + 1) & 1, (it + 1) * BK);
            CP_COMMIT();
            CP_WAIT1();
        } else {
            CP_WAIT0();
        }
        __syncthreads();

        uint32_t st = sb + (uint32_t)(it & 1) * STG_BYTES;
        uint32_t aH = st + 0 * MAT_BYTES + (uint32_t)(warpM * 64) * ROWB + laneOff;
        uint32_t aL = st + 1 * MAT_BYTES + (uint32_t)(warpM * 64) * ROWB + laneOff;
        uint32_t bH = st + 2 * MAT_BYTES + (uint32_t)(warpN * 32) * ROWB + laneOff;
        uint32_t bL = st + 3 * MAT_BYTES + (uint32_t)(warpN * 32) * ROWB + laneOff;

#pragma unroll
        for (int ks = 0; ks < 2; ks++) {
            const uint32_t kb = ks * 32;
            uint32_t ah[4][4], al[4][4], bh[2][4], bl[2][4];
#pragma unroll
            for (int mt = 0; mt < 4; mt++) {
                ldmx4(ah[mt], aH + (uint32_t)(mt * 16) * ROWB + kb);
                ldmx4(al[mt], aL + (uint32_t)(mt * 16) * ROWB + kb);
            }
#pragma unroll
            for (int p = 0; p < 2; p++) {
                ldmx4(bh[p], bH + (uint32_t)(p * 16) * ROWB + kb);
                ldmx4(bl[p], bL + (uint32_t)(p * 16) * ROWB + kb);
            }
#pragma unroll
            for (int mt = 0; mt < 4; mt++) {
#pragma unroll
                for (int nt = 0; nt < 4; nt++) {
                    const int p = nt >> 1, q = nt & 1;
                    mma16816(acc[mt][nt], ah[mt], bh[p][q], bh[p][q + 2]);
                    mma16816(acc[mt][nt], ah[mt], bl[p][q], bl[p][q + 2]);
                    mma16816(acc[mt][nt], al[mt], bh[p][q], bh[p][q + 2]);
                }
            }
        }
        __syncthreads();
    }
#undef BS_LOAD
#undef A_COMPUTE

    if (EPI == 2) {
        const float* b2z = b2 + (size_t)blockIdx.z * HDIM;
        const float* w3z = W3 + (size_t)blockIdx.z * HDIM;
        const float b3d = b3[blockIdx.z];
        const bool joint = (blockIdx.y < 4);
#pragma unroll
        for (int mt = 0; mt < 4; mt++) {
            float s0 = 0.f, s1 = 0.f;
#pragma unroll
            for (int nt = 0; nt < 4; nt++) {
                int n0 = warpN * 32 + nt * 8 + (lane & 3) * 2;
                float w0 = __ldg(w3z + n0), w1 = __ldg(w3z + n0 + 1);
                float c0 = __ldg(b2z + n0), c1 = __ldg(b2z + n0 + 1);
                s0 += eluf(acc[mt][nt][0] + c0) * w0 + eluf(acc[mt][nt][1] + c1) * w1;
                s1 += eluf(acc[mt][nt][2] + c0) * w0 + eluf(acc[mt][nt][3] + c1) * w1;
            }
            s0 += __shfl_xor_sync(0xffffffffu, s0, 1);
            s0 += __shfl_xor_sync(0xffffffffu, s0, 2);
            s1 += __shfl_xor_sync(0xffffffffu, s1, 1);
            s1 += __shfl_xor_sync(0xffffffffu, s1, 2);
            if ((lane & 3) == 0) {
                int r0 = warpM * 64 + mt * 16 + (lane >> 2);
                red[r0][warpN] = s0;
                red[r0 + 8][warpN] = s1;
            }
        }
        __syncthreads();
        float val = 0.f;
        if (tid < 128) {
            float s = red[tid][0] + red[tid][1] + red[tid][2] + red[tid][3] + b3d;
            val = joint ? s : expf(s);
        }
#pragma unroll
        for (int off = 16; off; off >>= 1)
            val += __shfl_xor_sync(0xffffffffu, val, off);
        if (lane == 0) wr[wid] = val;
        __syncthreads();
        if (tid == 0) {
            float s = wr[0] + wr[1] + wr[2] + wr[3];
            int slot = blockIdx.z * 8 + blockIdx.y;
            if (joint) { g_js[slot] = s; g_es[slot] = 0.f; }
            else       { g_js[slot] = 0.f; g_es[slot] = s; }
        }
        return;
    }

#pragma unroll
    for (int mt = 0; mt < 4; mt++) {
        int m0 = mBase + warpM * 64 + mt * 16 + (lane >> 2);
#pragma unroll
        for (int nt = 0; nt < 4; nt++) {
            int n0 = nBase + warpN * 32 + nt * 8 + (lane & 3) * 2;
            if (EPI == 0) {
                float* Cz = C + (size_t)blockIdx.z * sCz;
                *(float2*)(Cz + (size_t)m0 * ldc + n0) =
                    make_float2(acc[mt][nt][0], acc[mt][nt][1]);
                *(float2*)(Cz + (size_t)(m0 + 8) * ldc + n0) =
                    make_float2(acc[mt][nt][2], acc[mt][nt][3]);
            } else if (EPI == 1) {
                float bv0 = bias[n0], bv1 = bias[n0 + 1];
                float u0 = eluf(acc[mt][nt][0] + bv0);
                float u1 = eluf(acc[mt][nt][1] + bv1);
                float u2 = eluf(acc[mt][nt][2] + bv0);
                float u3 = eluf(acc[mt][nt][3] + bv1);
                __nv_bfloat16 h0, h1, h2, h3, l0, l1, l2, l3;
                hilo(u0, h0, l0); hilo(u1, h1, l1);
                hilo(u2, h2, l2); hilo(u3, h3, l3);
                __nv_bfloat162 vh, vl;
                vh.x = h0; vh.y = h1; vl.x = l0; vl.y = l1;
                *(__nv_bfloat162*)(Chi + (size_t)m0 * ldc + n0) = vh;
                *(__nv_bfloat162*)(Clo + (size_t)m0 * ldc + n0) = vl;
                vh.x = h2; vh.y = h3; vl.x = l2; vl.y = l3;
                *(__nv_bfloat162*)(Chi + (size_t)(m0 + 8) * ldc + n0) = vh;
                *(__nv_bfloat162*)(Clo + (size_t)(m0 + 8) * ldc + n0) = vl;
            }
        }
    }
}

__global__ void finalize_kernel(float* __restrict__ out)
{
    int t = threadIdx.x;
    float acc = 0.f;
    for (int d = t; d < DDIM; d += 32) {
        float js = 0.f, es = 0.f;
#pragma unroll
        for (int c = 0; c < 8; c++) { js += g_js[d * 8 + c]; es += g_es[d * 8 + c]; }
        acc += js * (1.f / BB) - logf(es * (1.f / BB));
    }
#pragma unroll
    for (int off = 16; off; off >>= 1)
        acc += __shfl_xor_sync(0xffffffffu, acc, off);
    if (t == 0) out[0] = -acc * (1.f / DDIM);
}

// ---------------------------------------------------------------------------
extern "C" void kernel_launch(void* const* d_in, const int* in_sizes, int n_in,
                              void* d_out, int out_size)
{
    const float* x   = (const float*)d_in[0];
    const float* z   = (const float*)d_in[1];
    const int*   perm= (const int*)  d_in[2];
    const float* Wg1 = (const float*)d_in[3];
    const float* bg1 = (const float*)d_in[4];
    const float* Wg2 = (const float*)d_in[5];
    const float* bg2 = (const float*)d_in[6];
    const float* Wh  = (const float*)d_in[7];
    const float* Wz  = (const float*)d_in[8];
    const float* b1  = (const float*)d_in[9];
    const float* W2  = (const float*)d_in[10];
    const float* b2  = (const float*)d_in[11];
    const float* W3  = (const float*)d_in[12];
    const float* b3  = (const float*)d_in[13];

    __nv_bfloat16 *h1hi, *h1lo, *wg2thi, *wg2tlo, *hhi, *hlo, *whthi, *whtlo;
    __nv_bfloat16 *w2thi, *w2tlo;
    float* hwh;
    cudaGetSymbolAddress((void**)&h1hi,   g_h1hi);
    cudaGetSymbolAddress((void**)&h1lo,   g_h1lo);
    cudaGetSymbolAddress((void**)&wg2thi, g_wg2thi);
    cudaGetSymbolAddress((void**)&wg2tlo, g_wg2tlo);
    cudaGetSymbolAddress((void**)&hhi,    g_hhi);
    cudaGetSymbolAddress((void**)&hlo,    g_hlo);
    cudaGetSymbolAddress((void**)&whthi,  g_whthi);
    cudaGetSymbolAddress((void**)&whtlo,  g_whtlo);
    cudaGetSymbolAddress((void**)&w2thi,  g_w2thi);
    cudaGetSymbolAddress((void**)&w2tlo,  g_w2tlo);
    cudaGetSymbolAddress((void**)&hwh,    g_hWh);

    // small-weight conversions only
    transconv_kernel<<<dim3(PDIM / 32, G1D / 32, 1), 256>>>(Wg2, wg2thi, wg2tlo,
                                                            G1D, PDIM);
    transconv_kernel<<<dim3(HDIM / 32, PDIM / 32, DDIM), 256>>>(Wh, whthi, whtlo,
                                                                PDIM, HDIM);
    transconv_kernel<<<dim3(HDIM / 32, HDIM / 32, DDIM), 256>>>(W2, w2thi, w2tlo,
                                                                HDIM, HDIM);

    // K1: fused fp32->hi/lo loader + bf16-split HMMA
    cudaFuncSetAttribute(gemm_k1_kernel,
                         cudaFuncAttributeMaxDynamicSharedMemorySize, K1_SMEM);
    gemm_k1_kernel<<<dim3(G1D / K1_BN, BB / BM, K1_KS), 256, K1_SMEM>>>(x, Wg1);
    reduce_h1_kernel<<<(BB * G1D) / 4 / 256, 256>>>(bg1);

    cudaFuncSetAttribute(gemm_bs<0>,
                         cudaFuncAttributeMaxDynamicSharedMemorySize, GEMM_SMEM);
    cudaFuncSetAttribute(gemm_bs<1>,
                         cudaFuncAttributeMaxDynamicSharedMemorySize, GEMM_SMEM);
    cudaFuncSetAttribute(gemm_bs<2>,
                         cudaFuncAttributeMaxDynamicSharedMemorySize, GEMM_SMEM);

    // K2: h = elu(h1 @ Wg2 + bg2) -> bf16 hi/lo
    gemm_bs<1><<<dim3(PDIM / 128, BB / BM, 1), 256, GEMM_SMEM>>>(
        h1hi, h1lo, G1D, 0, wg2thi, wg2tlo, G1D, 0,
        nullptr, hhi, hlo, bg2, PDIM, 0, G1D,
        nullptr, nullptr, nullptr, nullptr, nullptr, nullptr, nullptr, nullptr);

    // K3: hWh[d] = h @ WhT[d]  (fp32)
    gemm_bs<0><<<dim3(1, BB / BM, DDIM), 256, GEMM_SMEM>>>(
        hhi, hlo, PDIM, 0, whthi, whtlo, PDIM, (long)HDIM * PDIM,
        hwh, nullptr, nullptr, nullptr, HDIM, (long)BB * HDIM, PDIM,
        nullptr, nullptr, nullptr, nullptr, nullptr, nullptr, nullptr, nullptr);

    // head: fused a1 compute + a2 GEMM + scores + reductions
    gemm_bs<2><<<dim3(1, (2 * BB) / BM, DDIM), 256, GEMM_SMEM>>>(
        nullptr, nullptr, HDIM, 0,
        w2thi, w2tlo, HDIM, (long)HDIM * HDIM,
        nullptr, nullptr, nullptr, nullptr, HDIM, 0, HDIM,
        b2, W3, b3, hwh, z, perm, Wz, b1);

    finalize_kernel<<<1, 32>>>((float*)d_out);
}